// round 1
// baseline (speedup 1.0000x reference)
#include <cuda_runtime.h>

// ---------------------------------------------------------------------------
// Problem constants
// ---------------------------------------------------------------------------
namespace {
constexpr int BATCH  = 4;
constexpr int HEADS  = 16;
constexpr int SEQ    = 2048;
constexpr int DH     = 64;     // per-head dim (D_E = D_X = 64)
constexpr int DMODEL = 1024;
constexpr int MROWS  = BATCH * SEQ;           // 8192
constexpr int BHTOT  = BATCH * HEADS;         // 64
constexpr size_t HEAD_ELEMS = (size_t)BHTOT * SEQ * DH;   // 8,388,608
constexpr size_t FEAT_ELEMS = (size_t)MROWS * DMODEL;     // 8,388,608
}

// Scratch (allocation-free; module-load time, allowed)
__device__ __align__(16) float g_eh[HEAD_ELEMS];    // [B,H,L,DH]
__device__ __align__(16) float g_xh[HEAD_ELEMS];    // [B,H,L,DH]
__device__ __align__(16) float g_feat[FEAT_ELEMS];  // [B,L,DMODEL] (attn@V, head-merged)
__device__ __align__(16) float g_tmp[FEAT_ELEMS];   // pre-LN (fc + residual)

// ---------------------------------------------------------------------------
// Reduction helpers
// ---------------------------------------------------------------------------
__device__ __forceinline__ float warp_max(float v) {
    #pragma unroll
    for (int o = 16; o; o >>= 1) v = fmaxf(v, __shfl_xor_sync(0xffffffffu, v, o));
    return v;
}
__device__ __forceinline__ float warp_sum(float v) {
    #pragma unroll
    for (int o = 16; o; o >>= 1) v += __shfl_xor_sync(0xffffffffu, v, o);
    return v;
}

// ---------------------------------------------------------------------------
// Projection: out[b,h,l,d] = sum_k A[b,l,k] * W[h*64+d, k]
// A: [8192,1024] row-major, W: [1024,1024] (out_features, in_features)
// Tiled 64x64, BK=16, 256 threads, 4x4 per thread.
// which==0 -> g_eh, which==1 -> g_xh
// ---------------------------------------------------------------------------
__global__ __launch_bounds__(256) void proj_kernel(const float* __restrict__ A,
                                                   const float* __restrict__ W,
                                                   int which)
{
    __shared__ float As[64][17];
    __shared__ float Bs[16][65];
    float* outp = which ? g_xh : g_eh;

    const int tid = threadIdx.x;
    const int tx  = tid & 15, ty = tid >> 4;
    const int m0  = blockIdx.y * 64;
    const int n0  = blockIdx.x * 64;
    const int lr  = tid >> 2;          // 0..63
    const int lk  = (tid & 3) * 4;     // 0,4,8,12

    float acc[4][4] = {};
    for (int k0 = 0; k0 < DMODEL; k0 += 16) {
        float4 va = *(const float4*)&A[(size_t)(m0 + lr) * DMODEL + k0 + lk];
        As[lr][lk]   = va.x; As[lr][lk+1] = va.y;
        As[lr][lk+2] = va.z; As[lr][lk+3] = va.w;
        float4 vb = *(const float4*)&W[(size_t)(n0 + lr) * DMODEL + k0 + lk];
        Bs[lk][lr]   = vb.x; Bs[lk+1][lr] = vb.y;
        Bs[lk+2][lr] = vb.z; Bs[lk+3][lr] = vb.w;
        __syncthreads();
        #pragma unroll
        for (int kk = 0; kk < 16; kk++) {
            float a[4], b[4];
            #pragma unroll
            for (int i = 0; i < 4; i++) a[i] = As[ty*4+i][kk];
            #pragma unroll
            for (int j = 0; j < 4; j++) b[j] = Bs[kk][tx*4+j];
            #pragma unroll
            for (int i = 0; i < 4; i++)
                #pragma unroll
                for (int j = 0; j < 4; j++)
                    acc[i][j] = fmaf(a[i], b[j], acc[i][j]);
        }
        __syncthreads();
    }
    // n-tile == exactly one head (64 wide)
    const int b = m0 / SEQ;
    const int h = n0 >> 6;
    #pragma unroll
    for (int i = 0; i < 4; i++) {
        int l = (m0 % SEQ) + ty*4 + i;
        float4 v = make_float4(acc[i][0], acc[i][1], acc[i][2], acc[i][3]);
        *(float4*)&outp[(((size_t)(b*HEADS + h) * SEQ) + l) * DH + tx*4] = v;
    }
}

// ---------------------------------------------------------------------------
// Scores: S[bh,q,k] = (1/8) * sum_d eh[bh,q,d]*eh[bh,k,d], written raw to attn.
// K=64 fits entirely in smem; 64x64 output tile per block.
// ---------------------------------------------------------------------------
__global__ __launch_bounds__(256) void scores_kernel(float* __restrict__ attn)
{
    __shared__ float Qs[64][65];
    __shared__ float Ks[64][65];
    const int bh = blockIdx.z;
    const int q0 = blockIdx.y * 64;
    const int k0 = blockIdx.x * 64;
    const float* eh = g_eh + (size_t)bh * SEQ * DH;
    const int tid = threadIdx.x;
    const int tx  = tid & 15, ty = tid >> 4;

    #pragma unroll
    for (int i = 0; i < 4; i++) {
        int idx4 = tid + i * 256;        // 0..1023
        int r  = idx4 >> 4;              // 0..63
        int c4 = (idx4 & 15) * 4;        // 0..60
        float4 vq = *(const float4*)&eh[(size_t)(q0 + r) * DH + c4];
        Qs[r][c4] = vq.x; Qs[r][c4+1] = vq.y; Qs[r][c4+2] = vq.z; Qs[r][c4+3] = vq.w;
        float4 vk = *(const float4*)&eh[(size_t)(k0 + r) * DH + c4];
        Ks[r][c4] = vk.x; Ks[r][c4+1] = vk.y; Ks[r][c4+2] = vk.z; Ks[r][c4+3] = vk.w;
    }
    __syncthreads();

    float acc[4][4] = {};
    #pragma unroll
    for (int kk = 0; kk < 64; kk++) {
        float a[4], b[4];
        #pragma unroll
        for (int i = 0; i < 4; i++) a[i] = Qs[ty*4+i][kk];
        #pragma unroll
        for (int j = 0; j < 4; j++) b[j] = Ks[tx*4+j][kk];
        #pragma unroll
        for (int i = 0; i < 4; i++)
            #pragma unroll
            for (int j = 0; j < 4; j++)
                acc[i][j] = fmaf(a[i], b[j], acc[i][j]);
    }
    const float scale = 0.125f;   // 1/sqrt(64)
    #pragma unroll
    for (int i = 0; i < 4; i++) {
        size_t row = (size_t)bh * SEQ + q0 + ty*4 + i;
        float4 v = make_float4(acc[i][0]*scale, acc[i][1]*scale,
                               acc[i][2]*scale, acc[i][3]*scale);
        *(float4*)&attn[row * SEQ + k0 + tx*4] = v;
    }
}

// ---------------------------------------------------------------------------
// Softmax in place over rows of length 2048. One block (256 thr) per row.
// ---------------------------------------------------------------------------
__global__ __launch_bounds__(256) void softmax_kernel(float* __restrict__ attn)
{
    const int tid = threadIdx.x;
    float* p = attn + (size_t)blockIdx.x * SEQ;
    float4 v0 = ((float4*)p)[tid];
    float4 v1 = ((float4*)p)[tid + 256];

    float m = fmaxf(fmaxf(fmaxf(v0.x, v0.y), fmaxf(v0.z, v0.w)),
                    fmaxf(fmaxf(v1.x, v1.y), fmaxf(v1.z, v1.w)));
    __shared__ float sm[8];
    __shared__ float ssum[8];
    m = warp_max(m);
    if ((tid & 31) == 0) sm[tid >> 5] = m;
    __syncthreads();
    float mb = sm[0];
    #pragma unroll
    for (int i = 1; i < 8; i++) mb = fmaxf(mb, sm[i]);

    v0.x = __expf(v0.x - mb); v0.y = __expf(v0.y - mb);
    v0.z = __expf(v0.z - mb); v0.w = __expf(v0.w - mb);
    v1.x = __expf(v1.x - mb); v1.y = __expf(v1.y - mb);
    v1.z = __expf(v1.z - mb); v1.w = __expf(v1.w - mb);

    float s = v0.x + v0.y + v0.z + v0.w + v1.x + v1.y + v1.z + v1.w;
    s = warp_sum(s);
    if ((tid & 31) == 0) ssum[tid >> 5] = s;
    __syncthreads();
    float sb = 0.f;
    #pragma unroll
    for (int i = 0; i < 8; i++) sb += ssum[i];
    const float inv = 1.0f / sb;

    v0.x *= inv; v0.y *= inv; v0.z *= inv; v0.w *= inv;
    v1.x *= inv; v1.y *= inv; v1.z *= inv; v1.w *= inv;
    ((float4*)p)[tid]       = v0;
    ((float4*)p)[tid + 256] = v1;
}

// ---------------------------------------------------------------------------
// AV: feat[b,l,h*64+d] = sum_k attn[bh,q,k] * xh[bh,k,d]
// 64(q) x 64(d) tile per block, BK=32.
// ---------------------------------------------------------------------------
__global__ __launch_bounds__(256) void av_kernel(const float* __restrict__ attn)
{
    __shared__ float As[64][33];
    __shared__ float Xs[32][65];
    const int bh = blockIdx.y;
    const int q0 = blockIdx.x * 64;
    const float* xh   = g_xh + (size_t)bh * SEQ * DH;
    const float* arow = attn + ((size_t)bh * SEQ + q0) * SEQ;
    const int tid = threadIdx.x;
    const int tx  = tid & 15, ty = tid >> 4;

    float acc[4][4] = {};
    for (int k0 = 0; k0 < SEQ; k0 += 32) {
        #pragma unroll
        for (int i = 0; i < 2; i++) {
            int idx4 = tid + i * 256;       // 0..511
            int r  = idx4 >> 3;             // 0..63
            int c4 = (idx4 & 7) * 4;        // 0..28
            float4 v = *(const float4*)&arow[(size_t)r * SEQ + k0 + c4];
            As[r][c4] = v.x; As[r][c4+1] = v.y; As[r][c4+2] = v.z; As[r][c4+3] = v.w;
            int r2 = idx4 >> 4;             // 0..31
            int c2 = (idx4 & 15) * 4;       // 0..60
            float4 w = *(const float4*)&xh[(size_t)(k0 + r2) * DH + c2];
            Xs[r2][c2] = w.x; Xs[r2][c2+1] = w.y; Xs[r2][c2+2] = w.z; Xs[r2][c2+3] = w.w;
        }
        __syncthreads();
        #pragma unroll
        for (int kk = 0; kk < 32; kk++) {
            float a[4], b[4];
            #pragma unroll
            for (int i = 0; i < 4; i++) a[i] = As[ty*4+i][kk];
            #pragma unroll
            for (int j = 0; j < 4; j++) b[j] = Xs[kk][tx*4+j];
            #pragma unroll
            for (int i = 0; i < 4; i++)
                #pragma unroll
                for (int j = 0; j < 4; j++)
                    acc[i][j] = fmaf(a[i], b[j], acc[i][j]);
        }
        __syncthreads();
    }
    const int b = bh >> 4, h = bh & 15;
    #pragma unroll
    for (int i = 0; i < 4; i++) {
        int q = q0 + ty*4 + i;
        float4 v = make_float4(acc[i][0], acc[i][1], acc[i][2], acc[i][3]);
        *(float4*)&g_feat[((size_t)(b * SEQ + q)) * DMODEL + h * DH + tx*4] = v;
    }
}

// ---------------------------------------------------------------------------
// FC + residual: g_tmp[m,n] = sum_f g_feat[m,f]*Wfc[n,f] + x[m,n]
// ---------------------------------------------------------------------------
__global__ __launch_bounds__(256) void fc_kernel(const float* __restrict__ Wfc,
                                                 const float* __restrict__ x)
{
    __shared__ float As[64][17];
    __shared__ float Bs[16][65];
    const int tid = threadIdx.x;
    const int tx  = tid & 15, ty = tid >> 4;
    const int m0  = blockIdx.y * 64;
    const int n0  = blockIdx.x * 64;
    const int lr  = tid >> 2;
    const int lk  = (tid & 3) * 4;

    float acc[4][4] = {};
    for (int k0 = 0; k0 < DMODEL; k0 += 16) {
        float4 va = *(const float4*)&g_feat[(size_t)(m0 + lr) * DMODEL + k0 + lk];
        As[lr][lk]   = va.x; As[lr][lk+1] = va.y;
        As[lr][lk+2] = va.z; As[lr][lk+3] = va.w;
        float4 vb = *(const float4*)&Wfc[(size_t)(n0 + lr) * DMODEL + k0 + lk];
        Bs[lk][lr]   = vb.x; Bs[lk+1][lr] = vb.y;
        Bs[lk+2][lr] = vb.z; Bs[lk+3][lr] = vb.w;
        __syncthreads();
        #pragma unroll
        for (int kk = 0; kk < 16; kk++) {
            float a[4], b[4];
            #pragma unroll
            for (int i = 0; i < 4; i++) a[i] = As[ty*4+i][kk];
            #pragma unroll
            for (int j = 0; j < 4; j++) b[j] = Bs[kk][tx*4+j];
            #pragma unroll
            for (int i = 0; i < 4; i++)
                #pragma unroll
                for (int j = 0; j < 4; j++)
                    acc[i][j] = fmaf(a[i], b[j], acc[i][j]);
        }
        __syncthreads();
    }
    #pragma unroll
    for (int i = 0; i < 4; i++) {
        int m = m0 + ty*4 + i;
        float4 r = *(const float4*)&x[(size_t)m * DMODEL + n0 + tx*4];
        float4 v = make_float4(acc[i][0] + r.x, acc[i][1] + r.y,
                               acc[i][2] + r.z, acc[i][3] + r.w);
        *(float4*)&g_tmp[(size_t)m * DMODEL + n0 + tx*4] = v;
    }
}

// ---------------------------------------------------------------------------
// LayerNorm over last dim (1024), eps=1e-6. One block (256 thr) per row.
// ---------------------------------------------------------------------------
__global__ __launch_bounds__(256) void ln_kernel(const float* __restrict__ gamma,
                                                 const float* __restrict__ beta,
                                                 float* __restrict__ out)
{
    const int tid = threadIdx.x;
    const size_t row = blockIdx.x;
    const float* p = g_tmp + row * DMODEL;
    float4 v = ((const float4*)p)[tid];
    float s  = v.x + v.y + v.z + v.w;
    float ss = v.x*v.x + v.y*v.y + v.z*v.z + v.w*v.w;
    s  = warp_sum(s);
    ss = warp_sum(ss);
    __shared__ float rs[8], rss[8];
    if ((tid & 31) == 0) { rs[tid >> 5] = s; rss[tid >> 5] = ss; }
    __syncthreads();
    float S = 0.f, SS = 0.f;
    #pragma unroll
    for (int i = 0; i < 8; i++) { S += rs[i]; SS += rss[i]; }
    const float mean = S * (1.0f / DMODEL);
    const float var  = SS * (1.0f / DMODEL) - mean * mean;
    const float inv  = rsqrtf(var + 1e-6f);

    float4 g  = ((const float4*)gamma)[tid];
    float4 bb = ((const float4*)beta)[tid];
    float4 o;
    o.x = (v.x - mean) * inv * g.x + bb.x;
    o.y = (v.y - mean) * inv * g.y + bb.y;
    o.z = (v.z - mean) * inv * g.z + bb.z;
    o.w = (v.w - mean) * inv * g.w + bb.w;
    ((float4*)(out + row * DMODEL))[tid] = o;
}

// ---------------------------------------------------------------------------
// Launch
// ---------------------------------------------------------------------------
extern "C" void kernel_launch(void* const* d_in, const int* in_sizes, int n_in,
                              void* d_out, int out_size)
{
    const float* e     = (const float*)d_in[0];
    const float* x     = (const float*)d_in[1];
    const float* We    = (const float*)d_in[2];
    const float* Wx    = (const float*)d_in[3];
    const float* Wfc   = (const float*)d_in[4];
    const float* gamma = (const float*)d_in[5];
    const float* beta  = (const float*)d_in[6];

    float* out      = (float*)d_out;
    float* out_feat = out;                 // [B,L,DMODEL]
    float* out_attn = out + FEAT_ELEMS;    // [B,H,L,L]

    dim3 gproj(DMODEL / 64, MROWS / 64);               // (16,128)
    proj_kernel<<<gproj, 256>>>(e, We, 0);
    proj_kernel<<<gproj, 256>>>(x, Wx, 1);

    dim3 gsc(SEQ / 64, SEQ / 64, BHTOT);               // (32,32,64)
    scores_kernel<<<gsc, 256>>>(out_attn);

    softmax_kernel<<<BHTOT * SEQ, 256>>>(out_attn);    // 131072 rows

    av_kernel<<<dim3(SEQ / 64, BHTOT), 256>>>(out_attn);

    fc_kernel<<<gproj, 256>>>(Wfc, x);

    ln_kernel<<<MROWS, 256>>>(gamma, beta, out_feat);
}

// round 3
// speedup vs baseline: 1.4477x; 1.4477x over previous
#include <cuda_runtime.h>
#include <mma.h>
#include <cstdint>

using namespace nvcuda;

// ---------------------------------------------------------------------------
// Problem constants
// ---------------------------------------------------------------------------
namespace {
constexpr int BATCH  = 4;
constexpr int HEADS  = 16;
constexpr int SEQ    = 2048;
constexpr int DH     = 64;
constexpr int DMODEL = 1024;
constexpr int MROWS  = BATCH * SEQ;           // 8192
constexpr int BHTOT  = BATCH * HEADS;         // 64
constexpr size_t HEAD_ELEMS = (size_t)BHTOT * SEQ * DH;
constexpr size_t FEAT_ELEMS = (size_t)MROWS * DMODEL;
}

// Scratch (device globals; allocation-free)
__device__ __align__(16) float g_eh[HEAD_ELEMS];    // [bh][l][64]
__device__ __align__(16) float g_xh[HEAD_ELEMS];    // [bh][64][l]  (transposed)
__device__ __align__(16) float g_feat[FEAT_ELEMS];  // [b][l][1024]
__device__ __align__(16) float g_tmp[FEAT_ELEMS];   // pre-LN
__device__ __align__(16) float g_invs[(size_t)BHTOT * SEQ];

using FragA = wmma::fragment<wmma::matrix_a, 16, 16, 8, wmma::precision::tf32, wmma::row_major>;
using FragB = wmma::fragment<wmma::matrix_b, 16, 16, 8, wmma::precision::tf32, wmma::col_major>;
using FragC = wmma::fragment<wmma::accumulator, 16, 16, 8, float>;

__device__ __forceinline__ float to_tf32f(float f) {
    uint32_t r; asm("cvt.rna.tf32.f32 %0, %1;" : "=r"(r) : "f"(f));
    return __uint_as_float(r);
}

// Stage [ROWS][COLS] fp32 (global row stride gs) -> smem [ROWS][PAD], tf32-rounded, scaled.
template <int ROWS, int COLS, int PAD>
__device__ __forceinline__ void stage(float* sm, const float* __restrict__ g,
                                      int gs, float scale, int tid) {
    constexpr int QC = COLS / 4;
    #pragma unroll
    for (int i = tid; i < ROWS * QC; i += 256) {
        int r = i / QC, c4 = (i % QC) * 4;
        float4 v = *(const float4*)(g + (size_t)r * gs + c4);
        float4 t = make_float4(to_tf32f(v.x * scale), to_tf32f(v.y * scale),
                               to_tf32f(v.z * scale), to_tf32f(v.w * scale));
        *(float4*)(sm + r * PAD + c4) = t;
    }
}

// ---------------------------------------------------------------------------
// GEMM: D[m,n] = sum_k A[m,k] * W[n,k]  (M=8192, N=1024, K=1024)
// Block 128x128, 8 warps (4m x 2n), warp tile 32x64. K-chunk 32.
// MODE 0: A=e   -> g_eh  [bh][l][64]
// MODE 1: A=x   -> g_xh  [bh][64][l]   (col-major store = transpose)
// MODE 2: A=g_feat, acc init = residual x -> g_tmp
// ---------------------------------------------------------------------------
template <int MODE>
__global__ __launch_bounds__(256) void gemm_kernel(const float* __restrict__ Ain,
                                                   const float* __restrict__ W,
                                                   const float* __restrict__ resid)
{
    extern __shared__ float sm[];
    float* As = sm;                 // [128][40]
    float* Bs = sm + 128 * 40;      // [128][40]  (Bs[n][k])
    const int tid = threadIdx.x, wid = tid >> 5;
    const int wm = wid & 3, wn = wid >> 2;
    const int n0 = blockIdx.x * 128, m0 = blockIdx.y * 128;
    const float* A = (MODE == 2) ? g_feat : Ain;

    FragC acc[2][4];
    if (MODE == 2) {
        #pragma unroll
        for (int i = 0; i < 2; i++)
            #pragma unroll
            for (int j = 0; j < 4; j++)
                wmma::load_matrix_sync(acc[i][j],
                    resid + (size_t)(m0 + wm*32 + i*16) * DMODEL + n0 + wn*64 + j*16,
                    DMODEL, wmma::mem_row_major);
    } else {
        #pragma unroll
        for (int i = 0; i < 2; i++)
            #pragma unroll
            for (int j = 0; j < 4; j++)
                wmma::fill_fragment(acc[i][j], 0.0f);
    }

    for (int kc = 0; kc < DMODEL; kc += 32) {
        stage<128, 32, 40>(As, A + (size_t)m0 * DMODEL + kc, DMODEL, 1.0f, tid);
        stage<128, 32, 40>(Bs, W + (size_t)n0 * DMODEL + kc, DMODEL, 1.0f, tid);
        __syncthreads();
        #pragma unroll
        for (int ks = 0; ks < 4; ks++) {
            FragA a[2]; FragB b[4];
            #pragma unroll
            for (int i = 0; i < 2; i++)
                wmma::load_matrix_sync(a[i], As + (wm*32 + i*16) * 40 + ks*8, 40);
            #pragma unroll
            for (int j = 0; j < 4; j++)
                wmma::load_matrix_sync(b[j], Bs + (wn*64 + j*16) * 40 + ks*8, 40);
            #pragma unroll
            for (int i = 0; i < 2; i++)
                #pragma unroll
                for (int j = 0; j < 4; j++)
                    wmma::mma_sync(acc[i][j], a[i], b[j], acc[i][j]);
        }
        __syncthreads();
    }

    const int b  = m0 >> 11;        // batch
    const int ml = m0 & 2047;       // l within batch
    #pragma unroll
    for (int i = 0; i < 2; i++) {
        #pragma unroll
        for (int j = 0; j < 4; j++) {
            int n = n0 + wn*64 + j*16;
            if (MODE == 0) {
                int h = n >> 6, dl = n & 63;
                wmma::store_matrix_sync(
                    g_eh + ((size_t)(b*HEADS + h) * SEQ + ml + wm*32 + i*16) * DH + dl,
                    acc[i][j], DH, wmma::mem_row_major);
            } else if (MODE == 1) {
                int h = n >> 6, dl = n & 63;
                wmma::store_matrix_sync(
                    g_xh + ((size_t)(b*HEADS + h) * DH + dl) * SEQ + ml + wm*32 + i*16,
                    acc[i][j], SEQ, wmma::mem_col_major);
            } else {
                wmma::store_matrix_sync(
                    g_tmp + (size_t)(m0 + wm*32 + i*16) * DMODEL + n,
                    acc[i][j], DMODEL, wmma::mem_row_major);
            }
        }
    }
}

// ---------------------------------------------------------------------------
// Scores: E[q,k'] = exp(0.125 * eh[q,:]·eh[k',:]) -> attn (unnormalized),
// rowsums -> g_invs. Block: q-tile 128, loop 32 k'-tiles of 64. Warp 32x32.
// ---------------------------------------------------------------------------
__global__ __launch_bounds__(256) void scores_kernel(float* __restrict__ attn)
{
    extern __shared__ float sm[];
    float* Aq = sm;                           // [128][72]
    float* Bk = sm + 128 * 72;                // [64][72]
    float* Cb = sm + 128 * 72 + 64 * 72;      // [128][68]
    const int tid = threadIdx.x, wid = tid >> 5;
    const int wm = wid & 3, wn = wid >> 2;
    const int bh = blockIdx.y, q0 = blockIdx.x * 128;
    const float* ehb = g_eh + (size_t)bh * SEQ * DH;

    stage<128, 64, 72>(Aq, ehb + (size_t)q0 * DH, DH, 0.125f, tid);

    float rsum = 0.0f;
    float* arow = attn + ((size_t)bh * SEQ + q0 + (tid >> 1)) * SEQ + (tid & 1) * 32;

    for (int it = 0; it < 32; it++) {
        stage<64, 64, 72>(Bk, ehb + (size_t)it * 64 * DH, DH, 1.0f, tid);
        __syncthreads();

        FragC acc[2][2];
        #pragma unroll
        for (int i = 0; i < 2; i++)
            #pragma unroll
            for (int j = 0; j < 2; j++)
                wmma::fill_fragment(acc[i][j], 0.0f);

        #pragma unroll
        for (int ks = 0; ks < 8; ks++) {
            FragA a[2]; FragB b[2];
            #pragma unroll
            for (int i = 0; i < 2; i++)
                wmma::load_matrix_sync(a[i], Aq + (wm*32 + i*16) * 72 + ks*8, 72);
            #pragma unroll
            for (int j = 0; j < 2; j++)
                wmma::load_matrix_sync(b[j], Bk + (wn*32 + j*16) * 72 + ks*8, 72);
            #pragma unroll
            for (int i = 0; i < 2; i++)
                #pragma unroll
                for (int j = 0; j < 2; j++)
                    wmma::mma_sync(acc[i][j], a[i], b[j], acc[i][j]);
        }
        // exp elementwise on fragments, park in smem
        #pragma unroll
        for (int i = 0; i < 2; i++) {
            #pragma unroll
            for (int j = 0; j < 2; j++) {
                #pragma unroll
                for (int e = 0; e < acc[i][j].num_elements; e++)
                    acc[i][j].x[e] = __expf(acc[i][j].x[e]);
                wmma::store_matrix_sync(Cb + (wm*32 + i*16) * 68 + wn*32 + j*16,
                                        acc[i][j], 68, wmma::mem_row_major);
            }
        }
        __syncthreads();
        // write out 64 cols + accumulate rowsum (2 threads per row)
        const float* src = Cb + (tid >> 1) * 68 + (tid & 1) * 32;
        float4* dst = (float4*)(arow + it * 64);
        #pragma unroll
        for (int q = 0; q < 8; q++) {
            float4 v = ((const float4*)src)[q];
            rsum += v.x + v.y + v.z + v.w;
            dst[q] = v;
        }
        __syncthreads();
    }
    float tot = rsum + __shfl_xor_sync(0xffffffffu, rsum, 1);
    if (!(tid & 1)) g_invs[(size_t)bh * SEQ + q0 + (tid >> 1)] = 1.0f / tot;
}

// ---------------------------------------------------------------------------
// AV: normalize attn in place, feat[q,h*64+d] = sum_l attn[q,l]*xh[l,d].
// Persistent accumulators over K=2048 (32 chunks of 64). Warp 32x32.
// ---------------------------------------------------------------------------
__global__ __launch_bounds__(256) void av_kernel(float* __restrict__ attn)
{
    extern __shared__ float sm[];
    float* Ae   = sm;                         // [128][72]
    float* Bx   = sm + 128 * 72;              // [64][72]
    float* sinv = sm + 128 * 72 + 64 * 72;    // [128]
    const int tid = threadIdx.x, wid = tid >> 5;
    const int wm = wid & 3, wn = wid >> 2;
    const int bh = blockIdx.y, q0 = blockIdx.x * 128;

    if (tid < 128) sinv[tid] = g_invs[(size_t)bh * SEQ + q0 + tid];
    __syncthreads();

    float* Erow = attn + ((size_t)bh * SEQ + q0) * SEQ;
    const float* xhb = g_xh + (size_t)bh * DH * SEQ;

    FragC acc[2][2];
    #pragma unroll
    for (int i = 0; i < 2; i++)
        #pragma unroll
        for (int j = 0; j < 2; j++)
            wmma::fill_fragment(acc[i][j], 0.0f);

    for (int kc = 0; kc < 32; kc++) {
        const int k0 = kc * 64;
        // stage E tile, normalize, write back normalized attn
        #pragma unroll
        for (int i = tid; i < 128 * 16; i += 256) {
            int r = i >> 4, c4 = (i & 15) << 2;
            float* gp = Erow + (size_t)r * SEQ + k0 + c4;
            float4 v = *(float4*)gp;
            float is = sinv[r];
            v.x *= is; v.y *= is; v.z *= is; v.w *= is;
            *(float4*)gp = v;
            *(float4*)(Ae + r * 72 + c4) =
                make_float4(to_tf32f(v.x), to_tf32f(v.y), to_tf32f(v.z), to_tf32f(v.w));
        }
        stage<64, 64, 72>(Bx, xhb + k0, SEQ, 1.0f, tid);
        __syncthreads();
        #pragma unroll
        for (int ks = 0; ks < 8; ks++) {
            FragA a[2]; FragB b[2];
            #pragma unroll
            for (int i = 0; i < 2; i++)
                wmma::load_matrix_sync(a[i], Ae + (wm*32 + i*16) * 72 + ks*8, 72);
            #pragma unroll
            for (int j = 0; j < 2; j++)
                wmma::load_matrix_sync(b[j], Bx + (wn*32 + j*16) * 72 + ks*8, 72);
            #pragma unroll
            for (int i = 0; i < 2; i++)
                #pragma unroll
                for (int j = 0; j < 2; j++)
                    wmma::mma_sync(acc[i][j], a[i], b[j], acc[i][j]);
        }
        __syncthreads();
    }

    const int b = bh >> 4, h = bh & 15;
    #pragma unroll
    for (int i = 0; i < 2; i++)
        #pragma unroll
        for (int j = 0; j < 2; j++)
            wmma::store_matrix_sync(
                g_feat + (size_t)(b * SEQ + q0 + wm*32 + i*16) * DMODEL + h * DH + wn*32 + j*16,
                acc[i][j], DMODEL, wmma::mem_row_major);
}

// ---------------------------------------------------------------------------
// LayerNorm over last dim (1024), eps=1e-6. One block (256 thr) per row.
// ---------------------------------------------------------------------------
__device__ __forceinline__ float warp_sum(float v) {
    #pragma unroll
    for (int o = 16; o; o >>= 1) v += __shfl_xor_sync(0xffffffffu, v, o);
    return v;
}
__global__ __launch_bounds__(256) void ln_kernel(const float* __restrict__ gamma,
                                                 const float* __restrict__ beta,
                                                 float* __restrict__ out)
{
    const int tid = threadIdx.x;
    const size_t row = blockIdx.x;
    const float* p = g_tmp + row * DMODEL;
    float4 v = ((const float4*)p)[tid];
    float s  = v.x + v.y + v.z + v.w;
    float ss = v.x*v.x + v.y*v.y + v.z*v.z + v.w*v.w;
    s = warp_sum(s); ss = warp_sum(ss);
    __shared__ float rs[8], rss[8];
    if ((tid & 31) == 0) { rs[tid >> 5] = s; rss[tid >> 5] = ss; }
    __syncthreads();
    float S = 0.f, SS = 0.f;
    #pragma unroll
    for (int i = 0; i < 8; i++) { S += rs[i]; SS += rss[i]; }
    const float mean = S * (1.0f / DMODEL);
    const float var  = SS * (1.0f / DMODEL) - mean * mean;
    const float inv  = rsqrtf(var + 1e-6f);
    float4 g  = ((const float4*)gamma)[tid];
    float4 bb = ((const float4*)beta)[tid];
    float4 o;
    o.x = (v.x - mean) * inv * g.x + bb.x;
    o.y = (v.y - mean) * inv * g.y + bb.y;
    o.z = (v.z - mean) * inv * g.z + bb.z;
    o.w = (v.w - mean) * inv * g.w + bb.w;
    ((float4*)(out + row * DMODEL))[tid] = o;
}

// ---------------------------------------------------------------------------
// Launch
// ---------------------------------------------------------------------------
namespace {
constexpr int SMEM_GEMM   = (128 * 40 * 2) * 4;                       // 40960
constexpr int SMEM_SCORES = (128 * 72 + 64 * 72 + 128 * 68) * 4;      // 90112
constexpr int SMEM_AV     = (128 * 72 + 64 * 72 + 128) * 4;           // 55808
}

extern "C" void kernel_launch(void* const* d_in, const int* in_sizes, int n_in,
                              void* d_out, int out_size)
{
    const float* e     = (const float*)d_in[0];
    const float* x     = (const float*)d_in[1];
    const float* We    = (const float*)d_in[2];
    const float* Wx    = (const float*)d_in[3];
    const float* Wfc   = (const float*)d_in[4];
    const float* gamma = (const float*)d_in[5];
    const float* beta  = (const float*)d_in[6];

    float* out      = (float*)d_out;
    float* out_feat = out;
    float* out_attn = out + FEAT_ELEMS;

    cudaFuncSetAttribute(gemm_kernel<0>, cudaFuncAttributeMaxDynamicSharedMemorySize, SMEM_GEMM);
    cudaFuncSetAttribute(gemm_kernel<1>, cudaFuncAttributeMaxDynamicSharedMemorySize, SMEM_GEMM);
    cudaFuncSetAttribute(gemm_kernel<2>, cudaFuncAttributeMaxDynamicSharedMemorySize, SMEM_GEMM);
    cudaFuncSetAttribute(scores_kernel, cudaFuncAttributeMaxDynamicSharedMemorySize, SMEM_SCORES);
    cudaFuncSetAttribute(av_kernel,     cudaFuncAttributeMaxDynamicSharedMemorySize, SMEM_AV);

    dim3 gp(DMODEL / 128, MROWS / 128);     // (8, 64)
    gemm_kernel<0><<<gp, 256, SMEM_GEMM>>>(e, We, nullptr);
    gemm_kernel<1><<<gp, 256, SMEM_GEMM>>>(x, Wx, nullptr);

    dim3 ga(SEQ / 128, BHTOT);              // (16, 64)
    scores_kernel<<<ga, 256, SMEM_SCORES>>>(out_attn);
    av_kernel<<<ga, 256, SMEM_AV>>>(out_attn);

    gemm_kernel<2><<<gp, 256, SMEM_GEMM>>>(nullptr, Wfc, x);

    ln_kernel<<<MROWS, 256>>>(gamma, beta, out_feat);
}

// round 5
// speedup vs baseline: 1.6452x; 1.1365x over previous
#include <cuda_runtime.h>
#include <mma.h>
#include <cstdint>

using namespace nvcuda;

// ---------------------------------------------------------------------------
// Problem constants
// ---------------------------------------------------------------------------
namespace {
constexpr int BATCH  = 4;
constexpr int HEADS  = 16;
constexpr int SEQ    = 2048;
constexpr int DH     = 64;
constexpr int DMODEL = 1024;
constexpr int MROWS  = BATCH * SEQ;           // 8192
constexpr int BHTOT  = BATCH * HEADS;         // 64
constexpr size_t HEAD_ELEMS = (size_t)BHTOT * SEQ * DH;
constexpr size_t FEAT_ELEMS = (size_t)MROWS * DMODEL;
}

// Scratch (device globals; allocation-free)
__device__ __align__(16) float g_eh[HEAD_ELEMS];    // [bh][l][64]
__device__ __align__(16) float g_xh[HEAD_ELEMS];    // [bh][64][l]  (transposed)
__device__ __align__(16) float g_feat[FEAT_ELEMS];  // [b][l][1024]
__device__ __align__(16) float g_tmp[FEAT_ELEMS];   // pre-LN
__device__ __align__(16) float g_invs[(size_t)BHTOT * SEQ];

using FragA = wmma::fragment<wmma::matrix_a, 16, 16, 8, wmma::precision::tf32, wmma::row_major>;
using FragB = wmma::fragment<wmma::matrix_b, 16, 16, 8, wmma::precision::tf32, wmma::col_major>;
using FragC = wmma::fragment<wmma::accumulator, 16, 16, 8, float>;

// ---------------------------------------------------------------------------
// cp.async helpers
// ---------------------------------------------------------------------------
__device__ __forceinline__ uint32_t smem_u32(const void* p) {
    uint32_t a;
    asm("{ .reg .u64 t; cvta.to.shared.u64 t, %1; cvt.u32.u64 %0, t; }" : "=r"(a) : "l"(p));
    return a;
}
__device__ __forceinline__ void cp16(uint32_t s, const void* g) {
    asm volatile("cp.async.cg.shared.global [%0], [%1], 16;" :: "r"(s), "l"(g));
}
#define CP_COMMIT()  asm volatile("cp.async.commit_group;" ::: "memory")
#define CP_WAIT(n)   asm volatile("cp.async.wait_group %0;" :: "n"(n) : "memory")

__device__ __forceinline__ float to_tf32f(float f) {
    uint32_t r; asm("cvt.rna.tf32.f32 %0, %1;" : "=r"(r) : "f"(f));
    return __uint_as_float(r);
}
__device__ __forceinline__ void round4(float* p) {
    float4 v = *(float4*)p;
    *(float4*)p = make_float4(to_tf32f(v.x), to_tf32f(v.y), to_tf32f(v.z), to_tf32f(v.w));
}

// ---------------------------------------------------------------------------
// GEMM: D[m,n] = sum_k A[m,k] * W[n,k]  (M=8192, N=1024, K=1024)
// Block 128x128, 8 warps (4m x 2n), warp tile 32x64. 2-stage cp.async, BK=32.
// MODE 0: A=e -> g_eh (operands rna-rounded: feeds attn precision path)
// MODE 1: A=x -> g_xh (transposed) ; MODE 2: fc+resid -> g_tmp
// ---------------------------------------------------------------------------
namespace { constexpr int GP = 36; }   // smem pad (floats), 144B rows

template <int MODE>
__global__ __launch_bounds__(256) void gemm_kernel(const float* __restrict__ Ain,
                                                   const float* __restrict__ W,
                                                   const float* __restrict__ resid)
{
    extern __shared__ float sm[];
    float* As = sm;                    // [2][128][GP]
    float* Bs = sm + 2 * 128 * GP;     // [2][128][GP]
    const int tid = threadIdx.x, wid = tid >> 5;
    const int wm = wid & 3, wn = wid >> 2;
    const int n0 = blockIdx.x * 128, m0 = blockIdx.y * 128;
    const float* A = (MODE == 2) ? g_feat : Ain;
    const uint32_t As_u = smem_u32(As), Bs_u = smem_u32(Bs);

    FragC acc[2][4];
    if (MODE == 2) {
        #pragma unroll
        for (int i = 0; i < 2; i++)
            #pragma unroll
            for (int j = 0; j < 4; j++)
                wmma::load_matrix_sync(acc[i][j],
                    resid + (size_t)(m0 + wm*32 + i*16) * DMODEL + n0 + wn*64 + j*16,
                    DMODEL, wmma::mem_row_major);
    } else {
        #pragma unroll
        for (int i = 0; i < 2; i++)
            #pragma unroll
            for (int j = 0; j < 4; j++)
                wmma::fill_fragment(acc[i][j], 0.0f);
    }

    auto stage = [&](int k0, int buf) {
        const uint32_t ao = As_u + (uint32_t)buf * 128 * GP * 4;
        const uint32_t bo = Bs_u + (uint32_t)buf * 128 * GP * 4;
        #pragma unroll
        for (int i = tid; i < 128 * 8; i += 256) {
            int r = i >> 3, c4 = (i & 7) << 2;
            cp16(ao + (uint32_t)(r * GP + c4) * 4, A + (size_t)(m0 + r) * DMODEL + k0 + c4);
            cp16(bo + (uint32_t)(r * GP + c4) * 4, W + (size_t)(n0 + r) * DMODEL + k0 + c4);
        }
    };

    stage(0, 0); CP_COMMIT();
    for (int kc = 0; kc < 32; kc++) {
        if (kc + 1 < 32) { stage((kc + 1) * 32, (kc + 1) & 1); CP_COMMIT(); CP_WAIT(1); }
        else CP_WAIT(0);
        __syncthreads();
        float* Ab = As + (kc & 1) * 128 * GP;
        float* Bb = Bs + (kc & 1) * 128 * GP;
        if (MODE == 0) {
            // rna-round operands in place (attn precision path)
            #pragma unroll
            for (int i = tid; i < 128 * 8; i += 256) {
                int r = i >> 3, c4 = (i & 7) << 2;
                round4(Ab + r * GP + c4);
                round4(Bb + r * GP + c4);
            }
            __syncthreads();
        }
        #pragma unroll
        for (int ks = 0; ks < 4; ks++) {
            FragA a[2]; FragB b[4];
            #pragma unroll
            for (int i = 0; i < 2; i++)
                wmma::load_matrix_sync(a[i], Ab + (wm*32 + i*16) * GP + ks*8, GP);
            #pragma unroll
            for (int j = 0; j < 4; j++)
                wmma::load_matrix_sync(b[j], Bb + (wn*64 + j*16) * GP + ks*8, GP);
            #pragma unroll
            for (int i = 0; i < 2; i++)
                #pragma unroll
                for (int j = 0; j < 4; j++)
                    wmma::mma_sync(acc[i][j], a[i], b[j], acc[i][j]);
        }
        __syncthreads();
    }

    const int b  = m0 >> 11;
    const int ml = m0 & 2047;
    #pragma unroll
    for (int i = 0; i < 2; i++) {
        #pragma unroll
        for (int j = 0; j < 4; j++) {
            int n = n0 + wn*64 + j*16;
            if (MODE == 0) {
                int h = n >> 6, dl = n & 63;
                wmma::store_matrix_sync(
                    g_eh + ((size_t)(b*HEADS + h) * SEQ + ml + wm*32 + i*16) * DH + dl,
                    acc[i][j], DH, wmma::mem_row_major);
            } else if (MODE == 1) {
                int h = n >> 6, dl = n & 63;
                wmma::store_matrix_sync(
                    g_xh + ((size_t)(b*HEADS + h) * DH + dl) * SEQ + ml + wm*32 + i*16,
                    acc[i][j], SEQ, wmma::mem_col_major);
            } else {
                wmma::store_matrix_sync(
                    g_tmp + (size_t)(m0 + wm*32 + i*16) * DMODEL + n,
                    acc[i][j], DMODEL, wmma::mem_row_major);
            }
        }
    }
}

// ---------------------------------------------------------------------------
// Fused attention: per CTA = 128 q-rows of one bh.
//   loop over 32 k-chunks of 64:
//     sacc = (0.125*Q) @ K^T  -> exp -> Cb(smem) -> write attn (unnormalized),
//     rowsum += ; vacc += Cb @ xh
//   end: inv = 1/rowsum -> g_invs ; feat = vacc * inv -> g_feat
// 8 warps: 4(q) x 2(n), warp tile 32x32. 2-stage cp.async on K/X tiles.
// K tile rna-rounded in place (attn precision path); Q rounded at stage.
// ---------------------------------------------------------------------------
namespace { constexpr int AP = 68; }   // pad (floats), 272B rows

__global__ __launch_bounds__(256) void attn_kernel(float* __restrict__ attn)
{
    extern __shared__ float sm[];
    float* Aq    = sm;                    // [128][AP]
    float* Bk    = Aq + 128 * AP;         // [2][64][AP]
    float* Bx    = Bk + 2 * 64 * AP;      // [2][64][AP]
    float* Cb    = Bx + 2 * 64 * AP;      // [128][AP]
    float* sinvs = Cb + 128 * AP;         // [128]
    const int tid = threadIdx.x, wid = tid >> 5;
    const int wm = wid & 3, wn = wid >> 2;
    const int bh = blockIdx.y, q0 = blockIdx.x * 128;
    const float* ehb = g_eh + (size_t)bh * SEQ * DH;
    const float* xhb = g_xh + (size_t)bh * DH * SEQ;
    const uint32_t Bk_u = smem_u32(Bk), Bx_u = smem_u32(Bx);

    auto stage = [&](int k0, int buf) {
        const uint32_t ko = Bk_u + (uint32_t)buf * 64 * AP * 4;
        const uint32_t xo = Bx_u + (uint32_t)buf * 64 * AP * 4;
        #pragma unroll
        for (int i = tid; i < 64 * 16; i += 256) {
            int r = i >> 4, c4 = (i & 15) << 2;
            cp16(ko + (uint32_t)(r * AP + c4) * 4, ehb + (size_t)(k0 + r) * DH + c4);
            cp16(xo + (uint32_t)(r * AP + c4) * 4, xhb + (size_t)r * SEQ + k0 + c4);
        }
    };

    stage(0, 0); CP_COMMIT();

    // stage Q (scaled by 1/8, rna tf32-rounded) — one-time
    #pragma unroll
    for (int i = tid; i < 128 * 16; i += 256) {
        int r = i >> 4, c4 = (i & 15) << 2;
        float4 v = *(const float4*)(ehb + (size_t)(q0 + r) * DH + c4);
        *(float4*)(Aq + r * AP + c4) =
            make_float4(to_tf32f(v.x * 0.125f), to_tf32f(v.y * 0.125f),
                        to_tf32f(v.z * 0.125f), to_tf32f(v.w * 0.125f));
    }

    FragC vacc[2][2];
    #pragma unroll
    for (int i = 0; i < 2; i++)
        #pragma unroll
        for (int j = 0; j < 2; j++)
            wmma::fill_fragment(vacc[i][j], 0.0f);

    float rsum = 0.0f;
    float* arow = attn + ((size_t)bh * SEQ + q0 + (tid >> 1)) * SEQ + (tid & 1) * 32;

    for (int kc = 0; kc < 32; kc++) {
        if (kc + 1 < 32) { stage((kc + 1) * 64, (kc + 1) & 1); CP_COMMIT(); CP_WAIT(1); }
        else CP_WAIT(0);
        __syncthreads();
        float* Kb = Bk + (kc & 1) * 64 * AP;
        const float* Xb = Bx + (kc & 1) * 64 * AP;

        // rna-round K tile in place
        #pragma unroll
        for (int i = tid; i < 64 * 16; i += 256) {
            int r = i >> 4, c4 = (i & 15) << 2;
            round4(Kb + r * AP + c4);
        }
        __syncthreads();

        // ---- scores MMA ----
        FragC sacc[2][2];
        #pragma unroll
        for (int i = 0; i < 2; i++)
            #pragma unroll
            for (int j = 0; j < 2; j++)
                wmma::fill_fragment(sacc[i][j], 0.0f);
        #pragma unroll
        for (int ks = 0; ks < 8; ks++) {
            FragA a[2]; FragB b[2];
            #pragma unroll
            for (int i = 0; i < 2; i++)
                wmma::load_matrix_sync(a[i], Aq + (wm*32 + i*16) * AP + ks*8, AP);
            #pragma unroll
            for (int j = 0; j < 2; j++)
                wmma::load_matrix_sync(b[j], Kb + (wn*32 + j*16) * AP + ks*8, AP);
            #pragma unroll
            for (int i = 0; i < 2; i++)
                #pragma unroll
                for (int j = 0; j < 2; j++)
                    wmma::mma_sync(sacc[i][j], a[i], b[j], sacc[i][j]);
        }
        // ---- exp, park in Cb ----
        #pragma unroll
        for (int i = 0; i < 2; i++) {
            #pragma unroll
            for (int j = 0; j < 2; j++) {
                #pragma unroll
                for (int e = 0; e < sacc[i][j].num_elements; e++)
                    sacc[i][j].x[e] = __expf(sacc[i][j].x[e]);
                wmma::store_matrix_sync(Cb + (wm*32 + i*16) * AP + wn*32 + j*16,
                                        sacc[i][j], AP, wmma::mem_row_major);
            }
        }
        __syncthreads();

        // ---- AV MMA: Cb (E tile) @ xh ----
        #pragma unroll
        for (int ks = 0; ks < 8; ks++) {
            FragA a[2]; FragB b[2];
            #pragma unroll
            for (int i = 0; i < 2; i++)
                wmma::load_matrix_sync(a[i], Cb + (wm*32 + i*16) * AP + ks*8, AP);
            #pragma unroll
            for (int j = 0; j < 2; j++)
                wmma::load_matrix_sync(b[j], Xb + (wn*32 + j*16) * AP + ks*8, AP);
            #pragma unroll
            for (int i = 0; i < 2; i++)
                #pragma unroll
                for (int j = 0; j < 2; j++)
                    wmma::mma_sync(vacc[i][j], a[i], b[j], vacc[i][j]);
        }

        // ---- rowsum + write unnormalized E (2 threads per row) ----
        {
            const float* src = Cb + (tid >> 1) * AP + (tid & 1) * 32;
            float4* dst = (float4*)(arow + kc * 64);
            #pragma unroll
            for (int q = 0; q < 8; q++) {
                float4 v = ((const float4*)src)[q];
                rsum += v.x + v.y + v.z + v.w;
                dst[q] = v;
            }
        }
        __syncthreads();
    }

    // ---- rowsum combine, publish inv ----
    float tot = rsum + __shfl_xor_sync(0xffffffffu, rsum, 1);
    float inv = 1.0f / tot;
    if (!(tid & 1)) {
        g_invs[(size_t)bh * SEQ + q0 + (tid >> 1)] = inv;
        sinvs[tid >> 1] = inv;
    }
    __syncthreads();

    // ---- dump vacc to Cb, scale rows, write g_feat ----
    #pragma unroll
    for (int i = 0; i < 2; i++)
        #pragma unroll
        for (int j = 0; j < 2; j++)
            wmma::store_matrix_sync(Cb + (wm*32 + i*16) * AP + wn*32 + j*16,
                                    vacc[i][j], AP, wmma::mem_row_major);
    __syncthreads();
    const int b = bh >> 4, h = bh & 15;
    #pragma unroll
    for (int i = tid; i < 128 * 16; i += 256) {
        int r = i >> 4, c4 = (i & 15) << 2;
        float is = sinvs[r];
        float4 v = *(const float4*)(Cb + r * AP + c4);
        v.x *= is; v.y *= is; v.z *= is; v.w *= is;
        *(float4*)&g_feat[((size_t)(b * SEQ) + q0 + r) * DMODEL + h * DH + c4] = v;
    }
}

// ---------------------------------------------------------------------------
// Normalize attn rows in place: attn[row,:] *= g_invs[row]. Pure streaming.
// ---------------------------------------------------------------------------
__global__ __launch_bounds__(256) void norm_attn_kernel(float* __restrict__ attn)
{
    const size_t row = blockIdx.x;
    const float inv = g_invs[row];
    float4* p = (float4*)(attn + row * SEQ);
    const int tid = threadIdx.x;
    #pragma unroll
    for (int i = 0; i < 2; i++) {
        float4 v = p[tid + i * 256];
        v.x *= inv; v.y *= inv; v.z *= inv; v.w *= inv;
        p[tid + i * 256] = v;
    }
}

// ---------------------------------------------------------------------------
// LayerNorm over last dim (1024), eps=1e-6. One block (256 thr) per row.
// ---------------------------------------------------------------------------
__device__ __forceinline__ float warp_sum(float v) {
    #pragma unroll
    for (int o = 16; o; o >>= 1) v += __shfl_xor_sync(0xffffffffu, v, o);
    return v;
}
__global__ __launch_bounds__(256) void ln_kernel(const float* __restrict__ gamma,
                                                 const float* __restrict__ beta,
                                                 float* __restrict__ out)
{
    const int tid = threadIdx.x;
    const size_t row = blockIdx.x;
    const float* p = g_tmp + row * DMODEL;
    float4 v = ((const float4*)p)[tid];
    float s  = v.x + v.y + v.z + v.w;
    float ss = v.x*v.x + v.y*v.y + v.z*v.z + v.w*v.w;
    s = warp_sum(s); ss = warp_sum(ss);
    __shared__ float rs[8], rss[8];
    if ((tid & 31) == 0) { rs[tid >> 5] = s; rss[tid >> 5] = ss; }
    __syncthreads();
    float S = 0.f, SS = 0.f;
    #pragma unroll
    for (int i = 0; i < 8; i++) { S += rs[i]; SS += rss[i]; }
    const float mean = S * (1.0f / DMODEL);
    const float var  = SS * (1.0f / DMODEL) - mean * mean;
    const float inv  = rsqrtf(var + 1e-6f);
    float4 g  = ((const float4*)gamma)[tid];
    float4 bb = ((const float4*)beta)[tid];
    float4 o;
    o.x = (v.x - mean) * inv * g.x + bb.x;
    o.y = (v.y - mean) * inv * g.y + bb.y;
    o.z = (v.z - mean) * inv * g.z + bb.z;
    o.w = (v.w - mean) * inv * g.w + bb.w;
    ((float4*)(out + row * DMODEL))[tid] = o;
}

// ---------------------------------------------------------------------------
// Launch
// ---------------------------------------------------------------------------
namespace {
constexpr int SMEM_GEMM = 2 * 2 * 128 * GP * 4;                    // 73728
constexpr int SMEM_ATTN = (128*AP + 2*64*AP + 2*64*AP + 128*AP + 128) * 4;  // 139776
}

extern "C" void kernel_launch(void* const* d_in, const int* in_sizes, int n_in,
                              void* d_out, int out_size)
{
    const float* e     = (const float*)d_in[0];
    const float* x     = (const float*)d_in[1];
    const float* We    = (const float*)d_in[2];
    const float* Wx    = (const float*)d_in[3];
    const float* Wfc   = (const float*)d_in[4];
    const float* gamma = (const float*)d_in[5];
    const float* beta  = (const float*)d_in[6];

    float* out      = (float*)d_out;
    float* out_feat = out;
    float* out_attn = out + FEAT_ELEMS;

    cudaFuncSetAttribute(gemm_kernel<0>, cudaFuncAttributeMaxDynamicSharedMemorySize, SMEM_GEMM);
    cudaFuncSetAttribute(gemm_kernel<1>, cudaFuncAttributeMaxDynamicSharedMemorySize, SMEM_GEMM);
    cudaFuncSetAttribute(gemm_kernel<2>, cudaFuncAttributeMaxDynamicSharedMemorySize, SMEM_GEMM);
    cudaFuncSetAttribute(attn_kernel,    cudaFuncAttributeMaxDynamicSharedMemorySize, SMEM_ATTN);

    dim3 gp(DMODEL / 128, MROWS / 128);     // (8, 64)
    gemm_kernel<0><<<gp, 256, SMEM_GEMM>>>(e, We, nullptr);
    gemm_kernel<1><<<gp, 256, SMEM_GEMM>>>(x, Wx, nullptr);

    dim3 ga(SEQ / 128, BHTOT);              // (16, 64)
    attn_kernel<<<ga, 256, SMEM_ATTN>>>(out_attn);

    norm_attn_kernel<<<BHTOT * SEQ, 256>>>(out_attn);

    gemm_kernel<2><<<gp, 256, SMEM_GEMM>>>(nullptr, Wfc, x);

    ln_kernel<<<MROWS, 256>>>(gamma, beta, out_feat);
}

// round 6
// speedup vs baseline: 1.8753x; 1.1398x over previous
#include <cuda_runtime.h>
#include <mma.h>
#include <cstdint>

using namespace nvcuda;

// ---------------------------------------------------------------------------
// Problem constants
// ---------------------------------------------------------------------------
namespace {
constexpr int BATCH  = 4;
constexpr int HEADS  = 16;
constexpr int SEQ    = 2048;
constexpr int DH     = 64;
constexpr int DMODEL = 1024;
constexpr int MROWS  = BATCH * SEQ;           // 8192
constexpr int BHTOT  = BATCH * HEADS;         // 64
constexpr size_t HEAD_ELEMS = (size_t)BHTOT * SEQ * DH;
constexpr size_t FEAT_ELEMS = (size_t)MROWS * DMODEL;
}

// Scratch (device globals; allocation-free)
__device__ __align__(16) float g_eh[HEAD_ELEMS];    // [bh][l][64]  (tf32-exact values)
__device__ __align__(16) float g_xh[HEAD_ELEMS];    // [bh][64][l]  (transposed)
__device__ __align__(16) float g_feat[FEAT_ELEMS];  // [b][l][1024]
__device__ __align__(16) float g_tmp[FEAT_ELEMS];   // pre-LN
__device__ __align__(16) float g_invs[(size_t)BHTOT * SEQ];

using FragA = wmma::fragment<wmma::matrix_a, 16, 16, 8, wmma::precision::tf32, wmma::row_major>;
using FragB = wmma::fragment<wmma::matrix_b, 16, 16, 8, wmma::precision::tf32, wmma::col_major>;
using FragC = wmma::fragment<wmma::accumulator, 16, 16, 8, float>;

// ---------------------------------------------------------------------------
// helpers
// ---------------------------------------------------------------------------
__device__ __forceinline__ uint32_t smem_u32(const void* p) {
    uint32_t a;
    asm("{ .reg .u64 t; cvta.to.shared.u64 t, %1; cvt.u32.u64 %0, t; }" : "=r"(a) : "l"(p));
    return a;
}
__device__ __forceinline__ void cp16(uint32_t s, const void* g) {
    asm volatile("cp.async.cg.shared.global [%0], [%1], 16;" :: "r"(s), "l"(g));
}
#define CP_COMMIT()  asm volatile("cp.async.commit_group;" ::: "memory")
#define CP_WAIT(n)   asm volatile("cp.async.wait_group %0;" :: "n"(n) : "memory")

__device__ __forceinline__ float to_tf32f(float f) {
    uint32_t r; asm("cvt.rna.tf32.f32 %0, %1;" : "=r"(r) : "f"(f));
    return __uint_as_float(r);
}
__device__ __forceinline__ void round4(float* p) {
    float4 v = *(float4*)p;
    *(float4*)p = make_float4(to_tf32f(v.x), to_tf32f(v.y), to_tf32f(v.z), to_tf32f(v.w));
}

// ---------------------------------------------------------------------------
// GEMM: D[m,n] = sum_k A[m,k] * W[n,k]  (M=8192, N=1024, K=1024)
// Block 128x128, 8 warps (4m x 2n). 2-stage cp.async, BK=32.
// mode 0: A=e -> g_eh   (operands rna-rounded per chunk; OUTPUT rna-rounded
//                        so g_eh is tf32-exact -> attn needs no rounding)
// mode 1: A=x -> g_xh (transposed)
// mode 2: A=g_feat, acc init = residual x -> g_tmp
// modes 0 and 1 launched together via gridDim.z.
// ---------------------------------------------------------------------------
namespace { constexpr int GP = 36; }   // smem pad (floats)

__global__ __launch_bounds__(256, 2) void gemm_kernel(const float* __restrict__ e,
                                                      const float* __restrict__ x,
                                                      const float* __restrict__ We,
                                                      const float* __restrict__ Wx,
                                                      const float* __restrict__ Wfc,
                                                      int mode_base)
{
    extern __shared__ float sm[];
    float* As = sm;                    // [2][128][GP]
    float* Bs = sm + 2 * 128 * GP;     // [2][128][GP]
    const int tid = threadIdx.x, wid = tid >> 5;
    const int wm = wid & 3, wn = wid >> 2;
    const int n0 = blockIdx.x * 128, m0 = blockIdx.y * 128;
    const int mode = mode_base + blockIdx.z;

    const float* A = (mode == 0) ? e : (mode == 1) ? x : g_feat;
    const float* W = (mode == 0) ? We : (mode == 1) ? Wx : Wfc;
    const uint32_t As_u = smem_u32(As), Bs_u = smem_u32(Bs);

    FragC acc[2][4];
    if (mode == 2) {
        #pragma unroll
        for (int i = 0; i < 2; i++)
            #pragma unroll
            for (int j = 0; j < 4; j++)
                wmma::load_matrix_sync(acc[i][j],
                    x + (size_t)(m0 + wm*32 + i*16) * DMODEL + n0 + wn*64 + j*16,
                    DMODEL, wmma::mem_row_major);
    } else {
        #pragma unroll
        for (int i = 0; i < 2; i++)
            #pragma unroll
            for (int j = 0; j < 4; j++)
                wmma::fill_fragment(acc[i][j], 0.0f);
    }

    auto stage = [&](int k0, int buf) {
        const uint32_t ao = As_u + (uint32_t)buf * 128 * GP * 4;
        const uint32_t bo = Bs_u + (uint32_t)buf * 128 * GP * 4;
        #pragma unroll
        for (int i = tid; i < 128 * 8; i += 256) {
            int r = i >> 3, c4 = (i & 7) << 2;
            cp16(ao + (uint32_t)(r * GP + c4) * 4, A + (size_t)(m0 + r) * DMODEL + k0 + c4);
            cp16(bo + (uint32_t)(r * GP + c4) * 4, W + (size_t)(n0 + r) * DMODEL + k0 + c4);
        }
    };

    stage(0, 0); CP_COMMIT();
    for (int kc = 0; kc < 32; kc++) {
        if (kc + 1 < 32) { stage((kc + 1) * 32, (kc + 1) & 1); CP_COMMIT(); CP_WAIT(1); }
        else CP_WAIT(0);
        __syncthreads();
        float* Ab = As + (kc & 1) * 128 * GP;
        float* Bb = Bs + (kc & 1) * 128 * GP;
        if (mode == 0) {
            // rna-round operands in place (attn precision path)
            #pragma unroll
            for (int i = tid; i < 128 * 8; i += 256) {
                int r = i >> 3, c4 = (i & 7) << 2;
                round4(Ab + r * GP + c4);
                round4(Bb + r * GP + c4);
            }
            __syncthreads();
        }
        #pragma unroll
        for (int ks = 0; ks < 4; ks++) {
            FragA a[2]; FragB b[4];
            #pragma unroll
            for (int i = 0; i < 2; i++)
                wmma::load_matrix_sync(a[i], Ab + (wm*32 + i*16) * GP + ks*8, GP);
            #pragma unroll
            for (int j = 0; j < 4; j++)
                wmma::load_matrix_sync(b[j], Bb + (wn*64 + j*16) * GP + ks*8, GP);
            #pragma unroll
            for (int i = 0; i < 2; i++)
                #pragma unroll
                for (int j = 0; j < 4; j++)
                    wmma::mma_sync(acc[i][j], a[i], b[j], acc[i][j]);
        }
        __syncthreads();
    }

    const int b  = m0 >> 11;
    const int ml = m0 & 2047;
    #pragma unroll
    for (int i = 0; i < 2; i++) {
        #pragma unroll
        for (int j = 0; j < 4; j++) {
            int n = n0 + wn*64 + j*16;
            if (mode == 0) {
                // round output to tf32-exact before store
                #pragma unroll
                for (int t = 0; t < acc[i][j].num_elements; t++)
                    acc[i][j].x[t] = to_tf32f(acc[i][j].x[t]);
                int h = n >> 6, dl = n & 63;
                wmma::store_matrix_sync(
                    g_eh + ((size_t)(b*HEADS + h) * SEQ + ml + wm*32 + i*16) * DH + dl,
                    acc[i][j], DH, wmma::mem_row_major);
            } else if (mode == 1) {
                int h = n >> 6, dl = n & 63;
                wmma::store_matrix_sync(
                    g_xh + ((size_t)(b*HEADS + h) * DH + dl) * SEQ + ml + wm*32 + i*16,
                    acc[i][j], SEQ, wmma::mem_col_major);
            } else {
                wmma::store_matrix_sync(
                    g_tmp + (size_t)(m0 + wm*32 + i*16) * DMODEL + n,
                    acc[i][j], DMODEL, wmma::mem_row_major);
            }
        }
    }
}

// ---------------------------------------------------------------------------
// Fused attention: per CTA = 128 q-rows of one bh.
// Single-buffered smem (~104 KB) -> 2 CTAs/SM; cross-CTA overlap hides loads.
// g_eh is tf32-exact so no operand rounding needed anywhere here.
// ---------------------------------------------------------------------------
namespace { constexpr int AP = 68; }   // pad (floats)

__global__ __launch_bounds__(256, 2) void attn_kernel(float* __restrict__ attn)
{
    extern __shared__ float sm[];
    float* Aq    = sm;                 // [128][AP]
    float* Bk    = Aq + 128 * AP;      // [64][AP]
    float* Bx    = Bk + 64 * AP;       // [64][AP]
    float* Cb    = Bx + 64 * AP;       // [128][AP]
    float* sinvs = Cb + 128 * AP;      // [128]
    const int tid = threadIdx.x, wid = tid >> 5;
    const int wm = wid & 3, wn = wid >> 2;
    const int bh = blockIdx.y, q0 = blockIdx.x * 128;
    const float* ehb = g_eh + (size_t)bh * SEQ * DH;
    const float* xhb = g_xh + (size_t)bh * DH * SEQ;
    const uint32_t Bk_u = smem_u32(Bk), Bx_u = smem_u32(Bx);

    // stage Q (x 1/8: exponent shift on tf32-exact values -> still exact)
    #pragma unroll
    for (int i = tid; i < 128 * 16; i += 256) {
        int r = i >> 4, c4 = (i & 15) << 2;
        float4 v = *(const float4*)(ehb + (size_t)(q0 + r) * DH + c4);
        *(float4*)(Aq + r * AP + c4) =
            make_float4(v.x * 0.125f, v.y * 0.125f, v.z * 0.125f, v.w * 0.125f);
    }

    FragC vacc[2][2];
    #pragma unroll
    for (int i = 0; i < 2; i++)
        #pragma unroll
        for (int j = 0; j < 2; j++)
            wmma::fill_fragment(vacc[i][j], 0.0f);

    float rsum = 0.0f;
    float* arow = attn + ((size_t)bh * SEQ + q0 + (tid >> 1)) * SEQ + (tid & 1) * 32;

    for (int kc = 0; kc < 32; kc++) {
        const int k0 = kc * 64;
        __syncthreads();   // prev AV MMA / rowsum done with Bx/Cb; Q staged (kc==0)
        #pragma unroll
        for (int i = tid; i < 64 * 16; i += 256) {
            int r = i >> 4, c4 = (i & 15) << 2;
            cp16(Bk_u + (uint32_t)(r * AP + c4) * 4, ehb + (size_t)(k0 + r) * DH + c4);
            cp16(Bx_u + (uint32_t)(r * AP + c4) * 4, xhb + (size_t)r * SEQ + k0 + c4);
        }
        CP_COMMIT(); CP_WAIT(0);
        __syncthreads();

        // ---- scores MMA ----
        FragC sacc[2][2];
        #pragma unroll
        for (int i = 0; i < 2; i++)
            #pragma unroll
            for (int j = 0; j < 2; j++)
                wmma::fill_fragment(sacc[i][j], 0.0f);
        #pragma unroll
        for (int ks = 0; ks < 8; ks++) {
            FragA a[2]; FragB b[2];
            #pragma unroll
            for (int i = 0; i < 2; i++)
                wmma::load_matrix_sync(a[i], Aq + (wm*32 + i*16) * AP + ks*8, AP);
            #pragma unroll
            for (int j = 0; j < 2; j++)
                wmma::load_matrix_sync(b[j], Bk + (wn*32 + j*16) * AP + ks*8, AP);
            #pragma unroll
            for (int i = 0; i < 2; i++)
                #pragma unroll
                for (int j = 0; j < 2; j++)
                    wmma::mma_sync(sacc[i][j], a[i], b[j], sacc[i][j]);
        }
        // ---- exp, park in Cb ----
        #pragma unroll
        for (int i = 0; i < 2; i++) {
            #pragma unroll
            for (int j = 0; j < 2; j++) {
                #pragma unroll
                for (int t = 0; t < sacc[i][j].num_elements; t++)
                    sacc[i][j].x[t] = __expf(sacc[i][j].x[t]);
                wmma::store_matrix_sync(Cb + (wm*32 + i*16) * AP + wn*32 + j*16,
                                        sacc[i][j], AP, wmma::mem_row_major);
            }
        }
        __syncthreads();

        // ---- AV MMA: vacc += Cb @ xh ----
        #pragma unroll
        for (int ks = 0; ks < 8; ks++) {
            FragA a[2]; FragB b[2];
            #pragma unroll
            for (int i = 0; i < 2; i++)
                wmma::load_matrix_sync(a[i], Cb + (wm*32 + i*16) * AP + ks*8, AP);
            #pragma unroll
            for (int j = 0; j < 2; j++)
                wmma::load_matrix_sync(b[j], Bx + (wn*32 + j*16) * AP + ks*8, AP);
            #pragma unroll
            for (int i = 0; i < 2; i++)
                #pragma unroll
                for (int j = 0; j < 2; j++)
                    wmma::mma_sync(vacc[i][j], a[i], b[j], vacc[i][j]);
        }

        // ---- rowsum + write unnormalized E (2 threads per row) ----
        {
            const float* src = Cb + (tid >> 1) * AP + (tid & 1) * 32;
            float4* dst = (float4*)(arow + kc * 64);
            #pragma unroll
            for (int q = 0; q < 8; q++) {
                float4 v = ((const float4*)src)[q];
                rsum += v.x + v.y + v.z + v.w;
                __stcs(dst + q, v);
            }
        }
    }
    __syncthreads();

    // ---- rowsum combine, publish inv ----
    float tot = rsum + __shfl_xor_sync(0xffffffffu, rsum, 1);
    float inv = 1.0f / tot;
    if (!(tid & 1)) {
        g_invs[(size_t)bh * SEQ + q0 + (tid >> 1)] = inv;
        sinvs[tid >> 1] = inv;
    }
    __syncthreads();

    // ---- dump vacc to Cb, scale rows, write g_feat ----
    #pragma unroll
    for (int i = 0; i < 2; i++)
        #pragma unroll
        for (int j = 0; j < 2; j++)
            wmma::store_matrix_sync(Cb + (wm*32 + i*16) * AP + wn*32 + j*16,
                                    vacc[i][j], AP, wmma::mem_row_major);
    __syncthreads();
    const int b = bh >> 4, h = bh & 15;
    #pragma unroll
    for (int i = tid; i < 128 * 16; i += 256) {
        int r = i >> 4, c4 = (i & 15) << 2;
        float is = sinvs[r];
        float4 v = *(const float4*)(Cb + r * AP + c4);
        v.x *= is; v.y *= is; v.z *= is; v.w *= is;
        *(float4*)&g_feat[((size_t)(b * SEQ) + q0 + r) * DMODEL + h * DH + c4] = v;
    }
}

// ---------------------------------------------------------------------------
// Normalize attn rows in place: attn[row,:] *= g_invs[row]. Pure streaming.
// ---------------------------------------------------------------------------
__global__ __launch_bounds__(256) void norm_attn_kernel(float* __restrict__ attn)
{
    const size_t row = blockIdx.x;
    const float inv = g_invs[row];
    float4* p = (float4*)(attn + row * SEQ);
    const int tid = threadIdx.x;
    #pragma unroll
    for (int i = 0; i < 2; i++) {
        float4 v = __ldcs(p + tid + i * 256);
        v.x *= inv; v.y *= inv; v.z *= inv; v.w *= inv;
        __stcs(p + tid + i * 256, v);
    }
}

// ---------------------------------------------------------------------------
// LayerNorm over last dim (1024), eps=1e-6. One block (256 thr) per row.
// ---------------------------------------------------------------------------
__device__ __forceinline__ float warp_sum(float v) {
    #pragma unroll
    for (int o = 16; o; o >>= 1) v += __shfl_xor_sync(0xffffffffu, v, o);
    return v;
}
__global__ __launch_bounds__(256) void ln_kernel(const float* __restrict__ gamma,
                                                 const float* __restrict__ beta,
                                                 float* __restrict__ out)
{
    const int tid = threadIdx.x;
    const size_t row = blockIdx.x;
    const float* p = g_tmp + row * DMODEL;
    float4 v = ((const float4*)p)[tid];
    float s  = v.x + v.y + v.z + v.w;
    float ss = v.x*v.x + v.y*v.y + v.z*v.z + v.w*v.w;
    s = warp_sum(s); ss = warp_sum(ss);
    __shared__ float rs[8], rss[8];
    if ((tid & 31) == 0) { rs[tid >> 5] = s; rss[tid >> 5] = ss; }
    __syncthreads();
    float S = 0.f, SS = 0.f;
    #pragma unroll
    for (int i = 0; i < 8; i++) { S += rs[i]; SS += rss[i]; }
    const float mean = S * (1.0f / DMODEL);
    const float var  = SS * (1.0f / DMODEL) - mean * mean;
    const float inv  = rsqrtf(var + 1e-6f);
    float4 g  = ((const float4*)gamma)[tid];
    float4 bb = ((const float4*)beta)[tid];
    float4 o;
    o.x = (v.x - mean) * inv * g.x + bb.x;
    o.y = (v.y - mean) * inv * g.y + bb.y;
    o.z = (v.z - mean) * inv * g.z + bb.z;
    o.w = (v.w - mean) * inv * g.w + bb.w;
    ((float4*)(out + row * DMODEL))[tid] = o;
}

// ---------------------------------------------------------------------------
// Launch
// ---------------------------------------------------------------------------
namespace {
constexpr int SMEM_GEMM = 2 * 2 * 128 * GP * 4;                 // 73728
constexpr int SMEM_ATTN = (384 * AP + 128) * 4;                 // 104960
}

extern "C" void kernel_launch(void* const* d_in, const int* in_sizes, int n_in,
                              void* d_out, int out_size)
{
    const float* e     = (const float*)d_in[0];
    const float* x     = (const float*)d_in[1];
    const float* We    = (const float*)d_in[2];
    const float* Wx    = (const float*)d_in[3];
    const float* Wfc   = (const float*)d_in[4];
    const float* gamma = (const float*)d_in[5];
    const float* beta  = (const float*)d_in[6];

    float* out      = (float*)d_out;
    float* out_feat = out;
    float* out_attn = out + FEAT_ELEMS;

    cudaFuncSetAttribute(gemm_kernel, cudaFuncAttributeMaxDynamicSharedMemorySize, SMEM_GEMM);
    cudaFuncSetAttribute(attn_kernel, cudaFuncAttributeMaxDynamicSharedMemorySize, SMEM_ATTN);

    // both projections in one launch (z = mode)
    gemm_kernel<<<dim3(DMODEL / 128, MROWS / 128, 2), 256, SMEM_GEMM>>>(
        e, x, We, Wx, Wfc, 0);

    dim3 ga(SEQ / 128, BHTOT);              // (16, 64)
    attn_kernel<<<ga, 256, SMEM_ATTN>>>(out_attn);

    norm_attn_kernel<<<BHTOT * SEQ, 256>>>(out_attn);

    // fc + residual
    gemm_kernel<<<dim3(DMODEL / 128, MROWS / 128, 1), 256, SMEM_GEMM>>>(
        e, x, We, Wx, Wfc, 2);

    ln_kernel<<<MROWS, 256>>>(gamma, beta, out_feat);
}

// round 8
// speedup vs baseline: 1.8882x; 1.0069x over previous
#include <cuda_runtime.h>
#include <mma.h>
#include <cstdint>

using namespace nvcuda;

// ---------------------------------------------------------------------------
// Problem constants
// ---------------------------------------------------------------------------
namespace {
constexpr int BATCH  = 4;
constexpr int HEADS  = 16;
constexpr int SEQ    = 2048;
constexpr int DH     = 64;
constexpr int DMODEL = 1024;
constexpr int MROWS  = BATCH * SEQ;           // 8192
constexpr int BHTOT  = BATCH * HEADS;         // 64
constexpr size_t HEAD_ELEMS = (size_t)BHTOT * SEQ * DH;
constexpr size_t FEAT_ELEMS = (size_t)MROWS * DMODEL;
}

// Scratch (device globals; allocation-free)
__device__ __align__(16) float g_eh[HEAD_ELEMS];    // [bh][l][64]  (tf32-exact values)
__device__ __align__(16) float g_xh[HEAD_ELEMS];    // [bh][64][l]  (transposed)
__device__ __align__(16) float g_feat[FEAT_ELEMS];  // [b][l][1024]
__device__ __align__(16) float g_tmp[FEAT_ELEMS];   // pre-LN
__device__ __align__(16) float g_invs[(size_t)BHTOT * SEQ];

using FragA = wmma::fragment<wmma::matrix_a, 16, 16, 8, wmma::precision::tf32, wmma::row_major>;
using FragB = wmma::fragment<wmma::matrix_b, 16, 16, 8, wmma::precision::tf32, wmma::col_major>;
using FragC = wmma::fragment<wmma::accumulator, 16, 16, 8, float>;

// ---------------------------------------------------------------------------
// helpers
// ---------------------------------------------------------------------------
__device__ __forceinline__ uint32_t smem_u32(const void* p) {
    uint32_t a;
    asm("{ .reg .u64 t; cvta.to.shared.u64 t, %1; cvt.u32.u64 %0, t; }" : "=r"(a) : "l"(p));
    return a;
}
__device__ __forceinline__ void cp16(uint32_t s, const void* g) {
    asm volatile("cp.async.cg.shared.global [%0], [%1], 16;" :: "r"(s), "l"(g));
}
#define CP_COMMIT()  asm volatile("cp.async.commit_group;" ::: "memory")
#define CP_WAIT(n)   asm volatile("cp.async.wait_group %0;" :: "n"(n) : "memory")

__device__ __forceinline__ float to_tf32f(float f) {
    uint32_t r; asm("cvt.rna.tf32.f32 %0, %1;" : "=r"(r) : "f"(f));
    return __uint_as_float(r);
}
__device__ __forceinline__ void round4(float* p) {
    float4 v = *(float4*)p;
    *(float4*)p = make_float4(to_tf32f(v.x), to_tf32f(v.y), to_tf32f(v.z), to_tf32f(v.w));
}

// ---------------------------------------------------------------------------
// GEMM: D[m,n] = sum_k A[m,k] * W[n,k]  (M=8192, N=1024, K=1024)
// Block 128x128, 8 warps (4m x 2n). 2-stage cp.async, BK=32.  (unchanged, R6)
// mode 0: A=e -> g_eh ; mode 1: A=x -> g_xh (transposed) ; mode 2: fc+resid
// ---------------------------------------------------------------------------
namespace { constexpr int GP = 36; }   // smem pad (floats)

__global__ __launch_bounds__(256, 2) void gemm_kernel(const float* __restrict__ e,
                                                      const float* __restrict__ x,
                                                      const float* __restrict__ We,
                                                      const float* __restrict__ Wx,
                                                      const float* __restrict__ Wfc,
                                                      int mode_base)
{
    extern __shared__ float sm[];
    float* As = sm;                    // [2][128][GP]
    float* Bs = sm + 2 * 128 * GP;     // [2][128][GP]
    const int tid = threadIdx.x, wid = tid >> 5;
    const int wm = wid & 3, wn = wid >> 2;
    const int n0 = blockIdx.x * 128, m0 = blockIdx.y * 128;
    const int mode = mode_base + blockIdx.z;

    const float* A = (mode == 0) ? e : (mode == 1) ? x : g_feat;
    const float* W = (mode == 0) ? We : (mode == 1) ? Wx : Wfc;
    const uint32_t As_u = smem_u32(As), Bs_u = smem_u32(Bs);

    FragC acc[2][4];
    if (mode == 2) {
        #pragma unroll
        for (int i = 0; i < 2; i++)
            #pragma unroll
            for (int j = 0; j < 4; j++)
                wmma::load_matrix_sync(acc[i][j],
                    x + (size_t)(m0 + wm*32 + i*16) * DMODEL + n0 + wn*64 + j*16,
                    DMODEL, wmma::mem_row_major);
    } else {
        #pragma unroll
        for (int i = 0; i < 2; i++)
            #pragma unroll
            for (int j = 0; j < 4; j++)
                wmma::fill_fragment(acc[i][j], 0.0f);
    }

    auto stage = [&](int k0, int buf) {
        const uint32_t ao = As_u + (uint32_t)buf * 128 * GP * 4;
        const uint32_t bo = Bs_u + (uint32_t)buf * 128 * GP * 4;
        #pragma unroll
        for (int i = tid; i < 128 * 8; i += 256) {
            int r = i >> 3, c4 = (i & 7) << 2;
            cp16(ao + (uint32_t)(r * GP + c4) * 4, A + (size_t)(m0 + r) * DMODEL + k0 + c4);
            cp16(bo + (uint32_t)(r * GP + c4) * 4, W + (size_t)(n0 + r) * DMODEL + k0 + c4);
        }
    };

    stage(0, 0); CP_COMMIT();
    for (int kc = 0; kc < 32; kc++) {
        if (kc + 1 < 32) { stage((kc + 1) * 32, (kc + 1) & 1); CP_COMMIT(); CP_WAIT(1); }
        else CP_WAIT(0);
        __syncthreads();
        float* Ab = As + (kc & 1) * 128 * GP;
        float* Bb = Bs + (kc & 1) * 128 * GP;
        if (mode == 0) {
            #pragma unroll
            for (int i = tid; i < 128 * 8; i += 256) {
                int r = i >> 3, c4 = (i & 7) << 2;
                round4(Ab + r * GP + c4);
                round4(Bb + r * GP + c4);
            }
            __syncthreads();
        }
        #pragma unroll
        for (int ks = 0; ks < 4; ks++) {
            FragA a[2]; FragB b[4];
            #pragma unroll
            for (int i = 0; i < 2; i++)
                wmma::load_matrix_sync(a[i], Ab + (wm*32 + i*16) * GP + ks*8, GP);
            #pragma unroll
            for (int j = 0; j < 4; j++)
                wmma::load_matrix_sync(b[j], Bb + (wn*64 + j*16) * GP + ks*8, GP);
            #pragma unroll
            for (int i = 0; i < 2; i++)
                #pragma unroll
                for (int j = 0; j < 4; j++)
                    wmma::mma_sync(acc[i][j], a[i], b[j], acc[i][j]);
        }
        __syncthreads();
    }

    const int b  = m0 >> 11;
    const int ml = m0 & 2047;
    #pragma unroll
    for (int i = 0; i < 2; i++) {
        #pragma unroll
        for (int j = 0; j < 4; j++) {
            int n = n0 + wn*64 + j*16;
            if (mode == 0) {
                #pragma unroll
                for (int t = 0; t < acc[i][j].num_elements; t++)
                    acc[i][j].x[t] = to_tf32f(acc[i][j].x[t]);
                int h = n >> 6, dl = n & 63;
                wmma::store_matrix_sync(
                    g_eh + ((size_t)(b*HEADS + h) * SEQ + ml + wm*32 + i*16) * DH + dl,
                    acc[i][j], DH, wmma::mem_row_major);
            } else if (mode == 1) {
                int h = n >> 6, dl = n & 63;
                wmma::store_matrix_sync(
                    g_xh + ((size_t)(b*HEADS + h) * DH + dl) * SEQ + ml + wm*32 + i*16,
                    acc[i][j], SEQ, wmma::mem_col_major);
            } else {
                wmma::store_matrix_sync(
                    g_tmp + (size_t)(m0 + wm*32 + i*16) * DMODEL + n,
                    acc[i][j], DMODEL, wmma::mem_row_major);
            }
        }
    }
}

// ---------------------------------------------------------------------------
// Fused attention: per CTA = 128 q-rows of one bh, k-chunks of 32.
// Double-buffered (cp.async 2-stage) AND 2 CTAs/SM: smem = 89.6 KB.
//   Aq [128][68], Bk [2][32][68], Bx [2][64][36], Cb [128][36], sinvs[128]
// Scores: warp tile 32q x 16k' (sacc[2]) ; AV: warp tile 32q x 32d (vacc[2][2])
// Final vacc dump reuses Aq (free after last scores MMA).
// ---------------------------------------------------------------------------
namespace {
constexpr int QP = 68;                // Aq/Bk row pad (64 data cols)
constexpr int CP = 36;                // Bx/Cb row pad (32 data cols)
constexpr int CH = 32;                // k-chunk
constexpr int NCH = SEQ / CH;         // 64 chunks
}

__global__ __launch_bounds__(256, 2) void attn_kernel(float* __restrict__ attn)
{
    extern __shared__ float sm[];
    float* Aq    = sm;                   // [128][QP]
    float* Bk    = Aq + 128 * QP;        // [2][32][QP]
    float* Bx    = Bk + 2 * 32 * QP;     // [2][64][CP]
    float* Cb    = Bx + 2 * 64 * CP;     // [128][CP]
    float* sinvs = Cb + 128 * CP;        // [128]
    const int tid = threadIdx.x, wid = tid >> 5;
    const int wm = wid & 3, wn = wid >> 2;
    const int bh = blockIdx.y, q0 = blockIdx.x * 128;
    const float* ehb = g_eh + (size_t)bh * SEQ * DH;
    const float* xhb = g_xh + (size_t)bh * DH * SEQ;
    const uint32_t Bk_u = smem_u32(Bk), Bx_u = smem_u32(Bx);

    auto stage = [&](int k0, int buf) {
        const uint32_t ko = Bk_u + (uint32_t)buf * 32 * QP * 4;
        const uint32_t xo = Bx_u + (uint32_t)buf * 64 * CP * 4;
        #pragma unroll
        for (int i = tid; i < 32 * 16; i += 256) {       // K tile: 32 rows x 64
            int r = i >> 4, c4 = (i & 15) << 2;
            cp16(ko + (uint32_t)(r * QP + c4) * 4, ehb + (size_t)(k0 + r) * DH + c4);
        }
        #pragma unroll
        for (int i = tid; i < 64 * 8; i += 256) {        // X tile: 64 rows x 32
            int r = i >> 3, c4 = (i & 7) << 2;
            cp16(xo + (uint32_t)(r * CP + c4) * 4, xhb + (size_t)r * SEQ + k0 + c4);
        }
    };

    stage(0, 0); CP_COMMIT();

    // stage Q (x 1/8: exponent shift on tf32-exact values -> still exact)
    #pragma unroll
    for (int i = tid; i < 128 * 16; i += 256) {
        int r = i >> 4, c4 = (i & 15) << 2;
        float4 v = *(const float4*)(ehb + (size_t)(q0 + r) * DH + c4);
        *(float4*)(Aq + r * QP + c4) =
            make_float4(v.x * 0.125f, v.y * 0.125f, v.z * 0.125f, v.w * 0.125f);
    }

    FragC vacc[2][2];
    #pragma unroll
    for (int i = 0; i < 2; i++)
        #pragma unroll
        for (int j = 0; j < 2; j++)
            wmma::fill_fragment(vacc[i][j], 0.0f);

    float rsum = 0.0f;
    // per-thread output row / 16-col half for the E write
    float* arow = attn + ((size_t)bh * SEQ + q0 + (tid >> 1)) * SEQ + (tid & 1) * 16;

    for (int kc = 0; kc < NCH; kc++) {
        if (kc + 1 < NCH) { stage((kc + 1) * CH, (kc + 1) & 1); CP_COMMIT(); CP_WAIT(1); }
        else CP_WAIT(0);
        __syncthreads();                          // S1: chunk kc staged & visible
        const float* Kb = Bk + (kc & 1) * 32 * QP;
        const float* Xb = Bx + (kc & 1) * 64 * CP;

        // ---- scores MMA: [128q x 32k'], inner 64 ----
        FragC sacc[2];
        #pragma unroll
        for (int i = 0; i < 2; i++) wmma::fill_fragment(sacc[i], 0.0f);
        #pragma unroll
        for (int ks = 0; ks < 8; ks++) {
            FragA a[2]; FragB bk;
            #pragma unroll
            for (int i = 0; i < 2; i++)
                wmma::load_matrix_sync(a[i], Aq + (wm*32 + i*16) * QP + ks*8, QP);
            wmma::load_matrix_sync(bk, Kb + (wn*16) * QP + ks*8, QP);
            #pragma unroll
            for (int i = 0; i < 2; i++)
                wmma::mma_sync(sacc[i], a[i], bk, sacc[i]);
        }
        // ---- exp, park in Cb ----
        #pragma unroll
        for (int i = 0; i < 2; i++) {
            #pragma unroll
            for (int t = 0; t < sacc[i].num_elements; t++)
                sacc[i].x[t] = __expf(sacc[i].x[t]);
            wmma::store_matrix_sync(Cb + (wm*32 + i*16) * CP + wn*16,
                                    sacc[i], CP, wmma::mem_row_major);
        }
        __syncthreads();                          // S2: Cb visible

        // ---- AV MMA: vacc += Cb[128x32] @ XbT, inner 32 ----
        #pragma unroll
        for (int ks = 0; ks < 4; ks++) {
            FragA a[2]; FragB b[2];
            #pragma unroll
            for (int i = 0; i < 2; i++)
                wmma::load_matrix_sync(a[i], Cb + (wm*32 + i*16) * CP + ks*8, CP);
            #pragma unroll
            for (int j = 0; j < 2; j++)
                wmma::load_matrix_sync(b[j], Xb + (wn*32 + j*16) * CP + ks*8, CP);
            #pragma unroll
            for (int i = 0; i < 2; i++)
                #pragma unroll
                for (int j = 0; j < 2; j++)
                    wmma::mma_sync(vacc[i][j], a[i], b[j], vacc[i][j]);
        }

        // ---- rowsum + write unnormalized E (2 threads/row, 16 cols each) ----
        {
            const float* src = Cb + (tid >> 1) * CP + (tid & 1) * 16;
            float4* dst = (float4*)(arow + kc * CH);
            #pragma unroll
            for (int q = 0; q < 4; q++) {
                float4 v = ((const float4*)src)[q];
                rsum += v.x + v.y + v.z + v.w;
                __stcs(dst + q, v);
            }
        }
        __syncthreads();                          // S3: Cb/Xb/Kb free
    }

    // ---- rowsum combine, publish inv ----
    float tot = rsum + __shfl_xor_sync(0xffffffffu, rsum, 1);
    float inv = 1.0f / tot;
    if (!(tid & 1)) {
        g_invs[(size_t)bh * SEQ + q0 + (tid >> 1)] = inv;
        sinvs[tid >> 1] = inv;
    }
    __syncthreads();

    // ---- dump vacc into Aq (free now; 128x64 fits QP=68 rows) ----
    #pragma unroll
    for (int i = 0; i < 2; i++)
        #pragma unroll
        for (int j = 0; j < 2; j++)
            wmma::store_matrix_sync(Aq + (wm*32 + i*16) * QP + wn*32 + j*16,
                                    vacc[i][j], QP, wmma::mem_row_major);
    __syncthreads();
    const int b = bh >> 4, h = bh & 15;
    #pragma unroll
    for (int i = tid; i < 128 * 16; i += 256) {
        int r = i >> 4, c4 = (i & 15) << 2;
        float is = sinvs[r];
        float4 v = *(const float4*)(Aq + r * QP + c4);
        v.x *= is; v.y *= is; v.z *= is; v.w *= is;
        *(float4*)&g_feat[((size_t)(b * SEQ) + q0 + r) * DMODEL + h * DH + c4] = v;
    }
}

// ---------------------------------------------------------------------------
// Normalize attn rows in place: attn[row,:] *= g_invs[row]. Pure streaming.
// ---------------------------------------------------------------------------
__global__ __launch_bounds__(256) void norm_attn_kernel(float* __restrict__ attn)
{
    const size_t row = blockIdx.x;
    const float inv = g_invs[row];
    float4* p = (float4*)(attn + row * SEQ);
    const int tid = threadIdx.x;
    #pragma unroll
    for (int i = 0; i < 2; i++) {
        float4 v = __ldcs(p + tid + i * 256);
        v.x *= inv; v.y *= inv; v.z *= inv; v.w *= inv;
        __stcs(p + tid + i * 256, v);
    }
}

// ---------------------------------------------------------------------------
// LayerNorm over last dim (1024), eps=1e-6. One block (256 thr) per row.
// ---------------------------------------------------------------------------
__device__ __forceinline__ float warp_sum(float v) {
    #pragma unroll
    for (int o = 16; o; o >>= 1) v += __shfl_xor_sync(0xffffffffu, v, o);
    return v;
}
__global__ __launch_bounds__(256) void ln_kernel(const float* __restrict__ gamma,
                                                 const float* __restrict__ beta,
                                                 float* __restrict__ out)
{
    const int tid = threadIdx.x;
    const size_t row = blockIdx.x;
    const float* p = g_tmp + row * DMODEL;
    float4 v = ((const float4*)p)[tid];
    float s  = v.x + v.y + v.z + v.w;
    float ss = v.x*v.x + v.y*v.y + v.z*v.z + v.w*v.w;
    s = warp_sum(s); ss = warp_sum(ss);
    __shared__ float rs[8], rss[8];
    if ((tid & 31) == 0) { rs[tid >> 5] = s; rss[tid >> 5] = ss; }
    __syncthreads();
    float S = 0.f, SS = 0.f;
    #pragma unroll
    for (int i = 0; i < 8; i++) { S += rs[i]; SS += rss[i]; }
    const float mean = S * (1.0f / DMODEL);
    const float var  = SS * (1.0f / DMODEL) - mean * mean;
    const float inv  = rsqrtf(var + 1e-6f);
    float4 g  = ((const float4*)gamma)[tid];
    float4 bb = ((const float4*)beta)[tid];
    float4 o;
    o.x = (v.x - mean) * inv * g.x + bb.x;
    o.y = (v.y - mean) * inv * g.y + bb.y;
    o.z = (v.z - mean) * inv * g.z + bb.z;
    o.w = (v.w - mean) * inv * g.w + bb.w;
    ((float4*)(out + row * DMODEL))[tid] = o;
}

// ---------------------------------------------------------------------------
// Launch
// ---------------------------------------------------------------------------
namespace {
constexpr int SMEM_GEMM = 2 * 2 * 128 * GP * 4;   // 73728
constexpr int SMEM_ATTN = (128*QP + 2*32*QP + 2*64*CP + 128*CP + 128) * 4;  // 89600
}

extern "C" void kernel_launch(void* const* d_in, const int* in_sizes, int n_in,
                              void* d_out, int out_size)
{
    const float* e     = (const float*)d_in[0];
    const float* x     = (const float*)d_in[1];
    const float* We    = (const float*)d_in[2];
    const float* Wx    = (const float*)d_in[3];
    const float* Wfc   = (const float*)d_in[4];
    const float* gamma = (const float*)d_in[5];
    const float* beta  = (const float*)d_in[6];

    float* out      = (float*)d_out;
    float* out_feat = out;
    float* out_attn = out + FEAT_ELEMS;

    cudaFuncSetAttribute(gemm_kernel, cudaFuncAttributeMaxDynamicSharedMemorySize, SMEM_GEMM);
    cudaFuncSetAttribute(attn_kernel, cudaFuncAttributeMaxDynamicSharedMemorySize, SMEM_ATTN);

    // both projections in one launch (z = mode)
    gemm_kernel<<<dim3(DMODEL / 128, MROWS / 128, 2), 256, SMEM_GEMM>>>(
        e, x, We, Wx, Wfc, 0);

    dim3 ga(SEQ / 128, BHTOT);              // (16, 64)
    attn_kernel<<<ga, 256, SMEM_ATTN>>>(out_attn);

    norm_attn_kernel<<<BHTOT * SEQ, 256>>>(out_attn);

    // fc + residual
    gemm_kernel<<<dim3(DMODEL / 128, MROWS / 128, 1), 256, SMEM_GEMM>>>(
        e, x, We, Wx, Wfc, 2);

    ln_kernel<<<MROWS, 256>>>(gamma, beta, out_feat);
}

// round 9
// speedup vs baseline: 2.0634x; 1.0928x over previous
#include <cuda_runtime.h>
#include <mma.h>
#include <cstdint>

using namespace nvcuda;

// ---------------------------------------------------------------------------
// Problem constants
// ---------------------------------------------------------------------------
namespace {
constexpr int BATCH  = 4;
constexpr int HEADS  = 16;
constexpr int SEQ    = 2048;
constexpr int DH     = 64;
constexpr int DMODEL = 1024;
constexpr int MROWS  = BATCH * SEQ;           // 8192
constexpr int BHTOT  = BATCH * HEADS;         // 64
constexpr size_t HEAD_ELEMS = (size_t)BHTOT * SEQ * DH;
constexpr size_t FEAT_ELEMS = (size_t)MROWS * DMODEL;
}

// Scratch (device globals; allocation-free)
__device__ __align__(16) float g_eh[HEAD_ELEMS];    // [bh][l][64]  (tf32-exact values)
__device__ __align__(16) float g_xh[HEAD_ELEMS];    // [bh][64][l]  (transposed)
__device__ __align__(16) float g_feat[FEAT_ELEMS];  // [b][l][1024]
__device__ __align__(16) float g_tmp[FEAT_ELEMS];   // pre-LN
__device__ __align__(16) float g_invs[(size_t)BHTOT * SEQ];

using FragA = wmma::fragment<wmma::matrix_a, 16, 16, 8, wmma::precision::tf32, wmma::row_major>;
using FragB = wmma::fragment<wmma::matrix_b, 16, 16, 8, wmma::precision::tf32, wmma::col_major>;
using FragC = wmma::fragment<wmma::accumulator, 16, 16, 8, float>;

// ---------------------------------------------------------------------------
// helpers
// ---------------------------------------------------------------------------
__device__ __forceinline__ uint32_t smem_u32(const void* p) {
    uint32_t a;
    asm("{ .reg .u64 t; cvta.to.shared.u64 t, %1; cvt.u32.u64 %0, t; }" : "=r"(a) : "l"(p));
    return a;
}
__device__ __forceinline__ void cp16(uint32_t s, const void* g) {
    asm volatile("cp.async.cg.shared.global [%0], [%1], 16;" :: "r"(s), "l"(g));
}
#define CP_COMMIT()  asm volatile("cp.async.commit_group;" ::: "memory")
#define CP_WAIT(n)   asm volatile("cp.async.wait_group %0;" :: "n"(n) : "memory")

__device__ __forceinline__ float to_tf32f(float f) {
    uint32_t r; asm("cvt.rna.tf32.f32 %0, %1;" : "=r"(r) : "f"(f));
    return __uint_as_float(r);
}
__device__ __forceinline__ void round4(float* p) {
    float4 v = *(float4*)p;
    *(float4*)p = make_float4(to_tf32f(v.x), to_tf32f(v.y), to_tf32f(v.z), to_tf32f(v.w));
}

// no-op kernel: shifts launch index so ncu (-s 5 -c 1) captures attn_kernel
__global__ void nop_kernel() {}

// ---------------------------------------------------------------------------
// GEMM: D[m,n] = sum_k A[m,k] * W[n,k]  (M=8192, N=1024, K=1024)  (unchanged)
// ---------------------------------------------------------------------------
namespace { constexpr int GP = 36; }   // smem pad (floats)

__global__ __launch_bounds__(256, 2) void gemm_kernel(const float* __restrict__ e,
                                                      const float* __restrict__ x,
                                                      const float* __restrict__ We,
                                                      const float* __restrict__ Wx,
                                                      const float* __restrict__ Wfc,
                                                      int mode_base)
{
    extern __shared__ float sm[];
    float* As = sm;                    // [2][128][GP]
    float* Bs = sm + 2 * 128 * GP;     // [2][128][GP]
    const int tid = threadIdx.x, wid = tid >> 5;
    const int wm = wid & 3, wn = wid >> 2;
    const int n0 = blockIdx.x * 128, m0 = blockIdx.y * 128;
    const int mode = mode_base + blockIdx.z;

    const float* A = (mode == 0) ? e : (mode == 1) ? x : g_feat;
    const float* W = (mode == 0) ? We : (mode == 1) ? Wx : Wfc;
    const uint32_t As_u = smem_u32(As), Bs_u = smem_u32(Bs);

    FragC acc[2][4];
    if (mode == 2) {
        #pragma unroll
        for (int i = 0; i < 2; i++)
            #pragma unroll
            for (int j = 0; j < 4; j++)
                wmma::load_matrix_sync(acc[i][j],
                    x + (size_t)(m0 + wm*32 + i*16) * DMODEL + n0 + wn*64 + j*16,
                    DMODEL, wmma::mem_row_major);
    } else {
        #pragma unroll
        for (int i = 0; i < 2; i++)
            #pragma unroll
            for (int j = 0; j < 4; j++)
                wmma::fill_fragment(acc[i][j], 0.0f);
    }

    auto stage = [&](int k0, int buf) {
        const uint32_t ao = As_u + (uint32_t)buf * 128 * GP * 4;
        const uint32_t bo = Bs_u + (uint32_t)buf * 128 * GP * 4;
        #pragma unroll
        for (int i = tid; i < 128 * 8; i += 256) {
            int r = i >> 3, c4 = (i & 7) << 2;
            cp16(ao + (uint32_t)(r * GP + c4) * 4, A + (size_t)(m0 + r) * DMODEL + k0 + c4);
            cp16(bo + (uint32_t)(r * GP + c4) * 4, W + (size_t)(n0 + r) * DMODEL + k0 + c4);
        }
    };

    stage(0, 0); CP_COMMIT();
    for (int kc = 0; kc < 32; kc++) {
        if (kc + 1 < 32) { stage((kc + 1) * 32, (kc + 1) & 1); CP_COMMIT(); CP_WAIT(1); }
        else CP_WAIT(0);
        __syncthreads();
        float* Ab = As + (kc & 1) * 128 * GP;
        float* Bb = Bs + (kc & 1) * 128 * GP;
        if (mode == 0) {
            #pragma unroll
            for (int i = tid; i < 128 * 8; i += 256) {
                int r = i >> 3, c4 = (i & 7) << 2;
                round4(Ab + r * GP + c4);
                round4(Bb + r * GP + c4);
            }
            __syncthreads();
        }
        #pragma unroll
        for (int ks = 0; ks < 4; ks++) {
            FragA a[2]; FragB b[4];
            #pragma unroll
            for (int i = 0; i < 2; i++)
                wmma::load_matrix_sync(a[i], Ab + (wm*32 + i*16) * GP + ks*8, GP);
            #pragma unroll
            for (int j = 0; j < 4; j++)
                wmma::load_matrix_sync(b[j], Bb + (wn*64 + j*16) * GP + ks*8, GP);
            #pragma unroll
            for (int i = 0; i < 2; i++)
                #pragma unroll
                for (int j = 0; j < 4; j++)
                    wmma::mma_sync(acc[i][j], a[i], b[j], acc[i][j]);
        }
        __syncthreads();
    }

    const int b  = m0 >> 11;
    const int ml = m0 & 2047;
    #pragma unroll
    for (int i = 0; i < 2; i++) {
        #pragma unroll
        for (int j = 0; j < 4; j++) {
            int n = n0 + wn*64 + j*16;
            if (mode == 0) {
                #pragma unroll
                for (int t = 0; t < acc[i][j].num_elements; t++)
                    acc[i][j].x[t] = to_tf32f(acc[i][j].x[t]);
                int h = n >> 6, dl = n & 63;
                wmma::store_matrix_sync(
                    g_eh + ((size_t)(b*HEADS + h) * SEQ + ml + wm*32 + i*16) * DH + dl,
                    acc[i][j], DH, wmma::mem_row_major);
            } else if (mode == 1) {
                int h = n >> 6, dl = n & 63;
                wmma::store_matrix_sync(
                    g_xh + ((size_t)(b*HEADS + h) * DH + dl) * SEQ + ml + wm*32 + i*16,
                    acc[i][j], SEQ, wmma::mem_col_major);
            } else {
                wmma::store_matrix_sync(
                    g_tmp + (size_t)(m0 + wm*32 + i*16) * DMODEL + n,
                    acc[i][j], DMODEL, wmma::mem_row_major);
            }
        }
    }
}

// ---------------------------------------------------------------------------
// Fused attention: per CTA = 128 q-rows of one bh, k-chunks of 32.
// Scores: warp tile 16q x 32k', Aq A-fragments PRELOADED in registers
// (loop-invariant) -> no A-fragment LDS in main loop.
// AV: warp tile 32q x 32d. E-write: 8 lanes x 4 floats per row (4 lines/STG).
// ---------------------------------------------------------------------------
namespace {
constexpr int QP = 68;                // Aq/Bk row pad (64 data cols)
constexpr int CP = 36;                // Bx/Cb row pad (32 data cols)
constexpr int CH = 32;                // k-chunk
constexpr int NCH = SEQ / CH;         // 64 chunks
}

__global__ __launch_bounds__(256, 2) void attn_kernel(float* __restrict__ attn)
{
    extern __shared__ float sm[];
    float* Aq    = sm;                   // [128][QP]
    float* Bk    = Aq + 128 * QP;        // [2][32][QP]
    float* Bx    = Bk + 2 * 32 * QP;     // [2][64][CP]
    float* Cb    = Bx + 2 * 64 * CP;     // [128][CP]
    float* sinvs = Cb + 128 * CP;        // [128]
    const int tid = threadIdx.x, wid = tid >> 5;
    const int wm = wid & 3, wn = wid >> 2;
    const int bh = blockIdx.y, q0 = blockIdx.x * 128;
    const float* ehb = g_eh + (size_t)bh * SEQ * DH;
    const float* xhb = g_xh + (size_t)bh * DH * SEQ;
    const uint32_t Bk_u = smem_u32(Bk), Bx_u = smem_u32(Bx);

    auto stage = [&](int k0, int buf) {
        const uint32_t ko = Bk_u + (uint32_t)buf * 32 * QP * 4;
        const uint32_t xo = Bx_u + (uint32_t)buf * 64 * CP * 4;
        #pragma unroll
        for (int i = tid; i < 32 * 16; i += 256) {       // K tile: 32 rows x 64
            int r = i >> 4, c4 = (i & 15) << 2;
            cp16(ko + (uint32_t)(r * QP + c4) * 4, ehb + (size_t)(k0 + r) * DH + c4);
        }
        #pragma unroll
        for (int i = tid; i < 64 * 8; i += 256) {        // X tile: 64 rows x 32
            int r = i >> 3, c4 = (i & 7) << 2;
            cp16(xo + (uint32_t)(r * CP + c4) * 4, xhb + (size_t)r * SEQ + k0 + c4);
        }
    };

    stage(0, 0); CP_COMMIT();

    // stage Q (x 1/8: exponent shift on tf32-exact values -> still exact)
    #pragma unroll
    for (int i = tid; i < 128 * 16; i += 256) {
        int r = i >> 4, c4 = (i & 15) << 2;
        float4 v = *(const float4*)(ehb + (size_t)(q0 + r) * DH + c4);
        *(float4*)(Aq + r * QP + c4) =
            make_float4(v.x * 0.125f, v.y * 0.125f, v.z * 0.125f, v.w * 0.125f);
    }
    __syncthreads();

    // preload loop-invariant A fragments: warp wid owns q rows [wid*16, wid*16+16)
    FragA aq[8];
    #pragma unroll
    for (int ks = 0; ks < 8; ks++)
        wmma::load_matrix_sync(aq[ks], Aq + (wid * 16) * QP + ks * 8, QP);

    FragC vacc[2][2];
    #pragma unroll
    for (int i = 0; i < 2; i++)
        #pragma unroll
        for (int j = 0; j < 2; j++)
            wmma::fill_fragment(vacc[i][j], 0.0f);

    // E-write rowsums: thread covers rows {it*32 + (tid>>3)}, it=0..3
    float rsum[4] = {0.f, 0.f, 0.f, 0.f};
    const int erow = tid >> 3;            // 0..31
    const int ecol = (tid & 7) * 4;       // 0..28
    float* abase = attn + ((size_t)bh * SEQ + q0) * SEQ;

    for (int kc = 0; kc < NCH; kc++) {
        if (kc + 1 < NCH) { stage((kc + 1) * CH, (kc + 1) & 1); CP_COMMIT(); CP_WAIT(1); }
        else CP_WAIT(0);
        __syncthreads();                          // S1: chunk kc staged & visible
        const float* Kb = Bk + (kc & 1) * 32 * QP;
        const float* Xb = Bx + (kc & 1) * 64 * CP;

        // ---- scores MMA: warp tile 16q x 32k', A preloaded ----
        FragC sacc[2];
        #pragma unroll
        for (int j = 0; j < 2; j++) wmma::fill_fragment(sacc[j], 0.0f);
        #pragma unroll
        for (int ks = 0; ks < 8; ks++) {
            FragB b[2];
            #pragma unroll
            for (int j = 0; j < 2; j++)
                wmma::load_matrix_sync(b[j], Kb + (j*16) * QP + ks*8, QP);
            #pragma unroll
            for (int j = 0; j < 2; j++)
                wmma::mma_sync(sacc[j], aq[ks], b[j], sacc[j]);
        }
        // ---- exp, park in Cb ----
        #pragma unroll
        for (int j = 0; j < 2; j++) {
            #pragma unroll
            for (int t = 0; t < sacc[j].num_elements; t++)
                sacc[j].x[t] = __expf(sacc[j].x[t]);
            wmma::store_matrix_sync(Cb + (wid*16) * CP + j*16,
                                    sacc[j], CP, wmma::mem_row_major);
        }
        __syncthreads();                          // S2: Cb visible

        // ---- AV MMA: vacc += Cb[128x32] @ XbT, warp tile 32q x 32d ----
        #pragma unroll
        for (int ks = 0; ks < 4; ks++) {
            FragA a[2]; FragB b[2];
            #pragma unroll
            for (int i = 0; i < 2; i++)
                wmma::load_matrix_sync(a[i], Cb + (wm*32 + i*16) * CP + ks*8, CP);
            #pragma unroll
            for (int j = 0; j < 2; j++)
                wmma::load_matrix_sync(b[j], Xb + (wn*32 + j*16) * CP + ks*8, CP);
            #pragma unroll
            for (int i = 0; i < 2; i++)
                #pragma unroll
                for (int j = 0; j < 2; j++)
                    wmma::mma_sync(vacc[i][j], a[i], b[j], vacc[i][j]);
        }

        // ---- rowsum + write unnormalized E (8 lanes x 4 floats per row) ----
        #pragma unroll
        for (int it = 0; it < 4; it++) {
            int r = it * 32 + erow;
            float4 v = *(const float4*)(Cb + r * CP + ecol);
            rsum[it] += v.x + v.y + v.z + v.w;
            __stcs((float4*)(abase + (size_t)r * SEQ + kc * CH + ecol), v);
        }
        __syncthreads();                          // S3: Cb/Xb/Kb free
    }

    // ---- rowsum combine over 8-lane groups, publish inv ----
    #pragma unroll
    for (int it = 0; it < 4; it++) {
        float t = rsum[it];
        t += __shfl_xor_sync(0xffffffffu, t, 1);
        t += __shfl_xor_sync(0xffffffffu, t, 2);
        t += __shfl_xor_sync(0xffffffffu, t, 4);
        if ((tid & 7) == 0) {
            int r = it * 32 + erow;
            float inv = 1.0f / t;
            g_invs[(size_t)bh * SEQ + q0 + r] = inv;
            sinvs[r] = inv;
        }
    }
    __syncthreads();

    // ---- dump vacc into Aq (free now; 128x64 fits QP=68 rows) ----
    #pragma unroll
    for (int i = 0; i < 2; i++)
        #pragma unroll
        for (int j = 0; j < 2; j++)
            wmma::store_matrix_sync(Aq + (wm*32 + i*16) * QP + wn*32 + j*16,
                                    vacc[i][j], QP, wmma::mem_row_major);
    __syncthreads();
    const int b = bh >> 4, h = bh & 15;
    #pragma unroll
    for (int i = tid; i < 128 * 16; i += 256) {
        int r = i >> 4, c4 = (i & 15) << 2;
        float is = sinvs[r];
        float4 v = *(const float4*)(Aq + r * QP + c4);
        v.x *= is; v.y *= is; v.z *= is; v.w *= is;
        *(float4*)&g_feat[((size_t)(b * SEQ) + q0 + r) * DMODEL + h * DH + c4] = v;
    }
}

// ---------------------------------------------------------------------------
// Normalize attn rows in place: attn[row,:] *= g_invs[row]. Pure streaming.
// ---------------------------------------------------------------------------
__global__ __launch_bounds__(256) void norm_attn_kernel(float* __restrict__ attn)
{
    const size_t row = blockIdx.x;
    const float inv = g_invs[row];
    float4* p = (float4*)(attn + row * SEQ);
    const int tid = threadIdx.x;
    #pragma unroll
    for (int i = 0; i < 2; i++) {
        float4 v = __ldcs(p + tid + i * 256);
        v.x *= inv; v.y *= inv; v.z *= inv; v.w *= inv;
        __stcs(p + tid + i * 256, v);
    }
}

// ---------------------------------------------------------------------------
// LayerNorm over last dim (1024), eps=1e-6. One block (256 thr) per row.
// ---------------------------------------------------------------------------
__device__ __forceinline__ float warp_sum(float v) {
    #pragma unroll
    for (int o = 16; o; o >>= 1) v += __shfl_xor_sync(0xffffffffu, v, o);
    return v;
}
__global__ __launch_bounds__(256) void ln_kernel(const float* __restrict__ gamma,
                                                 const float* __restrict__ beta,
                                                 float* __restrict__ out)
{
    const int tid = threadIdx.x;
    const size_t row = blockIdx.x;
    const float* p = g_tmp + row * DMODEL;
    float4 v = ((const float4*)p)[tid];
    float s  = v.x + v.y + v.z + v.w;
    float ss = v.x*v.x + v.y*v.y + v.z*v.z + v.w*v.w;
    s = warp_sum(s); ss = warp_sum(ss);
    __shared__ float rs[8], rss[8];
    if ((tid & 31) == 0) { rs[tid >> 5] = s; rss[tid >> 5] = ss; }
    __syncthreads();
    float S = 0.f, SS = 0.f;
    #pragma unroll
    for (int i = 0; i < 8; i++) { S += rs[i]; SS += rss[i]; }
    const float mean = S * (1.0f / DMODEL);
    const float var  = SS * (1.0f / DMODEL) - mean * mean;
    const float inv  = rsqrtf(var + 1e-6f);
    float4 g  = ((const float4*)gamma)[tid];
    float4 bb = ((const float4*)beta)[tid];
    float4 o;
    o.x = (v.x - mean) * inv * g.x + bb.x;
    o.y = (v.y - mean) * inv * g.y + bb.y;
    o.z = (v.z - mean) * inv * g.z + bb.z;
    o.w = (v.w - mean) * inv * g.w + bb.w;
    ((float4*)(out + row * DMODEL))[tid] = o;
}

// ---------------------------------------------------------------------------
// Launch
// ---------------------------------------------------------------------------
namespace {
constexpr int SMEM_GEMM = 2 * 2 * 128 * GP * 4;   // 73728
constexpr int SMEM_ATTN = (128*QP + 2*32*QP + 2*64*CP + 128*CP + 128) * 4;  // 89600
}

extern "C" void kernel_launch(void* const* d_in, const int* in_sizes, int n_in,
                              void* d_out, int out_size)
{
    const float* e     = (const float*)d_in[0];
    const float* x     = (const float*)d_in[1];
    const float* We    = (const float*)d_in[2];
    const float* Wx    = (const float*)d_in[3];
    const float* Wfc   = (const float*)d_in[4];
    const float* gamma = (const float*)d_in[5];
    const float* beta  = (const float*)d_in[6];

    float* out      = (float*)d_out;
    float* out_feat = out;
    float* out_attn = out + FEAT_ELEMS;

    cudaFuncSetAttribute(gemm_kernel, cudaFuncAttributeMaxDynamicSharedMemorySize, SMEM_GEMM);
    cudaFuncSetAttribute(attn_kernel, cudaFuncAttributeMaxDynamicSharedMemorySize, SMEM_ATTN);

    // 4 no-op launches: shifts attn_kernel to launch index 5 for ncu -s 5 -c 1
    nop_kernel<<<1, 32>>>();
    nop_kernel<<<1, 32>>>();
    nop_kernel<<<1, 32>>>();
    nop_kernel<<<1, 32>>>();

    // both projections in one launch (z = mode)
    gemm_kernel<<<dim3(DMODEL / 128, MROWS / 128, 2), 256, SMEM_GEMM>>>(
        e, x, We, Wx, Wfc, 0);

    dim3 ga(SEQ / 128, BHTOT);              // (16, 64)
    attn_kernel<<<ga, 256, SMEM_ATTN>>>(out_attn);

    norm_attn_kernel<<<BHTOT * SEQ, 256>>>(out_attn);

    // fc + residual
    gemm_kernel<<<dim3(DMODEL / 128, MROWS / 128, 1), 256, SMEM_GEMM>>>(
        e, x, We, Wx, Wfc, 2);

    ln_kernel<<<MROWS, 256>>>(gamma, beta, out_feat);
}

// round 11
// speedup vs baseline: 3.0227x; 1.4649x over previous
#include <cuda_runtime.h>
#include <cuda_fp16.h>
#include <mma.h>
#include <cstdint>

using namespace nvcuda;

// ---------------------------------------------------------------------------
// Problem constants
// ---------------------------------------------------------------------------
namespace {
constexpr int BATCH  = 4;
constexpr int HEADS  = 16;
constexpr int SEQ    = 2048;
constexpr int DH     = 64;
constexpr int DMODEL = 1024;
constexpr int MROWS  = BATCH * SEQ;           // 8192
constexpr int BHTOT  = BATCH * HEADS;         // 64
constexpr size_t HEAD_ELEMS = (size_t)BHTOT * SEQ * DH;
constexpr size_t FEAT_ELEMS = (size_t)MROWS * DMODEL;
}

// Scratch (device globals; allocation-free)
__device__ __align__(16) __half g_eh16[HEAD_ELEMS];  // [bh][l][64] fp16
__device__ __align__(16) __half g_xh16[HEAD_ELEMS];  // [bh][l][64] fp16 (row-major!)
__device__ __align__(16) float  g_feat[FEAT_ELEMS];  // [b][l][1024]
__device__ __align__(16) float  g_tmp[FEAT_ELEMS];   // pre-LN
__device__ __align__(16) float  g_invs[(size_t)BHTOT * SEQ];

// tf32 fragments (GEMM)
using FragA  = wmma::fragment<wmma::matrix_a, 16, 16, 8, wmma::precision::tf32, wmma::row_major>;
using FragB  = wmma::fragment<wmma::matrix_b, 16, 16, 8, wmma::precision::tf32, wmma::col_major>;
using FragC  = wmma::fragment<wmma::accumulator, 16, 16, 8, float>;
// fp16 fragments (attention)
using FragAh  = wmma::fragment<wmma::matrix_a, 16, 16, 16, __half, wmma::row_major>;
using FragBhC = wmma::fragment<wmma::matrix_b, 16, 16, 16, __half, wmma::col_major>;
using FragBhR = wmma::fragment<wmma::matrix_b, 16, 16, 16, __half, wmma::row_major>;
using FragCh  = wmma::fragment<wmma::accumulator, 16, 16, 16, float>;

// ---------------------------------------------------------------------------
// helpers
// ---------------------------------------------------------------------------
__device__ __forceinline__ uint32_t smem_u32(const void* p) {
    uint32_t a;
    asm("{ .reg .u64 t; cvta.to.shared.u64 t, %1; cvt.u32.u64 %0, t; }" : "=r"(a) : "l"(p));
    return a;
}
__device__ __forceinline__ void cp16(uint32_t s, const void* g) {
    asm volatile("cp.async.cg.shared.global [%0], [%1], 16;" :: "r"(s), "l"(g));
}
#define CP_COMMIT()  asm volatile("cp.async.commit_group;" ::: "memory")
#define CP_WAIT(n)   asm volatile("cp.async.wait_group %0;" :: "n"(n) : "memory")

__device__ __forceinline__ float to_tf32f(float f) {
    uint32_t r; asm("cvt.rna.tf32.f32 %0, %1;" : "=r"(r) : "f"(f));
    return __uint_as_float(r);
}
__device__ __forceinline__ void round4(float* p) {
    float4 v = *(float4*)p;
    *(float4*)p = make_float4(to_tf32f(v.x), to_tf32f(v.y), to_tf32f(v.z), to_tf32f(v.w));
}

// ---------------------------------------------------------------------------
// GEMM: D[m,n] = sum_k A[m,k] * W[n,k]  (M=8192, N=1024, K=1024), tf32.
// mode 0: A=e -> g_eh16 (fp16, row-major; operands rna-rounded)
// mode 1: A=x -> g_xh16 (fp16, row-major)
// mode 2: A=g_feat, acc init = residual x -> g_tmp (f32)
// ---------------------------------------------------------------------------
namespace { constexpr int GP = 36; }   // smem pad (floats)

__global__ __launch_bounds__(256, 2) void gemm_kernel(const float* __restrict__ e,
                                                      const float* __restrict__ x,
                                                      const float* __restrict__ We,
                                                      const float* __restrict__ Wx,
                                                      const float* __restrict__ Wfc,
                                                      int mode_base)
{
    extern __shared__ float sm[];
    float* As = sm;                    // [2][128][GP]
    float* Bs = sm + 2 * 128 * GP;     // [2][128][GP]
    const int tid = threadIdx.x, wid = tid >> 5;
    const int wm = wid & 3, wn = wid >> 2;
    const int n0 = blockIdx.x * 128, m0 = blockIdx.y * 128;
    const int mode = mode_base + blockIdx.z;

    const float* A = (mode == 0) ? e : (mode == 1) ? x : g_feat;
    const float* W = (mode == 0) ? We : (mode == 1) ? Wx : Wfc;
    const uint32_t As_u = smem_u32(As), Bs_u = smem_u32(Bs);

    FragC acc[2][4];
    if (mode == 2) {
        #pragma unroll
        for (int i = 0; i < 2; i++)
            #pragma unroll
            for (int j = 0; j < 4; j++)
                wmma::load_matrix_sync(acc[i][j],
                    x + (size_t)(m0 + wm*32 + i*16) * DMODEL + n0 + wn*64 + j*16,
                    DMODEL, wmma::mem_row_major);
    } else {
        #pragma unroll
        for (int i = 0; i < 2; i++)
            #pragma unroll
            for (int j = 0; j < 4; j++)
                wmma::fill_fragment(acc[i][j], 0.0f);
    }

    auto stage = [&](int k0, int buf) {
        const uint32_t ao = As_u + (uint32_t)buf * 128 * GP * 4;
        const uint32_t bo = Bs_u + (uint32_t)buf * 128 * GP * 4;
        #pragma unroll
        for (int i = tid; i < 128 * 8; i += 256) {
            int r = i >> 3, c4 = (i & 7) << 2;
            cp16(ao + (uint32_t)(r * GP + c4) * 4, A + (size_t)(m0 + r) * DMODEL + k0 + c4);
            cp16(bo + (uint32_t)(r * GP + c4) * 4, W + (size_t)(n0 + r) * DMODEL + k0 + c4);
        }
    };

    stage(0, 0); CP_COMMIT();
    for (int kc = 0; kc < 32; kc++) {
        if (kc + 1 < 32) { stage((kc + 1) * 32, (kc + 1) & 1); CP_COMMIT(); CP_WAIT(1); }
        else CP_WAIT(0);
        __syncthreads();
        float* Ab = As + (kc & 1) * 128 * GP;
        float* Bb = Bs + (kc & 1) * 128 * GP;
        if (mode == 0) {
            #pragma unroll
            for (int i = tid; i < 128 * 8; i += 256) {
                int r = i >> 3, c4 = (i & 7) << 2;
                round4(Ab + r * GP + c4);
                round4(Bb + r * GP + c4);
            }
            __syncthreads();
        }
        #pragma unroll
        for (int ks = 0; ks < 4; ks++) {
            FragA a[2]; FragB b[4];
            #pragma unroll
            for (int i = 0; i < 2; i++)
                wmma::load_matrix_sync(a[i], Ab + (wm*32 + i*16) * GP + ks*8, GP);
            #pragma unroll
            for (int j = 0; j < 4; j++)
                wmma::load_matrix_sync(b[j], Bb + (wn*64 + j*16) * GP + ks*8, GP);
            #pragma unroll
            for (int i = 0; i < 2; i++)
                #pragma unroll
                for (int j = 0; j < 4; j++)
                    wmma::mma_sync(acc[i][j], a[i], b[j], acc[i][j]);
        }
        __syncthreads();
    }

    const int b  = m0 >> 11;
    const int ml = m0 & 2047;

    if (mode == 2) {
        #pragma unroll
        for (int i = 0; i < 2; i++)
            #pragma unroll
            for (int j = 0; j < 4; j++)
                wmma::store_matrix_sync(
                    g_tmp + (size_t)(m0 + wm*32 + i*16) * DMODEL + n0 + wn*64 + j*16,
                    acc[i][j], DMODEL, wmma::mem_row_major);
    } else {
        // roundtrip through smem, convert to fp16, store row-major [bh][l][64]
        float* Ts = sm;   // [128][132]  (67584 B <= 73728)
        __syncthreads();  // all warps done reading As/Bs
        #pragma unroll
        for (int i = 0; i < 2; i++)
            #pragma unroll
            for (int j = 0; j < 4; j++)
                wmma::store_matrix_sync(Ts + (wm*32 + i*16) * 132 + wn*64 + j*16,
                                        acc[i][j], 132, wmma::mem_row_major);
        __syncthreads();
        __half* dst_base = (mode == 0) ? g_eh16 : g_xh16;
        #pragma unroll
        for (int i = tid; i < 128 * 16; i += 256) {
            int r = i >> 4, c8 = (i & 15) * 8;
            float4 v0 = *(float4*)&Ts[r * 132 + c8];
            float4 v1 = *(float4*)&Ts[r * 132 + c8 + 4];
            __half2 hv[4];
            hv[0] = __floats2half2_rn(v0.x, v0.y);
            hv[1] = __floats2half2_rn(v0.z, v0.w);
            hv[2] = __floats2half2_rn(v1.x, v1.y);
            hv[3] = __floats2half2_rn(v1.z, v1.w);
            int n = n0 + c8, hh = n >> 6, d0 = n & 63;
            *(uint4*)&dst_base[((size_t)(b*HEADS + hh) * SEQ + ml + r) * DH + d0] =
                *(uint4*)hv;
        }
    }
}

// ---------------------------------------------------------------------------
// Fused attention (fp16 datapath): per CTA = 128 q-rows of one bh, CH=32.
// Triple-buffered K/X (cp.async). Per chunk:
//   S1; scores(fp16, f32 acc); exp -> Cb(f32); S2;
//   E-write(f32 to gmem)+rowsum + fp16 copy -> Ch; S3; AV(fp16: Ch @ Xb).
// Attn output E stays full f32 (only the AV operand is fp16-rounded).
// ---------------------------------------------------------------------------
namespace {
constexpr int QPH = 72;   // Aq/Bk/Bx row pad (halves), 64 data cols
constexpr int CPH = 40;   // Ch pad (halves), 32 data cols
constexpr int CPF = 36;   // Cb pad (floats), 32 data cols
constexpr int CH  = 32;
constexpr int NCH = SEQ / CH;   // 64
}

__global__ __launch_bounds__(256, 2) void attn_kernel(float* __restrict__ attn)
{
    extern __shared__ char smc[];
    __half* Aq = (__half*)smc;                  // [128][72]    18432 B
    __half* Bk = Aq + 128 * QPH;                // [3][32][72]  13824 B
    __half* Bx = Bk + 3 * 32 * QPH;             // [3][32][72]  13824 B
    float*  Cb = (float*)(Bx + 3 * 32 * QPH);   // [128][36]    18432 B
    __half* Ch = (__half*)(Cb + 128 * CPF);     // [128][40]    10240 B
    float* sinvs = (float*)(Ch + 128 * CPH);    // [128]          512 B
    const int tid = threadIdx.x, wid = tid >> 5;
    const int wm = wid & 3, wn = wid >> 2;
    const int bh = blockIdx.y, q0 = blockIdx.x * 128;
    const __half* ehb = g_eh16 + (size_t)bh * SEQ * DH;
    const __half* xhb = g_xh16 + (size_t)bh * SEQ * DH;
    const uint32_t Bk_u = smem_u32(Bk), Bx_u = smem_u32(Bx);

    // K tile: 32 rows x 64 halves (128 B/row); X tile same shape. 256 cp16 each.
    auto stage = [&](int k0, int buf) {
        const uint32_t ko = Bk_u + (uint32_t)buf * 32 * QPH * 2;
        const uint32_t xo = Bx_u + (uint32_t)buf * 32 * QPH * 2;
        int r = tid >> 3, c8 = (tid & 7) * 8;
        cp16(ko + (uint32_t)(r * QPH + c8) * 2, ehb + (size_t)(k0 + r) * DH + c8);
        cp16(xo + (uint32_t)(r * QPH + c8) * 2, xhb + (size_t)(k0 + r) * DH + c8);
    };

    stage(0, 0); CP_COMMIT();

    // stage Q (x 1/8, exact pow2 in fp16)
    {
        const __half2 sc = __half2half2(__float2half(0.125f));
        #pragma unroll
        for (int i = tid; i < 128 * 8; i += 256) {
            int r = i >> 3, c8 = (i & 7) * 8;
            uint4 raw = *(const uint4*)&ehb[(size_t)(q0 + r) * DH + c8];
            __half2* hp = (__half2*)&raw;
            hp[0] = __hmul2(hp[0], sc); hp[1] = __hmul2(hp[1], sc);
            hp[2] = __hmul2(hp[2], sc); hp[3] = __hmul2(hp[3], sc);
            *(uint4*)&Aq[r * QPH + c8] = raw;
        }
    }
    __syncthreads();

    // preload loop-invariant Q fragments (warp wid owns q rows [wid*16, +16))
    FragAh aq[4];
    #pragma unroll
    for (int ks = 0; ks < 4; ks++)
        wmma::load_matrix_sync(aq[ks], Aq + (wid * 16) * QPH + ks * 16, QPH);

    FragCh vacc[2][2];
    #pragma unroll
    for (int i = 0; i < 2; i++)
        #pragma unroll
        for (int j = 0; j < 2; j++)
            wmma::fill_fragment(vacc[i][j], 0.0f);

    float rsum[4] = {0.f, 0.f, 0.f, 0.f};
    const int erow = tid >> 3;            // 0..31
    const int ecol = (tid & 7) * 4;       // 0..28
    float* abase = attn + ((size_t)bh * SEQ + q0) * SEQ;

    int cur = 0, nxt = 1;
    for (int kc = 0; kc < NCH; kc++) {
        if (kc + 1 < NCH) { stage((kc + 1) * CH, nxt); CP_COMMIT(); CP_WAIT(1); }
        else CP_WAIT(0);
        __syncthreads();                          // S1: chunk kc staged & visible
        const __half* Kb = Bk + cur * 32 * QPH;
        const __half* Xb = Bx + cur * 32 * QPH;

        // ---- scores MMA: warp 16q x 32k', fp16, f32 acc; A preloaded ----
        FragCh sacc[2];
        #pragma unroll
        for (int j = 0; j < 2; j++) wmma::fill_fragment(sacc[j], 0.0f);
        #pragma unroll
        for (int ks = 0; ks < 4; ks++) {
            FragBhC bk[2];
            #pragma unroll
            for (int j = 0; j < 2; j++)
                wmma::load_matrix_sync(bk[j], Kb + (j * 16) * QPH + ks * 16, QPH);
            #pragma unroll
            for (int j = 0; j < 2; j++)
                wmma::mma_sync(sacc[j], aq[ks], bk[j], sacc[j]);
        }
        // ---- exp, park in Cb (f32) ----
        #pragma unroll
        for (int j = 0; j < 2; j++) {
            #pragma unroll
            for (int t = 0; t < sacc[j].num_elements; t++)
                sacc[j].x[t] = __expf(sacc[j].x[t]);
            wmma::store_matrix_sync(Cb + (wid * 16) * CPF + j * 16,
                                    sacc[j], CPF, wmma::mem_row_major);
        }
        __syncthreads();                          // S2: Cb visible

        // ---- E-write (f32) + rowsum + fp16 copy into Ch ----
        #pragma unroll
        for (int it = 0; it < 4; it++) {
            int r = it * 32 + erow;
            float4 v = *(const float4*)(Cb + r * CPF + ecol);
            rsum[it] += v.x + v.y + v.z + v.w;
            __stcs((float4*)(abase + (size_t)r * SEQ + kc * CH + ecol), v);
            uint2 pk;
            __half2 p0 = __floats2half2_rn(v.x, v.y);
            __half2 p1 = __floats2half2_rn(v.z, v.w);
            *(__half2*)&pk.x = p0;
            *(__half2*)&pk.y = p1;
            *(uint2*)&Ch[r * CPH + ecol] = pk;
        }
        __syncthreads();                          // S3: Ch ready

        // ---- AV MMA: vacc += Ch[128x32] @ Xb (row-major B), fp16 ----
        #pragma unroll
        for (int ks = 0; ks < 2; ks++) {
            FragAh a[2]; FragBhR bx[2];
            #pragma unroll
            for (int i = 0; i < 2; i++)
                wmma::load_matrix_sync(a[i], Ch + (wm*32 + i*16) * CPH + ks*16, CPH);
            #pragma unroll
            for (int j = 0; j < 2; j++)
                wmma::load_matrix_sync(bx[j], Xb + (ks*16) * QPH + wn*32 + j*16, QPH);
            #pragma unroll
            for (int i = 0; i < 2; i++)
                #pragma unroll
                for (int j = 0; j < 2; j++)
                    wmma::mma_sync(vacc[i][j], a[i], bx[j], vacc[i][j]);
        }
        cur = nxt; nxt = (nxt + 1 == 3) ? 0 : nxt + 1;
    }
    __syncthreads();

    // ---- rowsum combine over 8-lane groups, publish inv ----
    #pragma unroll
    for (int it = 0; it < 4; it++) {
        float t = rsum[it];
        t += __shfl_xor_sync(0xffffffffu, t, 1);
        t += __shfl_xor_sync(0xffffffffu, t, 2);
        t += __shfl_xor_sync(0xffffffffu, t, 4);
        if ((tid & 7) == 0) {
            int r = it * 32 + erow;
            float inv = 1.0f / t;
            g_invs[(size_t)bh * SEQ + q0 + r] = inv;
            sinvs[r] = inv;
        }
    }
    __syncthreads();

    // ---- dump vacc into Aq/Bk/Bx region as f32 [128][68], scale, write feat ----
    float* Df = (float*)smc;   // 34816 B <= 46080 (Aq+Bk+Bx)
    #pragma unroll
    for (int i = 0; i < 2; i++)
        #pragma unroll
        for (int j = 0; j < 2; j++)
            wmma::store_matrix_sync(Df + (wm*32 + i*16) * 68 + wn*32 + j*16,
                                    vacc[i][j], 68, wmma::mem_row_major);
    __syncthreads();
    const int b = bh >> 4, h = bh & 15;
    #pragma unroll
    for (int i = tid; i < 128 * 16; i += 256) {
        int r = i >> 4, c4 = (i & 15) << 2;
        float is = sinvs[r];
        float4 v = *(const float4*)(Df + r * 68 + c4);
        v.x *= is; v.y *= is; v.z *= is; v.w *= is;
        *(float4*)&g_feat[((size_t)(b * SEQ) + q0 + r) * DMODEL + h * DH + c4] = v;
    }
}

// ---------------------------------------------------------------------------
// Normalize attn rows in place: attn[row,:] *= g_invs[row]. Pure streaming.
// ---------------------------------------------------------------------------
__global__ __launch_bounds__(256) void norm_attn_kernel(float* __restrict__ attn)
{
    const size_t row = blockIdx.x;
    const float inv = g_invs[row];
    float4* p = (float4*)(attn + row * SEQ);
    const int tid = threadIdx.x;
    #pragma unroll
    for (int i = 0; i < 2; i++) {
        float4 v = __ldcs(p + tid + i * 256);
        v.x *= inv; v.y *= inv; v.z *= inv; v.w *= inv;
        __stcs(p + tid + i * 256, v);
    }
}

// ---------------------------------------------------------------------------
// LayerNorm over last dim (1024), eps=1e-6. One block (256 thr) per row.
// ---------------------------------------------------------------------------
__device__ __forceinline__ float warp_sum(float v) {
    #pragma unroll
    for (int o = 16; o; o >>= 1) v += __shfl_xor_sync(0xffffffffu, v, o);
    return v;
}
__global__ __launch_bounds__(256) void ln_kernel(const float* __restrict__ gamma,
                                                 const float* __restrict__ beta,
                                                 float* __restrict__ out)
{
    const int tid = threadIdx.x;
    const size_t row = blockIdx.x;
    const float* p = g_tmp + row * DMODEL;
    float4 v = ((const float4*)p)[tid];
    float s  = v.x + v.y + v.z + v.w;
    float ss = v.x*v.x + v.y*v.y + v.z*v.z + v.w*v.w;
    s = warp_sum(s); ss = warp_sum(ss);
    __shared__ float rs[8], rss[8];
    if ((tid & 31) == 0) { rs[tid >> 5] = s; rss[tid >> 5] = ss; }
    __syncthreads();
    float S = 0.f, SS = 0.f;
    #pragma unroll
    for (int i = 0; i < 8; i++) { S += rs[i]; SS += rss[i]; }
    const float mean = S * (1.0f / DMODEL);
    const float var  = SS * (1.0f / DMODEL) - mean * mean;
    const float inv  = rsqrtf(var + 1e-6f);
    float4 g  = ((const float4*)gamma)[tid];
    float4 bb = ((const float4*)beta)[tid];
    float4 o;
    o.x = (v.x - mean) * inv * g.x + bb.x;
    o.y = (v.y - mean) * inv * g.y + bb.y;
    o.z = (v.z - mean) * inv * g.z + bb.z;
    o.w = (v.w - mean) * inv * g.w + bb.w;
    ((float4*)(out + row * DMODEL))[tid] = o;
}

// ---------------------------------------------------------------------------
// Launch
// ---------------------------------------------------------------------------
namespace {
constexpr int SMEM_GEMM = 2 * 2 * 128 * GP * 4;   // 73728
constexpr int SMEM_ATTN = 128*QPH*2 + 3*32*QPH*2 + 3*32*QPH*2
                        + 128*CPF*4 + 128*CPH*2 + 128*4;   // 75264
}

extern "C" void kernel_launch(void* const* d_in, const int* in_sizes, int n_in,
                              void* d_out, int out_size)
{
    const float* e     = (const float*)d_in[0];
    const float* x     = (const float*)d_in[1];
    const float* We    = (const float*)d_in[2];
    const float* Wx    = (const float*)d_in[3];
    const float* Wfc   = (const float*)d_in[4];
    const float* gamma = (const float*)d_in[5];
    const float* beta  = (const float*)d_in[6];

    float* out      = (float*)d_out;
    float* out_feat = out;
    float* out_attn = out + FEAT_ELEMS;

    cudaFuncSetAttribute(gemm_kernel, cudaFuncAttributeMaxDynamicSharedMemorySize, SMEM_GEMM);
    cudaFuncSetAttribute(attn_kernel, cudaFuncAttributeMaxDynamicSharedMemorySize, SMEM_ATTN);

    // both projections in one launch (z = mode)
    gemm_kernel<<<dim3(DMODEL / 128, MROWS / 128, 2), 256, SMEM_GEMM>>>(
        e, x, We, Wx, Wfc, 0);

    dim3 ga(SEQ / 128, BHTOT);              // (16, 64)
    attn_kernel<<<ga, 256, SMEM_ATTN>>>(out_attn);

    norm_attn_kernel<<<BHTOT * SEQ, 256>>>(out_attn);

    // fc + residual
    gemm_kernel<<<dim3(DMODEL / 128, MROWS / 128, 1), 256, SMEM_GEMM>>>(
        e, x, We, Wx, Wfc, 2);

    ln_kernel<<<MROWS, 256>>>(gamma, beta, out_feat);
}

// round 12
// speedup vs baseline: 4.9417x; 1.6349x over previous
#include <cuda_runtime.h>
#include <cuda_fp16.h>
#include <mma.h>
#include <cstdint>

using namespace nvcuda;

// ---------------------------------------------------------------------------
// Problem constants
// ---------------------------------------------------------------------------
namespace {
constexpr int BATCH  = 4;
constexpr int HEADS  = 16;
constexpr int SEQ    = 2048;
constexpr int DH     = 64;
constexpr int DMODEL = 1024;
constexpr int MROWS  = BATCH * SEQ;           // 8192
constexpr int BHTOT  = BATCH * HEADS;         // 64
constexpr size_t HEAD_ELEMS = (size_t)BHTOT * SEQ * DH;
constexpr size_t FEAT_ELEMS = (size_t)MROWS * DMODEL;
constexpr size_t W_ELEMS    = (size_t)DMODEL * DMODEL;
}

// Scratch (device globals; allocation-free)
__device__ __align__(16) __half g_e16 [FEAT_ELEMS];  // e  converted fp16
__device__ __align__(16) __half g_x16 [FEAT_ELEMS];  // x  converted fp16
__device__ __align__(16) __half g_We16[W_ELEMS];
__device__ __align__(16) __half g_Wx16[W_ELEMS];
__device__ __align__(16) __half g_Wfc16[W_ELEMS];
__device__ __align__(16) __half g_eh16[HEAD_ELEMS];  // [bh][l][64]
__device__ __align__(16) __half g_xh16[HEAD_ELEMS];  // [bh][l][64]
__device__ __align__(16) __half g_feat16[FEAT_ELEMS];// [b][l][1024] fp16 (attn out)
__device__ __align__(16) float  g_tmp[FEAT_ELEMS];   // pre-LN (f32)
__device__ __align__(16) float  g_invs[(size_t)BHTOT * SEQ];

// fp16 fragments
using FragAh  = wmma::fragment<wmma::matrix_a, 16, 16, 16, __half, wmma::row_major>;
using FragBhC = wmma::fragment<wmma::matrix_b, 16, 16, 16, __half, wmma::col_major>;
using FragBhR = wmma::fragment<wmma::matrix_b, 16, 16, 16, __half, wmma::row_major>;
using FragCh  = wmma::fragment<wmma::accumulator, 16, 16, 16, float>;

// ---------------------------------------------------------------------------
// helpers
// ---------------------------------------------------------------------------
__device__ __forceinline__ uint32_t smem_u32(const void* p) {
    uint32_t a;
    asm("{ .reg .u64 t; cvta.to.shared.u64 t, %1; cvt.u32.u64 %0, t; }" : "=r"(a) : "l"(p));
    return a;
}
__device__ __forceinline__ void cp16(uint32_t s, const void* g) {
    asm volatile("cp.async.cg.shared.global [%0], [%1], 16;" :: "r"(s), "l"(g));
}
#define CP_COMMIT()  asm volatile("cp.async.commit_group;" ::: "memory")
#define CP_WAIT(n)   asm volatile("cp.async.wait_group %0;" :: "n"(n) : "memory")

// ---------------------------------------------------------------------------
// fp32 -> fp16 streaming convert (rna)
// ---------------------------------------------------------------------------
__global__ __launch_bounds__(256) void cvt_kernel(const float* __restrict__ src,
                                                  __half* __restrict__ dst, int n)
{
    int i = (blockIdx.x * 256 + threadIdx.x) * 8;
    if (i < n) {
        float4 v0 = *(const float4*)(src + i);
        float4 v1 = *(const float4*)(src + i + 4);
        __half2 h[4];
        h[0] = __floats2half2_rn(v0.x, v0.y);
        h[1] = __floats2half2_rn(v0.z, v0.w);
        h[2] = __floats2half2_rn(v1.x, v1.y);
        h[3] = __floats2half2_rn(v1.z, v1.w);
        *(uint4*)(dst + i) = *(uint4*)h;
    }
}

// ---------------------------------------------------------------------------
// fp16 GEMM: D[m,n] = sum_k A[m,k] * W[n,k]  (M=8192, N=1024, K=1024)
// Block 128x128, 8 warps (4m x 2n), warp tile 32x64. 2-stage cp.async, BK=64.
// mode 0: A=g_e16,   W=g_We16  -> g_eh16  (fp16 [bh][l][64])
// mode 1: A=g_x16,   W=g_Wx16  -> g_xh16  (fp16 [bh][l][64])
// mode 2: A=g_feat16,W=g_Wfc16, acc init = residual x -> g_tmp (f32)
// ---------------------------------------------------------------------------
namespace { constexpr int GQ = 72; }   // smem pad (halves), 144B rows

__global__ __launch_bounds__(256, 2) void gemm16_kernel(const float* __restrict__ x,
                                                        int mode_base)
{
    extern __shared__ char smc[];
    __half* As = (__half*)smc;          // [2][128][GQ]
    __half* Bs = As + 2 * 128 * GQ;     // [2][128][GQ]
    const int tid = threadIdx.x, wid = tid >> 5;
    const int wm = wid & 3, wn = wid >> 2;
    const int n0 = blockIdx.x * 128, m0 = blockIdx.y * 128;
    const int mode = mode_base + blockIdx.z;

    const __half* A = (mode == 0) ? g_e16 : (mode == 1) ? g_x16 : g_feat16;
    const __half* W = (mode == 0) ? g_We16 : (mode == 1) ? g_Wx16 : g_Wfc16;
    const uint32_t As_u = smem_u32(As), Bs_u = smem_u32(Bs);

    FragCh acc[2][4];
    if (mode == 2) {
        #pragma unroll
        for (int i = 0; i < 2; i++)
            #pragma unroll
            for (int j = 0; j < 4; j++)
                wmma::load_matrix_sync(acc[i][j],
                    x + (size_t)(m0 + wm*32 + i*16) * DMODEL + n0 + wn*64 + j*16,
                    DMODEL, wmma::mem_row_major);
    } else {
        #pragma unroll
        for (int i = 0; i < 2; i++)
            #pragma unroll
            for (int j = 0; j < 4; j++)
                wmma::fill_fragment(acc[i][j], 0.0f);
    }

    auto stage = [&](int k0, int buf) {
        const uint32_t ao = As_u + (uint32_t)buf * 128 * GQ * 2;
        const uint32_t bo = Bs_u + (uint32_t)buf * 128 * GQ * 2;
        #pragma unroll
        for (int i = tid; i < 128 * 8; i += 256) {
            int r = i >> 3, c8 = (i & 7) * 8;
            cp16(ao + (uint32_t)(r * GQ + c8) * 2, A + (size_t)(m0 + r) * DMODEL + k0 + c8);
            cp16(bo + (uint32_t)(r * GQ + c8) * 2, W + (size_t)(n0 + r) * DMODEL + k0 + c8);
        }
    };

    stage(0, 0); CP_COMMIT();
    for (int kc = 0; kc < 16; kc++) {
        if (kc + 1 < 16) { stage((kc + 1) * 64, (kc + 1) & 1); CP_COMMIT(); CP_WAIT(1); }
        else CP_WAIT(0);
        __syncthreads();
        const __half* Ab = As + (kc & 1) * 128 * GQ;
        const __half* Bb = Bs + (kc & 1) * 128 * GQ;
        #pragma unroll
        for (int ks = 0; ks < 4; ks++) {
            FragAh a[2]; FragBhC b[4];
            #pragma unroll
            for (int i = 0; i < 2; i++)
                wmma::load_matrix_sync(a[i], Ab + (wm*32 + i*16) * GQ + ks*16, GQ);
            #pragma unroll
            for (int j = 0; j < 4; j++)
                wmma::load_matrix_sync(b[j], Bb + (wn*64 + j*16) * GQ + ks*16, GQ);
            #pragma unroll
            for (int i = 0; i < 2; i++)
                #pragma unroll
                for (int j = 0; j < 4; j++)
                    wmma::mma_sync(acc[i][j], a[i], b[j], acc[i][j]);
        }
        __syncthreads();
    }

    const int b  = m0 >> 11;
    const int ml = m0 & 2047;

    if (mode == 2) {
        #pragma unroll
        for (int i = 0; i < 2; i++)
            #pragma unroll
            for (int j = 0; j < 4; j++)
                wmma::store_matrix_sync(
                    g_tmp + (size_t)(m0 + wm*32 + i*16) * DMODEL + n0 + wn*64 + j*16,
                    acc[i][j], DMODEL, wmma::mem_row_major);
    } else {
        // roundtrip through smem (f32), convert fp16, store row-major [bh][l][64]
        float* Ts = (float*)smc;   // [128][132] = 67584 B <= 73728
        __syncthreads();           // all warps done reading As/Bs
        #pragma unroll
        for (int i = 0; i < 2; i++)
            #pragma unroll
            for (int j = 0; j < 4; j++)
                wmma::store_matrix_sync(Ts + (wm*32 + i*16) * 132 + wn*64 + j*16,
                                        acc[i][j], 132, wmma::mem_row_major);
        __syncthreads();
        __half* dst_base = (mode == 0) ? g_eh16 : g_xh16;
        #pragma unroll
        for (int i = tid; i < 128 * 16; i += 256) {
            int r = i >> 4, c8 = (i & 15) * 8;
            float4 v0 = *(float4*)&Ts[r * 132 + c8];
            float4 v1 = *(float4*)&Ts[r * 132 + c8 + 4];
            __half2 hv[4];
            hv[0] = __floats2half2_rn(v0.x, v0.y);
            hv[1] = __floats2half2_rn(v0.z, v0.w);
            hv[2] = __floats2half2_rn(v1.x, v1.y);
            hv[3] = __floats2half2_rn(v1.z, v1.w);
            int n = n0 + c8, hh = n >> 6, d0 = n & 63;
            *(uint4*)&dst_base[((size_t)(b*HEADS + hh) * SEQ + ml + r) * DH + d0] =
                *(uint4*)hv;
        }
    }
}

// ---------------------------------------------------------------------------
// Fused attention (fp16 datapath): per CTA = 128 q-rows of one bh, CH=32.
// Triple-buffered K/X (cp.async). Per chunk:
//   S1; scores(fp16, f32 acc); exp -> Cb(f32); S2;
//   E-write(f32 to gmem)+rowsum + fp16 copy -> Ch; S3; AV(fp16: Ch @ Xb).
// Final: feat written fp16 to g_feat16 (feeds fc GEMM directly).
// ---------------------------------------------------------------------------
namespace {
constexpr int QPH = 72;   // Aq/Bk/Bx row pad (halves), 64 data cols
constexpr int CPH = 40;   // Ch pad (halves), 32 data cols
constexpr int CPF = 36;   // Cb pad (floats), 32 data cols
constexpr int CH  = 32;
constexpr int NCH = SEQ / CH;   // 64
}

__global__ __launch_bounds__(256, 2) void attn_kernel(float* __restrict__ attn)
{
    extern __shared__ char smc[];
    __half* Aq = (__half*)smc;                  // [128][72]    18432 B
    __half* Bk = Aq + 128 * QPH;                // [3][32][72]  13824 B
    __half* Bx = Bk + 3 * 32 * QPH;             // [3][32][72]  13824 B
    float*  Cb = (float*)(Bx + 3 * 32 * QPH);   // [128][36]    18432 B
    __half* Ch = (__half*)(Cb + 128 * CPF);     // [128][40]    10240 B
    float* sinvs = (float*)(Ch + 128 * CPH);    // [128]          512 B
    const int tid = threadIdx.x, wid = tid >> 5;
    const int wm = wid & 3, wn = wid >> 2;
    const int bh = blockIdx.y, q0 = blockIdx.x * 128;
    const __half* ehb = g_eh16 + (size_t)bh * SEQ * DH;
    const __half* xhb = g_xh16 + (size_t)bh * SEQ * DH;
    const uint32_t Bk_u = smem_u32(Bk), Bx_u = smem_u32(Bx);

    auto stage = [&](int k0, int buf) {
        const uint32_t ko = Bk_u + (uint32_t)buf * 32 * QPH * 2;
        const uint32_t xo = Bx_u + (uint32_t)buf * 32 * QPH * 2;
        int r = tid >> 3, c8 = (tid & 7) * 8;
        cp16(ko + (uint32_t)(r * QPH + c8) * 2, ehb + (size_t)(k0 + r) * DH + c8);
        cp16(xo + (uint32_t)(r * QPH + c8) * 2, xhb + (size_t)(k0 + r) * DH + c8);
    };

    stage(0, 0); CP_COMMIT();

    // stage Q (x 1/8, exact pow2 in fp16)
    {
        const __half2 sc = __half2half2(__float2half(0.125f));
        #pragma unroll
        for (int i = tid; i < 128 * 8; i += 256) {
            int r = i >> 3, c8 = (i & 7) * 8;
            uint4 raw = *(const uint4*)&ehb[(size_t)(q0 + r) * DH + c8];
            __half2* hp = (__half2*)&raw;
            hp[0] = __hmul2(hp[0], sc); hp[1] = __hmul2(hp[1], sc);
            hp[2] = __hmul2(hp[2], sc); hp[3] = __hmul2(hp[3], sc);
            *(uint4*)&Aq[r * QPH + c8] = raw;
        }
    }
    __syncthreads();

    // preload loop-invariant Q fragments (warp wid owns q rows [wid*16, +16))
    FragAh aq[4];
    #pragma unroll
    for (int ks = 0; ks < 4; ks++)
        wmma::load_matrix_sync(aq[ks], Aq + (wid * 16) * QPH + ks * 16, QPH);

    FragCh vacc[2][2];
    #pragma unroll
    for (int i = 0; i < 2; i++)
        #pragma unroll
        for (int j = 0; j < 2; j++)
            wmma::fill_fragment(vacc[i][j], 0.0f);

    float rsum[4] = {0.f, 0.f, 0.f, 0.f};
    const int erow = tid >> 3;            // 0..31
    const int ecol = (tid & 7) * 4;       // 0..28
    float* abase = attn + ((size_t)bh * SEQ + q0) * SEQ;

    int cur = 0, nxt = 1;
    for (int kc = 0; kc < NCH; kc++) {
        if (kc + 1 < NCH) { stage((kc + 1) * CH, nxt); CP_COMMIT(); CP_WAIT(1); }
        else CP_WAIT(0);
        __syncthreads();                          // S1: chunk kc staged & visible
        const __half* Kb = Bk + cur * 32 * QPH;
        const __half* Xb = Bx + cur * 32 * QPH;

        // ---- scores MMA: warp 16q x 32k', fp16, f32 acc; A preloaded ----
        FragCh sacc[2];
        #pragma unroll
        for (int j = 0; j < 2; j++) wmma::fill_fragment(sacc[j], 0.0f);
        #pragma unroll
        for (int ks = 0; ks < 4; ks++) {
            FragBhC bk[2];
            #pragma unroll
            for (int j = 0; j < 2; j++)
                wmma::load_matrix_sync(bk[j], Kb + (j * 16) * QPH + ks * 16, QPH);
            #pragma unroll
            for (int j = 0; j < 2; j++)
                wmma::mma_sync(sacc[j], aq[ks], bk[j], sacc[j]);
        }
        // ---- exp, park in Cb (f32) ----
        #pragma unroll
        for (int j = 0; j < 2; j++) {
            #pragma unroll
            for (int t = 0; t < sacc[j].num_elements; t++)
                sacc[j].x[t] = __expf(sacc[j].x[t]);
            wmma::store_matrix_sync(Cb + (wid * 16) * CPF + j * 16,
                                    sacc[j], CPF, wmma::mem_row_major);
        }
        __syncthreads();                          // S2: Cb visible

        // ---- E-write (f32) + rowsum + fp16 copy into Ch ----
        #pragma unroll
        for (int it = 0; it < 4; it++) {
            int r = it * 32 + erow;
            float4 v = *(const float4*)(Cb + r * CPF + ecol);
            rsum[it] += v.x + v.y + v.z + v.w;
            __stcs((float4*)(abase + (size_t)r * SEQ + kc * CH + ecol), v);
            uint2 pk;
            __half2 p0 = __floats2half2_rn(v.x, v.y);
            __half2 p1 = __floats2half2_rn(v.z, v.w);
            *(__half2*)&pk.x = p0;
            *(__half2*)&pk.y = p1;
            *(uint2*)&Ch[r * CPH + ecol] = pk;
        }
        __syncthreads();                          // S3: Ch ready

        // ---- AV MMA: vacc += Ch[128x32] @ Xb (row-major B), fp16 ----
        #pragma unroll
        for (int ks = 0; ks < 2; ks++) {
            FragAh a[2]; FragBhR bx[2];
            #pragma unroll
            for (int i = 0; i < 2; i++)
                wmma::load_matrix_sync(a[i], Ch + (wm*32 + i*16) * CPH + ks*16, CPH);
            #pragma unroll
            for (int j = 0; j < 2; j++)
                wmma::load_matrix_sync(bx[j], Xb + (ks*16) * QPH + wn*32 + j*16, QPH);
            #pragma unroll
            for (int i = 0; i < 2; i++)
                #pragma unroll
                for (int j = 0; j < 2; j++)
                    wmma::mma_sync(vacc[i][j], a[i], bx[j], vacc[i][j]);
        }
        cur = nxt; nxt = (nxt + 1 == 3) ? 0 : nxt + 1;
    }
    __syncthreads();

    // ---- rowsum combine over 8-lane groups, publish inv ----
    #pragma unroll
    for (int it = 0; it < 4; it++) {
        float t = rsum[it];
        t += __shfl_xor_sync(0xffffffffu, t, 1);
        t += __shfl_xor_sync(0xffffffffu, t, 2);
        t += __shfl_xor_sync(0xffffffffu, t, 4);
        if ((tid & 7) == 0) {
            int r = it * 32 + erow;
            float inv = 1.0f / t;
            g_invs[(size_t)bh * SEQ + q0 + r] = inv;
            sinvs[r] = inv;
        }
    }
    __syncthreads();

    // ---- dump vacc as f32 [128][68], scale, write g_feat16 (fp16) ----
    float* Df = (float*)smc;   // 34816 B <= 46080 (Aq+Bk+Bx region)
    #pragma unroll
    for (int i = 0; i < 2; i++)
        #pragma unroll
        for (int j = 0; j < 2; j++)
            wmma::store_matrix_sync(Df + (wm*32 + i*16) * 68 + wn*32 + j*16,
                                    vacc[i][j], 68, wmma::mem_row_major);
    __syncthreads();
    const int b = bh >> 4, h = bh & 15;
    #pragma unroll
    for (int i = tid; i < 128 * 16; i += 256) {
        int r = i >> 4, c4 = (i & 15) << 2;
        float is = sinvs[r];
        float4 v = *(const float4*)(Df + r * 68 + c4);
        uint2 pk;
        *(__half2*)&pk.x = __floats2half2_rn(v.x * is, v.y * is);
        *(__half2*)&pk.y = __floats2half2_rn(v.z * is, v.w * is);
        *(uint2*)&g_feat16[((size_t)(b * SEQ) + q0 + r) * DMODEL + h * DH + c4] = pk;
    }
}

// ---------------------------------------------------------------------------
// Normalize attn rows in place: attn[row,:] *= g_invs[row]. Pure streaming.
// ---------------------------------------------------------------------------
__global__ __launch_bounds__(256) void norm_attn_kernel(float* __restrict__ attn)
{
    const size_t row = blockIdx.x;
    const float inv = g_invs[row];
    float4* p = (float4*)(attn + row * SEQ);
    const int tid = threadIdx.x;
    #pragma unroll
    for (int i = 0; i < 2; i++) {
        float4 v = __ldcs(p + tid + i * 256);
        v.x *= inv; v.y *= inv; v.z *= inv; v.w *= inv;
        __stcs(p + tid + i * 256, v);
    }
}

// ---------------------------------------------------------------------------
// LayerNorm over last dim (1024), eps=1e-6. One block (256 thr) per row.
// ---------------------------------------------------------------------------
__device__ __forceinline__ float warp_sum(float v) {
    #pragma unroll
    for (int o = 16; o; o >>= 1) v += __shfl_xor_sync(0xffffffffu, v, o);
    return v;
}
__global__ __launch_bounds__(256) void ln_kernel(const float* __restrict__ gamma,
                                                 const float* __restrict__ beta,
                                                 float* __restrict__ out)
{
    const int tid = threadIdx.x;
    const size_t row = blockIdx.x;
    const float* p = g_tmp + row * DMODEL;
    float4 v = ((const float4*)p)[tid];
    float s  = v.x + v.y + v.z + v.w;
    float ss = v.x*v.x + v.y*v.y + v.z*v.z + v.w*v.w;
    s = warp_sum(s); ss = warp_sum(ss);
    __shared__ float rs[8], rss[8];
    if ((tid & 31) == 0) { rs[tid >> 5] = s; rss[tid >> 5] = ss; }
    __syncthreads();
    float S = 0.f, SS = 0.f;
    #pragma unroll
    for (int i = 0; i < 8; i++) { S += rs[i]; SS += rss[i]; }
    const float mean = S * (1.0f / DMODEL);
    const float var  = SS * (1.0f / DMODEL) - mean * mean;
    const float inv  = rsqrtf(var + 1e-6f);
    float4 g  = ((const float4*)gamma)[tid];
    float4 bb = ((const float4*)beta)[tid];
    float4 o;
    o.x = (v.x - mean) * inv * g.x + bb.x;
    o.y = (v.y - mean) * inv * g.y + bb.y;
    o.z = (v.z - mean) * inv * g.z + bb.z;
    o.w = (v.w - mean) * inv * g.w + bb.w;
    ((float4*)(out + row * DMODEL))[tid] = o;
}

// ---------------------------------------------------------------------------
// Launch
// ---------------------------------------------------------------------------
namespace {
constexpr int SMEM_GEMM = 2 * 2 * 128 * GQ * 2;   // 73728
constexpr int SMEM_ATTN = 128*QPH*2 + 3*32*QPH*2 + 3*32*QPH*2
                        + 128*CPF*4 + 128*CPH*2 + 128*4;   // 75264
}

extern "C" void kernel_launch(void* const* d_in, const int* in_sizes, int n_in,
                              void* d_out, int out_size)
{
    const float* e     = (const float*)d_in[0];
    const float* x     = (const float*)d_in[1];
    const float* We    = (const float*)d_in[2];
    const float* Wx    = (const float*)d_in[3];
    const float* Wfc   = (const float*)d_in[4];
    const float* gamma = (const float*)d_in[5];
    const float* beta  = (const float*)d_in[6];

    float* out      = (float*)d_out;
    float* out_feat = out;
    float* out_attn = out + FEAT_ELEMS;

    cudaFuncSetAttribute(gemm16_kernel, cudaFuncAttributeMaxDynamicSharedMemorySize, SMEM_GEMM);
    cudaFuncSetAttribute(attn_kernel,   cudaFuncAttributeMaxDynamicSharedMemorySize, SMEM_ATTN);

    __half *d_e16, *d_x16, *d_We16, *d_Wx16, *d_Wfc16;
    cudaGetSymbolAddress((void**)&d_e16,  g_e16);
    cudaGetSymbolAddress((void**)&d_x16,  g_x16);
    cudaGetSymbolAddress((void**)&d_We16, g_We16);
    cudaGetSymbolAddress((void**)&d_Wx16, g_Wx16);
    cudaGetSymbolAddress((void**)&d_Wfc16, g_Wfc16);

    // fp32 -> fp16 conversions
    cvt_kernel<<<FEAT_ELEMS / 8 / 256, 256>>>(e,   d_e16,  (int)FEAT_ELEMS);
    cvt_kernel<<<FEAT_ELEMS / 8 / 256, 256>>>(x,   d_x16,  (int)FEAT_ELEMS);
    cvt_kernel<<<W_ELEMS / 8 / 256, 256>>>(We,  d_We16, (int)W_ELEMS);
    cvt_kernel<<<W_ELEMS / 8 / 256, 256>>>(Wx,  d_Wx16, (int)W_ELEMS);
    cvt_kernel<<<W_ELEMS / 8 / 256, 256>>>(Wfc, d_Wfc16, (int)W_ELEMS);

    // both projections in one launch (z = mode)
    gemm16_kernel<<<dim3(DMODEL / 128, MROWS / 128, 2), 256, SMEM_GEMM>>>(x, 0);

    dim3 ga(SEQ / 128, BHTOT);              // (16, 64)
    attn_kernel<<<ga, 256, SMEM_ATTN>>>(out_attn);

    norm_attn_kernel<<<BHTOT * SEQ, 256>>>(out_attn);

    // fc + residual
    gemm16_kernel<<<dim3(DMODEL / 128, MROWS / 128, 1), 256, SMEM_GEMM>>>(x, 2);

    ln_kernel<<<MROWS, 256>>>(gamma, beta, out_feat);
}

// round 13
// speedup vs baseline: 5.6216x; 1.1376x over previous
#include <cuda_runtime.h>
#include <cuda_fp16.h>
#include <mma.h>
#include <cstdint>

using namespace nvcuda;

// ---------------------------------------------------------------------------
// Problem constants
// ---------------------------------------------------------------------------
namespace {
constexpr int BATCH  = 4;
constexpr int HEADS  = 16;
constexpr int SEQ    = 2048;
constexpr int DH     = 64;
constexpr int DMODEL = 1024;
constexpr int MROWS  = BATCH * SEQ;           // 8192
constexpr int BHTOT  = BATCH * HEADS;         // 64
constexpr size_t HEAD_ELEMS = (size_t)BHTOT * SEQ * DH;
constexpr size_t FEAT_ELEMS = (size_t)MROWS * DMODEL;
constexpr size_t W_ELEMS    = (size_t)DMODEL * DMODEL;
}

// Scratch (device globals; allocation-free)
__device__ __align__(16) __half g_e16 [FEAT_ELEMS];
__device__ __align__(16) __half g_x16 [FEAT_ELEMS];
__device__ __align__(16) __half g_We16[W_ELEMS];
__device__ __align__(16) __half g_Wx16[W_ELEMS];
__device__ __align__(16) __half g_Wfc16[W_ELEMS];
__device__ __align__(16) __half g_eh16[HEAD_ELEMS];  // [bh][l][64]
__device__ __align__(16) __half g_xh16[HEAD_ELEMS];  // [bh][l][64]
__device__ __align__(16) __half g_feat16[FEAT_ELEMS];// [b][l][1024] fp16 (attn out)
__device__ __align__(16) float  g_tmp[FEAT_ELEMS];   // pre-LN (f32)
__device__ __align__(16) float  g_invs[(size_t)BHTOT * SEQ];

// fp16 fragments
using FragAh  = wmma::fragment<wmma::matrix_a, 16, 16, 16, __half, wmma::row_major>;
using FragBhC = wmma::fragment<wmma::matrix_b, 16, 16, 16, __half, wmma::col_major>;
using FragBhR = wmma::fragment<wmma::matrix_b, 16, 16, 16, __half, wmma::row_major>;
using FragCh  = wmma::fragment<wmma::accumulator, 16, 16, 16, float>;

// ---------------------------------------------------------------------------
// helpers
// ---------------------------------------------------------------------------
__device__ __forceinline__ uint32_t smem_u32(const void* p) {
    uint32_t a;
    asm("{ .reg .u64 t; cvta.to.shared.u64 t, %1; cvt.u32.u64 %0, t; }" : "=r"(a) : "l"(p));
    return a;
}
__device__ __forceinline__ void cp16(uint32_t s, const void* g) {
    asm volatile("cp.async.cg.shared.global [%0], [%1], 16;" :: "r"(s), "l"(g));
}
#define CP_COMMIT()  asm volatile("cp.async.commit_group;" ::: "memory")
#define CP_WAIT(n)   asm volatile("cp.async.wait_group %0;" :: "n"(n) : "memory")

// ---------------------------------------------------------------------------
// fp32 -> fp16 streaming convert (rna)
// ---------------------------------------------------------------------------
__global__ __launch_bounds__(256) void cvt_kernel(const float* __restrict__ src,
                                                  __half* __restrict__ dst, int n)
{
    int i = (blockIdx.x * 256 + threadIdx.x) * 8;
    if (i < n) {
        float4 v0 = *(const float4*)(src + i);
        float4 v1 = *(const float4*)(src + i + 4);
        __half2 h[4];
        h[0] = __floats2half2_rn(v0.x, v0.y);
        h[1] = __floats2half2_rn(v0.z, v0.w);
        h[2] = __floats2half2_rn(v1.x, v1.y);
        h[3] = __floats2half2_rn(v1.z, v1.w);
        *(uint4*)(dst + i) = *(uint4*)h;
    }
}

// ---------------------------------------------------------------------------
// fp16 GEMM: D[m,n] = sum_k A[m,k] * W[n,k]  (M=8192, N=1024, K=1024)
// Block 128x128, 8 warps (4m x 2n). 2-stage cp.async, BK=64.
// mode 0: -> g_eh16 ; mode 1: -> g_xh16 ; mode 2: fc + residual -> g_tmp
// ---------------------------------------------------------------------------
namespace { constexpr int GQ = 72; }   // smem pad (halves), 144B rows

__global__ __launch_bounds__(256, 2) void gemm16_kernel(const float* __restrict__ x,
                                                        int mode_base)
{
    extern __shared__ char smc[];
    __half* As = (__half*)smc;          // [2][128][GQ]
    __half* Bs = As + 2 * 128 * GQ;     // [2][128][GQ]
    const int tid = threadIdx.x, wid = tid >> 5;
    const int wm = wid & 3, wn = wid >> 2;
    const int n0 = blockIdx.x * 128, m0 = blockIdx.y * 128;
    const int mode = mode_base + blockIdx.z;

    const __half* A = (mode == 0) ? g_e16 : (mode == 1) ? g_x16 : g_feat16;
    const __half* W = (mode == 0) ? g_We16 : (mode == 1) ? g_Wx16 : g_Wfc16;
    const uint32_t As_u = smem_u32(As), Bs_u = smem_u32(Bs);

    FragCh acc[2][4];
    if (mode == 2) {
        #pragma unroll
        for (int i = 0; i < 2; i++)
            #pragma unroll
            for (int j = 0; j < 4; j++)
                wmma::load_matrix_sync(acc[i][j],
                    x + (size_t)(m0 + wm*32 + i*16) * DMODEL + n0 + wn*64 + j*16,
                    DMODEL, wmma::mem_row_major);
    } else {
        #pragma unroll
        for (int i = 0; i < 2; i++)
            #pragma unroll
            for (int j = 0; j < 4; j++)
                wmma::fill_fragment(acc[i][j], 0.0f);
    }

    auto stage = [&](int k0, int buf) {
        const uint32_t ao = As_u + (uint32_t)buf * 128 * GQ * 2;
        const uint32_t bo = Bs_u + (uint32_t)buf * 128 * GQ * 2;
        #pragma unroll
        for (int i = tid; i < 128 * 8; i += 256) {
            int r = i >> 3, c8 = (i & 7) * 8;
            cp16(ao + (uint32_t)(r * GQ + c8) * 2, A + (size_t)(m0 + r) * DMODEL + k0 + c8);
            cp16(bo + (uint32_t)(r * GQ + c8) * 2, W + (size_t)(n0 + r) * DMODEL + k0 + c8);
        }
    };

    stage(0, 0); CP_COMMIT();
    for (int kc = 0; kc < 16; kc++) {
        if (kc + 1 < 16) { stage((kc + 1) * 64, (kc + 1) & 1); CP_COMMIT(); CP_WAIT(1); }
        else CP_WAIT(0);
        __syncthreads();
        const __half* Ab = As + (kc & 1) * 128 * GQ;
        const __half* Bb = Bs + (kc & 1) * 128 * GQ;
        #pragma unroll
        for (int ks = 0; ks < 4; ks++) {
            FragAh a[2]; FragBhC b[4];
            #pragma unroll
            for (int i = 0; i < 2; i++)
                wmma::load_matrix_sync(a[i], Ab + (wm*32 + i*16) * GQ + ks*16, GQ);
            #pragma unroll
            for (int j = 0; j < 4; j++)
                wmma::load_matrix_sync(b[j], Bb + (wn*64 + j*16) * GQ + ks*16, GQ);
            #pragma unroll
            for (int i = 0; i < 2; i++)
                #pragma unroll
                for (int j = 0; j < 4; j++)
                    wmma::mma_sync(acc[i][j], a[i], b[j], acc[i][j]);
        }
        __syncthreads();
    }

    const int b  = m0 >> 11;
    const int ml = m0 & 2047;

    if (mode == 2) {
        #pragma unroll
        for (int i = 0; i < 2; i++)
            #pragma unroll
            for (int j = 0; j < 4; j++)
                wmma::store_matrix_sync(
                    g_tmp + (size_t)(m0 + wm*32 + i*16) * DMODEL + n0 + wn*64 + j*16,
                    acc[i][j], DMODEL, wmma::mem_row_major);
    } else {
        // roundtrip through smem (f32), convert fp16, store row-major [bh][l][64]
        float* Ts = (float*)smc;   // [128][132] = 67584 B <= 73728
        __syncthreads();           // all warps done reading As/Bs
        #pragma unroll
        for (int i = 0; i < 2; i++)
            #pragma unroll
            for (int j = 0; j < 4; j++)
                wmma::store_matrix_sync(Ts + (wm*32 + i*16) * 132 + wn*64 + j*16,
                                        acc[i][j], 132, wmma::mem_row_major);
        __syncthreads();
        __half* dst_base = (mode == 0) ? g_eh16 : g_xh16;
        #pragma unroll
        for (int i = tid; i < 128 * 16; i += 256) {
            int r = i >> 4, c8 = (i & 15) * 8;
            float4 v0 = *(float4*)&Ts[r * 132 + c8];
            float4 v1 = *(float4*)&Ts[r * 132 + c8 + 4];
            __half2 hv[4];
            hv[0] = __floats2half2_rn(v0.x, v0.y);
            hv[1] = __floats2half2_rn(v0.z, v0.w);
            hv[2] = __floats2half2_rn(v1.x, v1.y);
            hv[3] = __floats2half2_rn(v1.z, v1.w);
            int n = n0 + c8, hh = n >> 6, d0 = n & 63;
            *(uint4*)&dst_base[((size_t)(b*HEADS + hh) * SEQ + ml + r) * DH + d0] =
                *(uint4*)hv;
        }
    }
}

// ---------------------------------------------------------------------------
// Attention pass A (no E output): rowsums + feat.
// Per CTA = 128 q-rows of one bh, CH=32, triple-buffered K/X.
//   S1; scores(fp16, f32 acc); exp -> Cb(f32); S2;
//   rowsum + fp16 copy -> Ch; S3; AV(fp16: Ch @ Xb).
// ---------------------------------------------------------------------------
namespace {
constexpr int QPH = 72;   // Aq/Bk/Bx row pad (halves), 64 data cols
constexpr int CPH = 40;   // Ch pad (halves), 32 data cols
constexpr int CPF = 36;   // Cb pad (floats), 32 data cols
constexpr int CH  = 32;
constexpr int NCH = SEQ / CH;   // 64
}

__global__ __launch_bounds__(256, 2) void attn_kernel()
{
    extern __shared__ char smc[];
    __half* Aq = (__half*)smc;                  // [128][72]    18432 B
    __half* Bk = Aq + 128 * QPH;                // [3][32][72]  13824 B
    __half* Bx = Bk + 3 * 32 * QPH;             // [3][32][72]  13824 B
    float*  Cb = (float*)(Bx + 3 * 32 * QPH);   // [128][36]    18432 B
    __half* Ch = (__half*)(Cb + 128 * CPF);     // [128][40]    10240 B
    float* sinvs = (float*)(Ch + 128 * CPH);    // [128]          512 B
    const int tid = threadIdx.x, wid = tid >> 5;
    const int wm = wid & 3, wn = wid >> 2;
    const int bh = blockIdx.y, q0 = blockIdx.x * 128;
    const __half* ehb = g_eh16 + (size_t)bh * SEQ * DH;
    const __half* xhb = g_xh16 + (size_t)bh * SEQ * DH;
    const uint32_t Bk_u = smem_u32(Bk), Bx_u = smem_u32(Bx);

    auto stage = [&](int k0, int buf) {
        const uint32_t ko = Bk_u + (uint32_t)buf * 32 * QPH * 2;
        const uint32_t xo = Bx_u + (uint32_t)buf * 32 * QPH * 2;
        int r = tid >> 3, c8 = (tid & 7) * 8;
        cp16(ko + (uint32_t)(r * QPH + c8) * 2, ehb + (size_t)(k0 + r) * DH + c8);
        cp16(xo + (uint32_t)(r * QPH + c8) * 2, xhb + (size_t)(k0 + r) * DH + c8);
    };

    stage(0, 0); CP_COMMIT();

    // stage Q (x 1/8, exact pow2 in fp16)
    {
        const __half2 sc = __half2half2(__float2half(0.125f));
        #pragma unroll
        for (int i = tid; i < 128 * 8; i += 256) {
            int r = i >> 3, c8 = (i & 7) * 8;
            uint4 raw = *(const uint4*)&ehb[(size_t)(q0 + r) * DH + c8];
            __half2* hp = (__half2*)&raw;
            hp[0] = __hmul2(hp[0], sc); hp[1] = __hmul2(hp[1], sc);
            hp[2] = __hmul2(hp[2], sc); hp[3] = __hmul2(hp[3], sc);
            *(uint4*)&Aq[r * QPH + c8] = raw;
        }
    }
    __syncthreads();

    FragAh aq[4];
    #pragma unroll
    for (int ks = 0; ks < 4; ks++)
        wmma::load_matrix_sync(aq[ks], Aq + (wid * 16) * QPH + ks * 16, QPH);

    FragCh vacc[2][2];
    #pragma unroll
    for (int i = 0; i < 2; i++)
        #pragma unroll
        for (int j = 0; j < 2; j++)
            wmma::fill_fragment(vacc[i][j], 0.0f);

    float rsum[4] = {0.f, 0.f, 0.f, 0.f};
    const int erow = tid >> 3;            // 0..31
    const int ecol = (tid & 7) * 4;       // 0..28

    int cur = 0, nxt = 1;
    for (int kc = 0; kc < NCH; kc++) {
        if (kc + 1 < NCH) { stage((kc + 1) * CH, nxt); CP_COMMIT(); CP_WAIT(1); }
        else CP_WAIT(0);
        __syncthreads();                          // S1
        const __half* Kb = Bk + cur * 32 * QPH;
        const __half* Xb = Bx + cur * 32 * QPH;

        // ---- scores MMA ----
        FragCh sacc[2];
        #pragma unroll
        for (int j = 0; j < 2; j++) wmma::fill_fragment(sacc[j], 0.0f);
        #pragma unroll
        for (int ks = 0; ks < 4; ks++) {
            FragBhC bk[2];
            #pragma unroll
            for (int j = 0; j < 2; j++)
                wmma::load_matrix_sync(bk[j], Kb + (j * 16) * QPH + ks * 16, QPH);
            #pragma unroll
            for (int j = 0; j < 2; j++)
                wmma::mma_sync(sacc[j], aq[ks], bk[j], sacc[j]);
        }
        // ---- exp -> Cb ----
        #pragma unroll
        for (int j = 0; j < 2; j++) {
            #pragma unroll
            for (int t = 0; t < sacc[j].num_elements; t++)
                sacc[j].x[t] = __expf(sacc[j].x[t]);
            wmma::store_matrix_sync(Cb + (wid * 16) * CPF + j * 16,
                                    sacc[j], CPF, wmma::mem_row_major);
        }
        __syncthreads();                          // S2

        // ---- rowsum + fp16 copy into Ch (no gmem write) ----
        #pragma unroll
        for (int it = 0; it < 4; it++) {
            int r = it * 32 + erow;
            float4 v = *(const float4*)(Cb + r * CPF + ecol);
            rsum[it] += v.x + v.y + v.z + v.w;
            uint2 pk;
            *(__half2*)&pk.x = __floats2half2_rn(v.x, v.y);
            *(__half2*)&pk.y = __floats2half2_rn(v.z, v.w);
            *(uint2*)&Ch[r * CPH + ecol] = pk;
        }
        __syncthreads();                          // S3

        // ---- AV MMA ----
        #pragma unroll
        for (int ks = 0; ks < 2; ks++) {
            FragAh a[2]; FragBhR bx[2];
            #pragma unroll
            for (int i = 0; i < 2; i++)
                wmma::load_matrix_sync(a[i], Ch + (wm*32 + i*16) * CPH + ks*16, CPH);
            #pragma unroll
            for (int j = 0; j < 2; j++)
                wmma::load_matrix_sync(bx[j], Xb + (ks*16) * QPH + wn*32 + j*16, QPH);
            #pragma unroll
            for (int i = 0; i < 2; i++)
                #pragma unroll
                for (int j = 0; j < 2; j++)
                    wmma::mma_sync(vacc[i][j], a[i], bx[j], vacc[i][j]);
        }
        cur = nxt; nxt = (nxt + 1 == 3) ? 0 : nxt + 1;
    }
    __syncthreads();

    // ---- rowsum combine, publish inv ----
    #pragma unroll
    for (int it = 0; it < 4; it++) {
        float t = rsum[it];
        t += __shfl_xor_sync(0xffffffffu, t, 1);
        t += __shfl_xor_sync(0xffffffffu, t, 2);
        t += __shfl_xor_sync(0xffffffffu, t, 4);
        if ((tid & 7) == 0) {
            int r = it * 32 + erow;
            float inv = 1.0f / t;
            g_invs[(size_t)bh * SEQ + q0 + r] = inv;
            sinvs[r] = inv;
        }
    }
    __syncthreads();

    // ---- dump vacc as f32 [128][68], scale, write g_feat16 ----
    float* Df = (float*)smc;
    #pragma unroll
    for (int i = 0; i < 2; i++)
        #pragma unroll
        for (int j = 0; j < 2; j++)
            wmma::store_matrix_sync(Df + (wm*32 + i*16) * 68 + wn*32 + j*16,
                                    vacc[i][j], 68, wmma::mem_row_major);
    __syncthreads();
    const int b = bh >> 4, h = bh & 15;
    #pragma unroll
    for (int i = tid; i < 128 * 16; i += 256) {
        int r = i >> 4, c4 = (i & 15) << 2;
        float is = sinvs[r];
        float4 v = *(const float4*)(Df + r * 68 + c4);
        uint2 pk;
        *(__half2*)&pk.x = __floats2half2_rn(v.x * is, v.y * is);
        *(__half2*)&pk.y = __floats2half2_rn(v.z * is, v.w * is);
        *(uint2*)&g_feat16[((size_t)(b * SEQ) + q0 + r) * DMODEL + h * DH + c4] = pk;
    }
}

// ---------------------------------------------------------------------------
// Attention pass B: recompute scores+exp (bitwise identical MMA), scale by
// g_invs, stream final normalized attn (write-only, 1.07 GB).
// Per CTA = 128 q-rows of one bh; K triple-buffered; 2 syncs/chunk.
// ---------------------------------------------------------------------------
__global__ __launch_bounds__(256, 2) void write_attn_kernel(float* __restrict__ attn)
{
    extern __shared__ char smc[];
    __half* Aq = (__half*)smc;                  // [128][72]    18432 B
    __half* Bk = Aq + 128 * QPH;                // [3][32][72]  13824 B
    float*  Cb = (float*)(Bk + 3 * 32 * QPH);   // [128][36]    18432 B
    float* sinvs = (float*)(Cb + 128 * CPF);    // [128]          512 B
    const int tid = threadIdx.x, wid = tid >> 5;
    const int bh = blockIdx.y, q0 = blockIdx.x * 128;
    const __half* ehb = g_eh16 + (size_t)bh * SEQ * DH;
    const uint32_t Bk_u = smem_u32(Bk);

    auto stage = [&](int k0, int buf) {
        const uint32_t ko = Bk_u + (uint32_t)buf * 32 * QPH * 2;
        if (tid < 256) {   // all threads; 32 rows x 4 cp16/row
            int r = tid >> 3, c8 = (tid & 7) * 8;
            cp16(ko + (uint32_t)(r * QPH + c8) * 2, ehb + (size_t)(k0 + r) * DH + c8);
        }
    };

    stage(0, 0); CP_COMMIT();

    if (tid < 128) sinvs[tid] = g_invs[(size_t)bh * SEQ + q0 + tid];

    // stage Q (x 1/8)
    {
        const __half2 sc = __half2half2(__float2half(0.125f));
        #pragma unroll
        for (int i = tid; i < 128 * 8; i += 256) {
            int r = i >> 3, c8 = (i & 7) * 8;
            uint4 raw = *(const uint4*)&ehb[(size_t)(q0 + r) * DH + c8];
            __half2* hp = (__half2*)&raw;
            hp[0] = __hmul2(hp[0], sc); hp[1] = __hmul2(hp[1], sc);
            hp[2] = __hmul2(hp[2], sc); hp[3] = __hmul2(hp[3], sc);
            *(uint4*)&Aq[r * QPH + c8] = raw;
        }
    }
    __syncthreads();

    FragAh aq[4];
    #pragma unroll
    for (int ks = 0; ks < 4; ks++)
        wmma::load_matrix_sync(aq[ks], Aq + (wid * 16) * QPH + ks * 16, QPH);

    const int erow = tid >> 3;            // 0..31
    const int ecol = (tid & 7) * 4;       // 0..28
    float* abase = attn + ((size_t)bh * SEQ + q0) * SEQ;

    int cur = 0, nxt = 1;
    for (int kc = 0; kc < NCH; kc++) {
        if (kc + 1 < NCH) { stage((kc + 1) * CH, nxt); CP_COMMIT(); CP_WAIT(1); }
        else CP_WAIT(0);
        __syncthreads();                          // S1 (also Cb WAR guard)
        const __half* Kb = Bk + cur * 32 * QPH;

        FragCh sacc[2];
        #pragma unroll
        for (int j = 0; j < 2; j++) wmma::fill_fragment(sacc[j], 0.0f);
        #pragma unroll
        for (int ks = 0; ks < 4; ks++) {
            FragBhC bk[2];
            #pragma unroll
            for (int j = 0; j < 2; j++)
                wmma::load_matrix_sync(bk[j], Kb + (j * 16) * QPH + ks * 16, QPH);
            #pragma unroll
            for (int j = 0; j < 2; j++)
                wmma::mma_sync(sacc[j], aq[ks], bk[j], sacc[j]);
        }
        #pragma unroll
        for (int j = 0; j < 2; j++) {
            #pragma unroll
            for (int t = 0; t < sacc[j].num_elements; t++)
                sacc[j].x[t] = __expf(sacc[j].x[t]);
            wmma::store_matrix_sync(Cb + (wid * 16) * CPF + j * 16,
                                    sacc[j], CPF, wmma::mem_row_major);
        }
        __syncthreads();                          // S2: Cb visible

        // scale by inv, stream out (write-only)
        #pragma unroll
        for (int it = 0; it < 4; it++) {
            int r = it * 32 + erow;
            float is = sinvs[r];
            float4 v = *(const float4*)(Cb + r * CPF + ecol);
            v.x *= is; v.y *= is; v.z *= is; v.w *= is;
            __stcs((float4*)(abase + (size_t)r * SEQ + kc * CH + ecol), v);
        }
        cur = nxt; nxt = (nxt + 1 == 3) ? 0 : nxt + 1;
    }
}

// ---------------------------------------------------------------------------
// LayerNorm over last dim (1024), eps=1e-6. One block (256 thr) per row.
// ---------------------------------------------------------------------------
__device__ __forceinline__ float warp_sum(float v) {
    #pragma unroll
    for (int o = 16; o; o >>= 1) v += __shfl_xor_sync(0xffffffffu, v, o);
    return v;
}
__global__ __launch_bounds__(256) void ln_kernel(const float* __restrict__ gamma,
                                                 const float* __restrict__ beta,
                                                 float* __restrict__ out)
{
    const int tid = threadIdx.x;
    const size_t row = blockIdx.x;
    const float* p = g_tmp + row * DMODEL;
    float4 v = ((const float4*)p)[tid];
    float s  = v.x + v.y + v.z + v.w;
    float ss = v.x*v.x + v.y*v.y + v.z*v.z + v.w*v.w;
    s = warp_sum(s); ss = warp_sum(ss);
    __shared__ float rs[8], rss[8];
    if ((tid & 31) == 0) { rs[tid >> 5] = s; rss[tid >> 5] = ss; }
    __syncthreads();
    float S = 0.f, SS = 0.f;
    #pragma unroll
    for (int i = 0; i < 8; i++) { S += rs[i]; SS += rss[i]; }
    const float mean = S * (1.0f / DMODEL);
    const float var  = SS * (1.0f / DMODEL) - mean * mean;
    const float inv  = rsqrtf(var + 1e-6f);
    float4 g  = ((const float4*)gamma)[tid];
    float4 bb = ((const float4*)beta)[tid];
    float4 o;
    o.x = (v.x - mean) * inv * g.x + bb.x;
    o.y = (v.y - mean) * inv * g.y + bb.y;
    o.z = (v.z - mean) * inv * g.z + bb.z;
    o.w = (v.w - mean) * inv * g.w + bb.w;
    ((float4*)(out + row * DMODEL))[tid] = o;
}

// ---------------------------------------------------------------------------
// Launch
// ---------------------------------------------------------------------------
namespace {
constexpr int SMEM_GEMM  = 2 * 2 * 128 * GQ * 2;   // 73728
constexpr int SMEM_ATTN  = 128*QPH*2 + 3*32*QPH*2 + 3*32*QPH*2
                         + 128*CPF*4 + 128*CPH*2 + 128*4;    // 75264
constexpr int SMEM_WATTN = 128*QPH*2 + 3*32*QPH*2 + 128*CPF*4 + 128*4;  // 51200
}

extern "C" void kernel_launch(void* const* d_in, const int* in_sizes, int n_in,
                              void* d_out, int out_size)
{
    const float* e     = (const float*)d_in[0];
    const float* x     = (const float*)d_in[1];
    const float* We    = (const float*)d_in[2];
    const float* Wx    = (const float*)d_in[3];
    const float* Wfc   = (const float*)d_in[4];
    const float* gamma = (const float*)d_in[5];
    const float* beta  = (const float*)d_in[6];

    float* out      = (float*)d_out;
    float* out_feat = out;
    float* out_attn = out + FEAT_ELEMS;

    cudaFuncSetAttribute(gemm16_kernel,     cudaFuncAttributeMaxDynamicSharedMemorySize, SMEM_GEMM);
    cudaFuncSetAttribute(attn_kernel,       cudaFuncAttributeMaxDynamicSharedMemorySize, SMEM_ATTN);
    cudaFuncSetAttribute(write_attn_kernel, cudaFuncAttributeMaxDynamicSharedMemorySize, SMEM_WATTN);

    __half *d_e16, *d_x16, *d_We16, *d_Wx16, *d_Wfc16;
    cudaGetSymbolAddress((void**)&d_e16,  g_e16);
    cudaGetSymbolAddress((void**)&d_x16,  g_x16);
    cudaGetSymbolAddress((void**)&d_We16, g_We16);
    cudaGetSymbolAddress((void**)&d_Wx16, g_Wx16);
    cudaGetSymbolAddress((void**)&d_Wfc16, g_Wfc16);

    cvt_kernel<<<FEAT_ELEMS / 8 / 256, 256>>>(e,   d_e16,  (int)FEAT_ELEMS);
    cvt_kernel<<<FEAT_ELEMS / 8 / 256, 256>>>(x,   d_x16,  (int)FEAT_ELEMS);
    cvt_kernel<<<W_ELEMS / 8 / 256, 256>>>(We,  d_We16, (int)W_ELEMS);
    cvt_kernel<<<W_ELEMS / 8 / 256, 256>>>(Wx,  d_Wx16, (int)W_ELEMS);
    cvt_kernel<<<W_ELEMS / 8 / 256, 256>>>(Wfc, d_Wfc16, (int)W_ELEMS);

    gemm16_kernel<<<dim3(DMODEL / 128, MROWS / 128, 2), 256, SMEM_GEMM>>>(x, 0);

    dim3 ga(SEQ / 128, BHTOT);              // (16, 64)
    attn_kernel<<<ga, 256, SMEM_ATTN>>>();

    write_attn_kernel<<<ga, 256, SMEM_WATTN>>>(out_attn);

    gemm16_kernel<<<dim3(DMODEL / 128, MROWS / 128, 1), 256, SMEM_GEMM>>>(x, 2);

    ln_kernel<<<MROWS, 256>>>(gamma, beta, out_feat);
}

// round 14
// speedup vs baseline: 5.6401x; 1.0033x over previous
#include <cuda_runtime.h>
#include <cuda_fp16.h>
#include <mma.h>
#include <cstdint>

using namespace nvcuda;

// ---------------------------------------------------------------------------
// Problem constants
// ---------------------------------------------------------------------------
namespace {
constexpr int BATCH  = 4;
constexpr int HEADS  = 16;
constexpr int SEQ    = 2048;
constexpr int DH     = 64;
constexpr int DMODEL = 1024;
constexpr int MROWS  = BATCH * SEQ;           // 8192
constexpr int BHTOT  = BATCH * HEADS;         // 64
constexpr size_t HEAD_ELEMS = (size_t)BHTOT * SEQ * DH;
constexpr size_t FEAT_ELEMS = (size_t)MROWS * DMODEL;
constexpr size_t W_ELEMS    = (size_t)DMODEL * DMODEL;
}

// Scratch (device globals; allocation-free)
__device__ __align__(16) __half g_e16 [FEAT_ELEMS];
__device__ __align__(16) __half g_x16 [FEAT_ELEMS];
__device__ __align__(16) __half g_We16[W_ELEMS];
__device__ __align__(16) __half g_Wx16[W_ELEMS];
__device__ __align__(16) __half g_Wfc16[W_ELEMS];
__device__ __align__(16) __half g_eh16[HEAD_ELEMS];  // [bh][l][64]
__device__ __align__(16) __half g_xh16[HEAD_ELEMS];  // [bh][l][64]
__device__ __align__(16) __half g_feat16[FEAT_ELEMS];// [b][l][1024] fp16 (attn out)
__device__ __align__(16) float  g_tmp[FEAT_ELEMS];   // pre-LN (f32)
__device__ __align__(16) float  g_invs[(size_t)BHTOT * SEQ];

// fp16 fragments
using FragAh  = wmma::fragment<wmma::matrix_a, 16, 16, 16, __half, wmma::row_major>;
using FragBhC = wmma::fragment<wmma::matrix_b, 16, 16, 16, __half, wmma::col_major>;
using FragBhR = wmma::fragment<wmma::matrix_b, 16, 16, 16, __half, wmma::row_major>;
using FragCh  = wmma::fragment<wmma::accumulator, 16, 16, 16, float>;

// ---------------------------------------------------------------------------
// helpers
// ---------------------------------------------------------------------------
__device__ __forceinline__ uint32_t smem_u32(const void* p) {
    uint32_t a;
    asm("{ .reg .u64 t; cvta.to.shared.u64 t, %1; cvt.u32.u64 %0, t; }" : "=r"(a) : "l"(p));
    return a;
}
__device__ __forceinline__ void cp16(uint32_t s, const void* g) {
    asm volatile("cp.async.cg.shared.global [%0], [%1], 16;" :: "r"(s), "l"(g));
}
#define CP_COMMIT()  asm volatile("cp.async.commit_group;" ::: "memory")
#define CP_WAIT(n)   asm volatile("cp.async.wait_group %0;" :: "n"(n) : "memory")

// ---------------------------------------------------------------------------
// fp32 -> fp16 streaming converts (batched: blockIdx.y selects tensor)
// ---------------------------------------------------------------------------
__global__ __launch_bounds__(256) void cvt_ex_kernel(const float* __restrict__ e,
                                                     const float* __restrict__ x)
{
    const float* src = blockIdx.y ? x : e;
    __half* dst = blockIdx.y ? g_x16 : g_e16;
    size_t i = ((size_t)blockIdx.x * 256 + threadIdx.x) * 8;
    if (i < FEAT_ELEMS) {
        float4 v0 = *(const float4*)(src + i);
        float4 v1 = *(const float4*)(src + i + 4);
        __half2 h[4];
        h[0] = __floats2half2_rn(v0.x, v0.y);
        h[1] = __floats2half2_rn(v0.z, v0.w);
        h[2] = __floats2half2_rn(v1.x, v1.y);
        h[3] = __floats2half2_rn(v1.z, v1.w);
        *(uint4*)(dst + i) = *(uint4*)h;
    }
}
__global__ __launch_bounds__(256) void cvt_w_kernel(const float* __restrict__ We,
                                                    const float* __restrict__ Wx,
                                                    const float* __restrict__ Wfc)
{
    const float* src = (blockIdx.y == 0) ? We : (blockIdx.y == 1) ? Wx : Wfc;
    __half* dst = (blockIdx.y == 0) ? g_We16 : (blockIdx.y == 1) ? g_Wx16 : g_Wfc16;
    size_t i = ((size_t)blockIdx.x * 256 + threadIdx.x) * 8;
    if (i < W_ELEMS) {
        float4 v0 = *(const float4*)(src + i);
        float4 v1 = *(const float4*)(src + i + 4);
        __half2 h[4];
        h[0] = __floats2half2_rn(v0.x, v0.y);
        h[1] = __floats2half2_rn(v0.z, v0.w);
        h[2] = __floats2half2_rn(v1.x, v1.y);
        h[3] = __floats2half2_rn(v1.z, v1.w);
        *(uint4*)(dst + i) = *(uint4*)h;
    }
}

// ---------------------------------------------------------------------------
// fp16 GEMM: D[m,n] = sum_k A[m,k] * W[n,k]  (M=8192, N=1024, K=1024)
// Block 128x128, 8 warps (4m x 2n). 3-stage cp.async, BK=64.
// mode 0: -> g_eh16 ; mode 1: -> g_xh16 ; mode 2: fc + residual -> g_tmp
// ---------------------------------------------------------------------------
namespace { constexpr int GQ = 72; }   // smem pad (halves), 144B rows

__global__ __launch_bounds__(256, 2) void gemm16_kernel(const float* __restrict__ x,
                                                        int mode_base)
{
    extern __shared__ char smc[];
    __half* As = (__half*)smc;          // [3][128][GQ]
    __half* Bs = As + 3 * 128 * GQ;     // [3][128][GQ]
    const int tid = threadIdx.x, wid = tid >> 5;
    const int wm = wid & 3, wn = wid >> 2;
    const int n0 = blockIdx.x * 128, m0 = blockIdx.y * 128;
    const int mode = mode_base + blockIdx.z;

    const __half* A = (mode == 0) ? g_e16 : (mode == 1) ? g_x16 : g_feat16;
    const __half* W = (mode == 0) ? g_We16 : (mode == 1) ? g_Wx16 : g_Wfc16;
    const uint32_t As_u = smem_u32(As), Bs_u = smem_u32(Bs);

    FragCh acc[2][4];
    if (mode == 2) {
        #pragma unroll
        for (int i = 0; i < 2; i++)
            #pragma unroll
            for (int j = 0; j < 4; j++)
                wmma::load_matrix_sync(acc[i][j],
                    x + (size_t)(m0 + wm*32 + i*16) * DMODEL + n0 + wn*64 + j*16,
                    DMODEL, wmma::mem_row_major);
    } else {
        #pragma unroll
        for (int i = 0; i < 2; i++)
            #pragma unroll
            for (int j = 0; j < 4; j++)
                wmma::fill_fragment(acc[i][j], 0.0f);
    }

    auto stage = [&](int k0, int buf) {
        const uint32_t ao = As_u + (uint32_t)buf * 128 * GQ * 2;
        const uint32_t bo = Bs_u + (uint32_t)buf * 128 * GQ * 2;
        #pragma unroll
        for (int i = tid; i < 128 * 8; i += 256) {
            int r = i >> 3, c8 = (i & 7) * 8;
            cp16(ao + (uint32_t)(r * GQ + c8) * 2, A + (size_t)(m0 + r) * DMODEL + k0 + c8);
            cp16(bo + (uint32_t)(r * GQ + c8) * 2, W + (size_t)(n0 + r) * DMODEL + k0 + c8);
        }
    };

    stage(0, 0); CP_COMMIT();
    stage(64, 1); CP_COMMIT();
    for (int kc = 0; kc < 16; kc++) {
        if (kc + 2 < 16)      { stage((kc + 2) * 64, (kc + 2) % 3); CP_COMMIT(); CP_WAIT(2); }
        else if (kc + 1 < 16) { CP_WAIT(1); }
        else                  { CP_WAIT(0); }
        __syncthreads();
        const __half* Ab = As + (kc % 3) * 128 * GQ;
        const __half* Bb = Bs + (kc % 3) * 128 * GQ;
        #pragma unroll
        for (int ks = 0; ks < 4; ks++) {
            FragAh a[2]; FragBhC b[4];
            #pragma unroll
            for (int i = 0; i < 2; i++)
                wmma::load_matrix_sync(a[i], Ab + (wm*32 + i*16) * GQ + ks*16, GQ);
            #pragma unroll
            for (int j = 0; j < 4; j++)
                wmma::load_matrix_sync(b[j], Bb + (wn*64 + j*16) * GQ + ks*16, GQ);
            #pragma unroll
            for (int i = 0; i < 2; i++)
                #pragma unroll
                for (int j = 0; j < 4; j++)
                    wmma::mma_sync(acc[i][j], a[i], b[j], acc[i][j]);
        }
        __syncthreads();
    }

    const int b  = m0 >> 11;
    const int ml = m0 & 2047;

    if (mode == 2) {
        #pragma unroll
        for (int i = 0; i < 2; i++)
            #pragma unroll
            for (int j = 0; j < 4; j++)
                wmma::store_matrix_sync(
                    g_tmp + (size_t)(m0 + wm*32 + i*16) * DMODEL + n0 + wn*64 + j*16,
                    acc[i][j], DMODEL, wmma::mem_row_major);
    } else {
        // roundtrip through smem (f32), convert fp16, store row-major [bh][l][64]
        float* Ts = (float*)smc;   // [128][132] = 67584 B <= 110592
        __syncthreads();           // all warps done reading As/Bs
        #pragma unroll
        for (int i = 0; i < 2; i++)
            #pragma unroll
            for (int j = 0; j < 4; j++)
                wmma::store_matrix_sync(Ts + (wm*32 + i*16) * 132 + wn*64 + j*16,
                                        acc[i][j], 132, wmma::mem_row_major);
        __syncthreads();
        __half* dst_base = (mode == 0) ? g_eh16 : g_xh16;
        #pragma unroll
        for (int i = tid; i < 128 * 16; i += 256) {
            int r = i >> 4, c8 = (i & 15) * 8;
            float4 v0 = *(float4*)&Ts[r * 132 + c8];
            float4 v1 = *(float4*)&Ts[r * 132 + c8 + 4];
            __half2 hv[4];
            hv[0] = __floats2half2_rn(v0.x, v0.y);
            hv[1] = __floats2half2_rn(v0.z, v0.w);
            hv[2] = __floats2half2_rn(v1.x, v1.y);
            hv[3] = __floats2half2_rn(v1.z, v1.w);
            int n = n0 + c8, hh = n >> 6, d0 = n & 63;
            *(uint4*)&dst_base[((size_t)(b*HEADS + hh) * SEQ + ml + r) * DH + d0] =
                *(uint4*)hv;
        }
    }
}

// ---------------------------------------------------------------------------
// Attention pass A (no E output): rowsums + feat.
// Per CTA = 128 q-rows of one bh, CH=32, triple-buffered K/X.
// ---------------------------------------------------------------------------
namespace {
constexpr int QPH = 72;   // Aq/Bk/Bx row pad (halves), 64 data cols
constexpr int CPH = 40;   // Ch pad (halves), 32 data cols
constexpr int CPF = 36;   // Cb pad (floats), 32 data cols
constexpr int CH  = 32;
constexpr int NCH = SEQ / CH;   // 64
}

__global__ __launch_bounds__(256, 2) void attn_kernel()
{
    extern __shared__ char smc[];
    __half* Aq = (__half*)smc;                  // [128][72]    18432 B
    __half* Bk = Aq + 128 * QPH;                // [3][32][72]  13824 B
    __half* Bx = Bk + 3 * 32 * QPH;             // [3][32][72]  13824 B
    float*  Cb = (float*)(Bx + 3 * 32 * QPH);   // [128][36]    18432 B
    __half* Ch = (__half*)(Cb + 128 * CPF);     // [128][40]    10240 B
    float* sinvs = (float*)(Ch + 128 * CPH);    // [128]          512 B
    const int tid = threadIdx.x, wid = tid >> 5;
    const int wm = wid & 3, wn = wid >> 2;
    const int bh = blockIdx.y, q0 = blockIdx.x * 128;
    const __half* ehb = g_eh16 + (size_t)bh * SEQ * DH;
    const __half* xhb = g_xh16 + (size_t)bh * SEQ * DH;
    const uint32_t Bk_u = smem_u32(Bk), Bx_u = smem_u32(Bx);

    auto stage = [&](int k0, int buf) {
        const uint32_t ko = Bk_u + (uint32_t)buf * 32 * QPH * 2;
        const uint32_t xo = Bx_u + (uint32_t)buf * 32 * QPH * 2;
        int r = tid >> 3, c8 = (tid & 7) * 8;
        cp16(ko + (uint32_t)(r * QPH + c8) * 2, ehb + (size_t)(k0 + r) * DH + c8);
        cp16(xo + (uint32_t)(r * QPH + c8) * 2, xhb + (size_t)(k0 + r) * DH + c8);
    };

    stage(0, 0); CP_COMMIT();

    // stage Q (x 1/8, exact pow2 in fp16)
    {
        const __half2 sc = __half2half2(__float2half(0.125f));
        #pragma unroll
        for (int i = tid; i < 128 * 8; i += 256) {
            int r = i >> 3, c8 = (i & 7) * 8;
            uint4 raw = *(const uint4*)&ehb[(size_t)(q0 + r) * DH + c8];
            __half2* hp = (__half2*)&raw;
            hp[0] = __hmul2(hp[0], sc); hp[1] = __hmul2(hp[1], sc);
            hp[2] = __hmul2(hp[2], sc); hp[3] = __hmul2(hp[3], sc);
            *(uint4*)&Aq[r * QPH + c8] = raw;
        }
    }
    __syncthreads();

    FragAh aq[4];
    #pragma unroll
    for (int ks = 0; ks < 4; ks++)
        wmma::load_matrix_sync(aq[ks], Aq + (wid * 16) * QPH + ks * 16, QPH);

    FragCh vacc[2][2];
    #pragma unroll
    for (int i = 0; i < 2; i++)
        #pragma unroll
        for (int j = 0; j < 2; j++)
            wmma::fill_fragment(vacc[i][j], 0.0f);

    float rsum[4] = {0.f, 0.f, 0.f, 0.f};
    const int erow = tid >> 3;            // 0..31
    const int ecol = (tid & 7) * 4;       // 0..28

    int cur = 0, nxt = 1;
    for (int kc = 0; kc < NCH; kc++) {
        if (kc + 1 < NCH) { stage((kc + 1) * CH, nxt); CP_COMMIT(); CP_WAIT(1); }
        else CP_WAIT(0);
        __syncthreads();                          // S1
        const __half* Kb = Bk + cur * 32 * QPH;
        const __half* Xb = Bx + cur * 32 * QPH;

        // ---- scores MMA ----
        FragCh sacc[2];
        #pragma unroll
        for (int j = 0; j < 2; j++) wmma::fill_fragment(sacc[j], 0.0f);
        #pragma unroll
        for (int ks = 0; ks < 4; ks++) {
            FragBhC bk[2];
            #pragma unroll
            for (int j = 0; j < 2; j++)
                wmma::load_matrix_sync(bk[j], Kb + (j * 16) * QPH + ks * 16, QPH);
            #pragma unroll
            for (int j = 0; j < 2; j++)
                wmma::mma_sync(sacc[j], aq[ks], bk[j], sacc[j]);
        }
        // ---- exp -> Cb ----
        #pragma unroll
        for (int j = 0; j < 2; j++) {
            #pragma unroll
            for (int t = 0; t < sacc[j].num_elements; t++)
                sacc[j].x[t] = __expf(sacc[j].x[t]);
            wmma::store_matrix_sync(Cb + (wid * 16) * CPF + j * 16,
                                    sacc[j], CPF, wmma::mem_row_major);
        }
        __syncthreads();                          // S2

        // ---- rowsum + fp16 copy into Ch ----
        #pragma unroll
        for (int it = 0; it < 4; it++) {
            int r = it * 32 + erow;
            float4 v = *(const float4*)(Cb + r * CPF + ecol);
            rsum[it] += v.x + v.y + v.z + v.w;
            uint2 pk;
            *(__half2*)&pk.x = __floats2half2_rn(v.x, v.y);
            *(__half2*)&pk.y = __floats2half2_rn(v.z, v.w);
            *(uint2*)&Ch[r * CPH + ecol] = pk;
        }
        __syncthreads();                          // S3

        // ---- AV MMA ----
        #pragma unroll
        for (int ks = 0; ks < 2; ks++) {
            FragAh a[2]; FragBhR bx[2];
            #pragma unroll
            for (int i = 0; i < 2; i++)
                wmma::load_matrix_sync(a[i], Ch + (wm*32 + i*16) * CPH + ks*16, CPH);
            #pragma unroll
            for (int j = 0; j < 2; j++)
                wmma::load_matrix_sync(bx[j], Xb + (ks*16) * QPH + wn*32 + j*16, QPH);
            #pragma unroll
            for (int i = 0; i < 2; i++)
                #pragma unroll
                for (int j = 0; j < 2; j++)
                    wmma::mma_sync(vacc[i][j], a[i], bx[j], vacc[i][j]);
        }
        cur = nxt; nxt = (nxt + 1 == 3) ? 0 : nxt + 1;
    }
    __syncthreads();

    // ---- rowsum combine, publish inv ----
    #pragma unroll
    for (int it = 0; it < 4; it++) {
        float t = rsum[it];
        t += __shfl_xor_sync(0xffffffffu, t, 1);
        t += __shfl_xor_sync(0xffffffffu, t, 2);
        t += __shfl_xor_sync(0xffffffffu, t, 4);
        if ((tid & 7) == 0) {
            int r = it * 32 + erow;
            float inv = 1.0f / t;
            g_invs[(size_t)bh * SEQ + q0 + r] = inv;
            sinvs[r] = inv;
        }
    }
    __syncthreads();

    // ---- dump vacc as f32 [128][68], scale, write g_feat16 ----
    float* Df = (float*)smc;
    #pragma unroll
    for (int i = 0; i < 2; i++)
        #pragma unroll
        for (int j = 0; j < 2; j++)
            wmma::store_matrix_sync(Df + (wm*32 + i*16) * 68 + wn*32 + j*16,
                                    vacc[i][j], 68, wmma::mem_row_major);
    __syncthreads();
    const int b = bh >> 4, h = bh & 15;
    #pragma unroll
    for (int i = tid; i < 128 * 16; i += 256) {
        int r = i >> 4, c4 = (i & 15) << 2;
        float is = sinvs[r];
        float4 v = *(const float4*)(Df + r * 68 + c4);
        uint2 pk;
        *(__half2*)&pk.x = __floats2half2_rn(v.x * is, v.y * is);
        *(__half2*)&pk.y = __floats2half2_rn(v.z * is, v.w * is);
        *(uint2*)&g_feat16[((size_t)(b * SEQ) + q0 + r) * DMODEL + h * DH + c4] = pk;
    }
}

// ---------------------------------------------------------------------------
// Attention pass B: recompute scores+exp, scale by g_invs, stream final attn.
// ---------------------------------------------------------------------------
__global__ __launch_bounds__(256, 2) void write_attn_kernel(float* __restrict__ attn)
{
    extern __shared__ char smc[];
    __half* Aq = (__half*)smc;                  // [128][72]    18432 B
    __half* Bk = Aq + 128 * QPH;                // [3][32][72]  13824 B
    float*  Cb = (float*)(Bk + 3 * 32 * QPH);   // [128][36]    18432 B
    float* sinvs = (float*)(Cb + 128 * CPF);    // [128]          512 B
    const int tid = threadIdx.x, wid = tid >> 5;
    const int bh = blockIdx.y, q0 = blockIdx.x * 128;
    const __half* ehb = g_eh16 + (size_t)bh * SEQ * DH;
    const uint32_t Bk_u = smem_u32(Bk);

    auto stage = [&](int k0, int buf) {
        const uint32_t ko = Bk_u + (uint32_t)buf * 32 * QPH * 2;
        int r = tid >> 3, c8 = (tid & 7) * 8;
        cp16(ko + (uint32_t)(r * QPH + c8) * 2, ehb + (size_t)(k0 + r) * DH + c8);
    };

    stage(0, 0); CP_COMMIT();

    if (tid < 128) sinvs[tid] = g_invs[(size_t)bh * SEQ + q0 + tid];

    // stage Q (x 1/8)
    {
        const __half2 sc = __half2half2(__float2half(0.125f));
        #pragma unroll
        for (int i = tid; i < 128 * 8; i += 256) {
            int r = i >> 3, c8 = (i & 7) * 8;
            uint4 raw = *(const uint4*)&ehb[(size_t)(q0 + r) * DH + c8];
            __half2* hp = (__half2*)&raw;
            hp[0] = __hmul2(hp[0], sc); hp[1] = __hmul2(hp[1], sc);
            hp[2] = __hmul2(hp[2], sc); hp[3] = __hmul2(hp[3], sc);
            *(uint4*)&Aq[r * QPH + c8] = raw;
        }
    }
    __syncthreads();

    FragAh aq[4];
    #pragma unroll
    for (int ks = 0; ks < 4; ks++)
        wmma::load_matrix_sync(aq[ks], Aq + (wid * 16) * QPH + ks * 16, QPH);

    const int erow = tid >> 3;            // 0..31
    const int ecol = (tid & 7) * 4;       // 0..28
    float* abase = attn + ((size_t)bh * SEQ + q0) * SEQ;

    int cur = 0, nxt = 1;
    for (int kc = 0; kc < NCH; kc++) {
        if (kc + 1 < NCH) { stage((kc + 1) * CH, nxt); CP_COMMIT(); CP_WAIT(1); }
        else CP_WAIT(0);
        __syncthreads();                          // S1 (also Cb WAR guard)
        const __half* Kb = Bk + cur * 32 * QPH;

        FragCh sacc[2];
        #pragma unroll
        for (int j = 0; j < 2; j++) wmma::fill_fragment(sacc[j], 0.0f);
        #pragma unroll
        for (int ks = 0; ks < 4; ks++) {
            FragBhC bk[2];
            #pragma unroll
            for (int j = 0; j < 2; j++)
                wmma::load_matrix_sync(bk[j], Kb + (j * 16) * QPH + ks * 16, QPH);
            #pragma unroll
            for (int j = 0; j < 2; j++)
                wmma::mma_sync(sacc[j], aq[ks], bk[j], sacc[j]);
        }
        #pragma unroll
        for (int j = 0; j < 2; j++) {
            #pragma unroll
            for (int t = 0; t < sacc[j].num_elements; t++)
                sacc[j].x[t] = __expf(sacc[j].x[t]);
            wmma::store_matrix_sync(Cb + (wid * 16) * CPF + j * 16,
                                    sacc[j], CPF, wmma::mem_row_major);
        }
        __syncthreads();                          // S2: Cb visible

        #pragma unroll
        for (int it = 0; it < 4; it++) {
            int r = it * 32 + erow;
            float is = sinvs[r];
            float4 v = *(const float4*)(Cb + r * CPF + ecol);
            v.x *= is; v.y *= is; v.z *= is; v.w *= is;
            __stcs((float4*)(abase + (size_t)r * SEQ + kc * CH + ecol), v);
        }
        cur = nxt; nxt = (nxt + 1 == 3) ? 0 : nxt + 1;
    }
}

// ---------------------------------------------------------------------------
// LayerNorm: warp-per-row (8 rows per 256-thr block), shfl-only reduction.
// ---------------------------------------------------------------------------
__global__ __launch_bounds__(256) void ln_kernel(const float* __restrict__ gamma,
                                                 const float* __restrict__ beta,
                                                 float* __restrict__ out)
{
    const int lane = threadIdx.x & 31;
    const size_t row = (size_t)blockIdx.x * 8 + (threadIdx.x >> 5);
    const float4* p = (const float4*)(g_tmp + row * DMODEL);

    float4 v[8];
    float s = 0.f, ss = 0.f;
    #pragma unroll
    for (int i = 0; i < 8; i++) {
        v[i] = p[lane + 32 * i];
        s  += v[i].x + v[i].y + v[i].z + v[i].w;
        ss += v[i].x*v[i].x + v[i].y*v[i].y + v[i].z*v[i].z + v[i].w*v[i].w;
    }
    #pragma unroll
    for (int o = 16; o; o >>= 1) {
        s  += __shfl_xor_sync(0xffffffffu, s, o);
        ss += __shfl_xor_sync(0xffffffffu, ss, o);
    }
    const float mean = s * (1.0f / DMODEL);
    const float var  = ss * (1.0f / DMODEL) - mean * mean;
    const float inv  = rsqrtf(var + 1e-6f);

    float4* q = (float4*)(out + row * DMODEL);
    const float4* gp = (const float4*)gamma;
    const float4* bp = (const float4*)beta;
    #pragma unroll
    for (int i = 0; i < 8; i++) {
        float4 g = gp[lane + 32 * i];
        float4 b = bp[lane + 32 * i];
        float4 o;
        o.x = (v[i].x - mean) * inv * g.x + b.x;
        o.y = (v[i].y - mean) * inv * g.y + b.y;
        o.z = (v[i].z - mean) * inv * g.z + b.z;
        o.w = (v[i].w - mean) * inv * g.w + b.w;
        q[lane + 32 * i] = o;
    }
}

// ---------------------------------------------------------------------------
// Launch
// ---------------------------------------------------------------------------
namespace {
constexpr int SMEM_GEMM  = 3 * 2 * 128 * GQ * 2;   // 110592
constexpr int SMEM_ATTN  = 128*QPH*2 + 3*32*QPH*2 + 3*32*QPH*2
                         + 128*CPF*4 + 128*CPH*2 + 128*4;    // 75264
constexpr int SMEM_WATTN = 128*QPH*2 + 3*32*QPH*2 + 128*CPF*4 + 128*4;  // 51200
}

extern "C" void kernel_launch(void* const* d_in, const int* in_sizes, int n_in,
                              void* d_out, int out_size)
{
    const float* e     = (const float*)d_in[0];
    const float* x     = (const float*)d_in[1];
    const float* We    = (const float*)d_in[2];
    const float* Wx    = (const float*)d_in[3];
    const float* Wfc   = (const float*)d_in[4];
    const float* gamma = (const float*)d_in[5];
    const float* beta  = (const float*)d_in[6];

    float* out      = (float*)d_out;
    float* out_feat = out;
    float* out_attn = out + FEAT_ELEMS;

    cudaFuncSetAttribute(gemm16_kernel,     cudaFuncAttributeMaxDynamicSharedMemorySize, SMEM_GEMM);
    cudaFuncSetAttribute(attn_kernel,       cudaFuncAttributeMaxDynamicSharedMemorySize, SMEM_ATTN);
    cudaFuncSetAttribute(write_attn_kernel, cudaFuncAttributeMaxDynamicSharedMemorySize, SMEM_WATTN);

    // idx 0: e+x convert ; idx 1: weight converts
    cvt_ex_kernel<<<dim3(FEAT_ELEMS / 8 / 256, 2), 256>>>(e, x);
    cvt_w_kernel<<<dim3(W_ELEMS / 8 / 256, 3), 256>>>(We, Wx, Wfc);

    // idx 2: both projections (z = mode)
    gemm16_kernel<<<dim3(DMODEL / 128, MROWS / 128, 2), 256, SMEM_GEMM>>>(x, 0);

    dim3 ga(SEQ / 128, BHTOT);              // (16, 64)
    attn_kernel<<<ga, 256, SMEM_ATTN>>>();            // idx 3 (ncu captures this)

    write_attn_kernel<<<ga, 256, SMEM_WATTN>>>(out_attn);  // idx 4

    gemm16_kernel<<<dim3(DMODEL / 128, MROWS / 128, 1), 256, SMEM_GEMM>>>(x, 2);  // idx 5

    ln_kernel<<<MROWS / 8, 256>>>(gamma, beta, out_feat);   // idx 6
}

// round 15
// speedup vs baseline: 6.5566x; 1.1625x over previous
#include <cuda_runtime.h>
#include <cuda_fp16.h>
#include <mma.h>
#include <cstdint>

using namespace nvcuda;

// ---------------------------------------------------------------------------
// Problem constants
// ---------------------------------------------------------------------------
namespace {
constexpr int BATCH  = 4;
constexpr int HEADS  = 16;
constexpr int SEQ    = 2048;
constexpr int DH     = 64;
constexpr int DMODEL = 1024;
constexpr int MROWS  = BATCH * SEQ;           // 8192
constexpr int BHTOT  = BATCH * HEADS;         // 64
constexpr size_t HEAD_ELEMS = (size_t)BHTOT * SEQ * DH;
constexpr size_t FEAT_ELEMS = (size_t)MROWS * DMODEL;
constexpr size_t W_ELEMS    = (size_t)DMODEL * DMODEL;
}

// Scratch (device globals; allocation-free)
__device__ __align__(16) __half g_e16 [FEAT_ELEMS];
__device__ __align__(16) __half g_x16 [FEAT_ELEMS];
__device__ __align__(16) __half g_We16[W_ELEMS];
__device__ __align__(16) __half g_Wx16[W_ELEMS];
__device__ __align__(16) __half g_Wfc16[W_ELEMS];
__device__ __align__(16) __half g_eh16[HEAD_ELEMS];  // [bh][l][64]
__device__ __align__(16) __half g_xh16[HEAD_ELEMS];  // [bh][l][64]
__device__ __align__(16) __half g_feat16[FEAT_ELEMS];// [b][l][1024] fp16 (attn out)
__device__ __align__(16) float  g_tmp[FEAT_ELEMS];   // pre-LN (f32)
__device__ __align__(16) float  g_invs[(size_t)BHTOT * SEQ];

// fp16 wmma fragments (GEMM + pass B)
using FragAh  = wmma::fragment<wmma::matrix_a, 16, 16, 16, __half, wmma::row_major>;
using FragBhC = wmma::fragment<wmma::matrix_b, 16, 16, 16, __half, wmma::col_major>;
using FragCh  = wmma::fragment<wmma::accumulator, 16, 16, 16, float>;

// ---------------------------------------------------------------------------
// helpers
// ---------------------------------------------------------------------------
__device__ __forceinline__ uint32_t smem_u32(const void* p) {
    uint32_t a;
    asm("{ .reg .u64 t; cvta.to.shared.u64 t, %1; cvt.u32.u64 %0, t; }" : "=r"(a) : "l"(p));
    return a;
}
__device__ __forceinline__ void cp16(uint32_t s, const void* g) {
    asm volatile("cp.async.cg.shared.global [%0], [%1], 16;" :: "r"(s), "l"(g));
}
#define CP_COMMIT()  asm volatile("cp.async.commit_group;" ::: "memory")
#define CP_WAIT(n)   asm volatile("cp.async.wait_group %0;" :: "n"(n) : "memory")

__device__ __forceinline__ void ldsm4(uint32_t* r, uint32_t addr) {
    asm volatile("ldmatrix.sync.aligned.m8n8.x4.shared.b16 {%0,%1,%2,%3}, [%4];"
        : "=r"(r[0]), "=r"(r[1]), "=r"(r[2]), "=r"(r[3]) : "r"(addr));
}
__device__ __forceinline__ void ldsm4t(uint32_t* r, uint32_t addr) {
    asm volatile("ldmatrix.sync.aligned.m8n8.x4.trans.shared.b16 {%0,%1,%2,%3}, [%4];"
        : "=r"(r[0]), "=r"(r[1]), "=r"(r[2]), "=r"(r[3]) : "r"(addr));
}
__device__ __forceinline__ void mma16816(float* d, const uint32_t* a, const uint32_t* b) {
    asm volatile("mma.sync.aligned.m16n8k16.row.col.f32.f16.f16.f32 "
        "{%0,%1,%2,%3}, {%4,%5,%6,%7}, {%8,%9}, {%0,%1,%2,%3};"
        : "+f"(d[0]), "+f"(d[1]), "+f"(d[2]), "+f"(d[3])
        : "r"(a[0]), "r"(a[1]), "r"(a[2]), "r"(a[3]), "r"(b[0]), "r"(b[1]));
}
__device__ __forceinline__ uint32_t h2u(float lo, float hi) {
    __half2 h = __floats2half2_rn(lo, hi);
    return *(uint32_t*)&h;
}

// ---------------------------------------------------------------------------
// fp32 -> fp16 streaming converts (batched: blockIdx.y selects tensor)
// ---------------------------------------------------------------------------
__global__ __launch_bounds__(256) void cvt_ex_kernel(const float* __restrict__ e,
                                                     const float* __restrict__ x)
{
    const float* src = blockIdx.y ? x : e;
    __half* dst = blockIdx.y ? g_x16 : g_e16;
    size_t i = ((size_t)blockIdx.x * 256 + threadIdx.x) * 8;
    if (i < FEAT_ELEMS) {
        float4 v0 = *(const float4*)(src + i);
        float4 v1 = *(const float4*)(src + i + 4);
        __half2 h[4];
        h[0] = __floats2half2_rn(v0.x, v0.y);
        h[1] = __floats2half2_rn(v0.z, v0.w);
        h[2] = __floats2half2_rn(v1.x, v1.y);
        h[3] = __floats2half2_rn(v1.z, v1.w);
        *(uint4*)(dst + i) = *(uint4*)h;
    }
}
__global__ __launch_bounds__(256) void cvt_w_kernel(const float* __restrict__ We,
                                                    const float* __restrict__ Wx,
                                                    const float* __restrict__ Wfc)
{
    const float* src = (blockIdx.y == 0) ? We : (blockIdx.y == 1) ? Wx : Wfc;
    __half* dst = (blockIdx.y == 0) ? g_We16 : (blockIdx.y == 1) ? g_Wx16 : g_Wfc16;
    size_t i = ((size_t)blockIdx.x * 256 + threadIdx.x) * 8;
    if (i < W_ELEMS) {
        float4 v0 = *(const float4*)(src + i);
        float4 v1 = *(const float4*)(src + i + 4);
        __half2 h[4];
        h[0] = __floats2half2_rn(v0.x, v0.y);
        h[1] = __floats2half2_rn(v0.z, v0.w);
        h[2] = __floats2half2_rn(v1.x, v1.y);
        h[3] = __floats2half2_rn(v1.z, v1.w);
        *(uint4*)(dst + i) = *(uint4*)h;
    }
}

// ---------------------------------------------------------------------------
// fp16 GEMM: D[m,n] = sum_k A[m,k] * W[n,k]  (M=8192, N=1024, K=1024)
// Block 128x128, 8 warps (4m x 2n). 3-stage cp.async, BK=64. (unchanged R14)
// ---------------------------------------------------------------------------
namespace { constexpr int GQ = 72; }   // smem pad (halves)

__global__ __launch_bounds__(256, 2) void gemm16_kernel(const float* __restrict__ x,
                                                        int mode_base)
{
    extern __shared__ char smc[];
    __half* As = (__half*)smc;          // [3][128][GQ]
    __half* Bs = As + 3 * 128 * GQ;     // [3][128][GQ]
    const int tid = threadIdx.x, wid = tid >> 5;
    const int wm = wid & 3, wn = wid >> 2;
    const int n0 = blockIdx.x * 128, m0 = blockIdx.y * 128;
    const int mode = mode_base + blockIdx.z;

    const __half* A = (mode == 0) ? g_e16 : (mode == 1) ? g_x16 : g_feat16;
    const __half* W = (mode == 0) ? g_We16 : (mode == 1) ? g_Wx16 : g_Wfc16;
    const uint32_t As_u = smem_u32(As), Bs_u = smem_u32(Bs);

    FragCh acc[2][4];
    if (mode == 2) {
        #pragma unroll
        for (int i = 0; i < 2; i++)
            #pragma unroll
            for (int j = 0; j < 4; j++)
                wmma::load_matrix_sync(acc[i][j],
                    x + (size_t)(m0 + wm*32 + i*16) * DMODEL + n0 + wn*64 + j*16,
                    DMODEL, wmma::mem_row_major);
    } else {
        #pragma unroll
        for (int i = 0; i < 2; i++)
            #pragma unroll
            for (int j = 0; j < 4; j++)
                wmma::fill_fragment(acc[i][j], 0.0f);
    }

    auto stage = [&](int k0, int buf) {
        const uint32_t ao = As_u + (uint32_t)buf * 128 * GQ * 2;
        const uint32_t bo = Bs_u + (uint32_t)buf * 128 * GQ * 2;
        #pragma unroll
        for (int i = tid; i < 128 * 8; i += 256) {
            int r = i >> 3, c8 = (i & 7) * 8;
            cp16(ao + (uint32_t)(r * GQ + c8) * 2, A + (size_t)(m0 + r) * DMODEL + k0 + c8);
            cp16(bo + (uint32_t)(r * GQ + c8) * 2, W + (size_t)(n0 + r) * DMODEL + k0 + c8);
        }
    };

    stage(0, 0); CP_COMMIT();
    stage(64, 1); CP_COMMIT();
    for (int kc = 0; kc < 16; kc++) {
        if (kc + 2 < 16)      { stage((kc + 2) * 64, (kc + 2) % 3); CP_COMMIT(); CP_WAIT(2); }
        else if (kc + 1 < 16) { CP_WAIT(1); }
        else                  { CP_WAIT(0); }
        __syncthreads();
        const __half* Ab = As + (kc % 3) * 128 * GQ;
        const __half* Bb = Bs + (kc % 3) * 128 * GQ;
        #pragma unroll
        for (int ks = 0; ks < 4; ks++) {
            FragAh a[2]; FragBhC b[4];
            #pragma unroll
            for (int i = 0; i < 2; i++)
                wmma::load_matrix_sync(a[i], Ab + (wm*32 + i*16) * GQ + ks*16, GQ);
            #pragma unroll
            for (int j = 0; j < 4; j++)
                wmma::load_matrix_sync(b[j], Bb + (wn*64 + j*16) * GQ + ks*16, GQ);
            #pragma unroll
            for (int i = 0; i < 2; i++)
                #pragma unroll
                for (int j = 0; j < 4; j++)
                    wmma::mma_sync(acc[i][j], a[i], b[j], acc[i][j]);
        }
        __syncthreads();
    }

    const int b  = m0 >> 11;
    const int ml = m0 & 2047;

    if (mode == 2) {
        #pragma unroll
        for (int i = 0; i < 2; i++)
            #pragma unroll
            for (int j = 0; j < 4; j++)
                wmma::store_matrix_sync(
                    g_tmp + (size_t)(m0 + wm*32 + i*16) * DMODEL + n0 + wn*64 + j*16,
                    acc[i][j], DMODEL, wmma::mem_row_major);
    } else {
        float* Ts = (float*)smc;   // [128][132]
        __syncthreads();
        #pragma unroll
        for (int i = 0; i < 2; i++)
            #pragma unroll
            for (int j = 0; j < 4; j++)
                wmma::store_matrix_sync(Ts + (wm*32 + i*16) * 132 + wn*64 + j*16,
                                        acc[i][j], 132, wmma::mem_row_major);
        __syncthreads();
        __half* dst_base = (mode == 0) ? g_eh16 : g_xh16;
        #pragma unroll
        for (int i = tid; i < 128 * 16; i += 256) {
            int r = i >> 4, c8 = (i & 15) * 8;
            float4 v0 = *(float4*)&Ts[r * 132 + c8];
            float4 v1 = *(float4*)&Ts[r * 132 + c8 + 4];
            __half2 hv[4];
            hv[0] = __floats2half2_rn(v0.x, v0.y);
            hv[1] = __floats2half2_rn(v0.z, v0.w);
            hv[2] = __floats2half2_rn(v1.x, v1.y);
            hv[3] = __floats2half2_rn(v1.z, v1.w);
            int n = n0 + c8, hh = n >> 6, d0 = n & 63;
            *(uint4*)&dst_base[((size_t)(b*HEADS + hh) * SEQ + ml + r) * DH + d0] =
                *(uint4*)hv;
        }
    }
}

// ---------------------------------------------------------------------------
// Attention pass A — register-resident (raw mma.m16n8k16 + ldmatrix).
// CTA = 128 q rows; warp w owns 16 q rows. CH=32, triple-buffered K/X.
// Per chunk: 1 barrier. P(16x32) in regs -> exp in regs -> fp16 A-frags in
// regs -> AV mma. Rowsums accumulated in regs; feat stored from regs.
// ---------------------------------------------------------------------------
namespace {
constexpr int QPH = 72;   // row pad (halves), 64 data cols, 144B rows
constexpr int CH  = 32;
constexpr int NCH = SEQ / CH;   // 64
constexpr int CPF = 36;   // Cb pad (floats) — pass B only
}

__global__ __launch_bounds__(256, 2) void attn_kernel()
{
    extern __shared__ char smc[];
    __half* Aq = (__half*)smc;                  // [128][72]    18432 B
    __half* Bk = Aq + 128 * QPH;                // [3][32][72]  13824 B
    __half* Bx = Bk + 3 * 32 * QPH;             // [3][32][72]  13824 B
    const int tid = threadIdx.x, wid = tid >> 5, lane = tid & 31;
    const int bh = blockIdx.y, q0 = blockIdx.x * 128;
    const __half* ehb = g_eh16 + (size_t)bh * SEQ * DH;
    const __half* xhb = g_xh16 + (size_t)bh * SEQ * DH;
    const uint32_t Aq_u = smem_u32(Aq), Bk_u = smem_u32(Bk), Bx_u = smem_u32(Bx);

    auto stage = [&](int k0, int buf) {
        const uint32_t ko = Bk_u + (uint32_t)buf * 32 * QPH * 2;
        const uint32_t xo = Bx_u + (uint32_t)buf * 32 * QPH * 2;
        int r = tid >> 3, c8 = (tid & 7) * 8;
        cp16(ko + (uint32_t)(r * QPH + c8) * 2, ehb + (size_t)(k0 + r) * DH + c8);
        cp16(xo + (uint32_t)(r * QPH + c8) * 2, xhb + (size_t)(k0 + r) * DH + c8);
    };

    stage(0, 0); CP_COMMIT();

    // stage Q (x 1/8, exact pow2 in fp16)
    {
        const __half2 sc = __half2half2(__float2half(0.125f));
        #pragma unroll
        for (int i = tid; i < 128 * 8; i += 256) {
            int r = i >> 3, c8 = (i & 7) * 8;
            uint4 raw = *(const uint4*)&ehb[(size_t)(q0 + r) * DH + c8];
            __half2* hp = (__half2*)&raw;
            hp[0] = __hmul2(hp[0], sc); hp[1] = __hmul2(hp[1], sc);
            hp[2] = __hmul2(hp[2], sc); hp[3] = __hmul2(hp[3], sc);
            *(uint4*)&Aq[r * QPH + c8] = raw;
        }
    }
    __syncthreads();

    // preload Q A-fragments (4 k-steps), loop-invariant
    uint32_t aq[4][4];
    {
        const int lr = lane & 7;
        const int rofs = ((lane >> 3) & 1) * 8;     // +8 rows for groups 1,3
        const int cofs = (lane >> 4) * 8;           // +8 cols for groups 2,3
        const int row  = wid * 16 + rofs + lr;
        #pragma unroll
        for (int s = 0; s < 4; s++)
            ldsm4(aq[s], Aq_u + (uint32_t)(row * QPH + s * 16 + cofs) * 2);
    }

    float vacc[8][4];
    #pragma unroll
    for (int j = 0; j < 8; j++)
        #pragma unroll
        for (int e = 0; e < 4; e++) vacc[j][e] = 0.0f;
    float rsum0 = 0.0f, rsum1 = 0.0f;

    // per-lane ldmatrix address components
    const int lr = lane & 7;
    const int g01 = ((lane >> 3) & 1) * 8;
    const int g23 = (lane >> 4) * 8;

    int cur = 0, nxt = 1;
    for (int kc = 0; kc < NCH; kc++) {
        if (kc + 1 < NCH) { stage((kc + 1) * CH, nxt); CP_COMMIT(); CP_WAIT(1); }
        else CP_WAIT(0);
        __syncthreads();                          // single barrier per chunk
        const uint32_t Kb_u = Bk_u + (uint32_t)cur * 32 * QPH * 2;
        const uint32_t Xb_u = Bx_u + (uint32_t)cur * 32 * QPH * 2;

        // ---- scores: P[16 x 32] = Q(16x64) . K'(64x32) ----
        float P[4][4];
        #pragma unroll
        for (int j = 0; j < 4; j++) {
            #pragma unroll
            for (int e = 0; e < 4; e++) P[j][e] = 0.0f;
            // K B-fragments: rows = k' (n), cols = d (k). non-trans ldmatrix.
            // x4 #p covers ksteps 2p, 2p+1: lane addr row=j*8+lr, col=p*32+(lane>>3)*8
            uint32_t kb0[4], kb1[4];
            ldsm4(kb0, Kb_u + (uint32_t)((j * 8 + lr) * QPH + 0  + (lane >> 3) * 8) * 2);
            ldsm4(kb1, Kb_u + (uint32_t)((j * 8 + lr) * QPH + 32 + (lane >> 3) * 8) * 2);
            mma16816(P[j], aq[0], kb0 + 0);
            mma16816(P[j], aq[1], kb0 + 2);
            mma16816(P[j], aq[2], kb1 + 0);
            mma16816(P[j], aq[3], kb1 + 2);
        }
        // ---- exp + rowsum (in registers) ----
        #pragma unroll
        for (int j = 0; j < 4; j++) {
            P[j][0] = __expf(P[j][0]); P[j][1] = __expf(P[j][1]);
            P[j][2] = __expf(P[j][2]); P[j][3] = __expf(P[j][3]);
            rsum0 += P[j][0] + P[j][1];
            rsum1 += P[j][2] + P[j][3];
        }
        // ---- convert P -> fp16 A-fragments (FA2 identity) ----
        uint32_t pa[2][4];
        #pragma unroll
        for (int s = 0; s < 2; s++) {
            pa[s][0] = h2u(P[2*s][0],   P[2*s][1]);
            pa[s][1] = h2u(P[2*s][2],   P[2*s][3]);
            pa[s][2] = h2u(P[2*s+1][0], P[2*s+1][1]);
            pa[s][3] = h2u(P[2*s+1][2], P[2*s+1][3]);
        }
        // ---- AV: vacc(16q x 64d) += P(16x32) . X(32x64) ----
        #pragma unroll
        for (int s = 0; s < 2; s++) {
            #pragma unroll
            for (int j0 = 0; j0 < 8; j0 += 2) {
                // X B-frags: rows = k' (k), cols = d (n). trans ldmatrix.
                // x4 covers n-tiles j0, j0+1 at kstep s.
                uint32_t xb[4];
                ldsm4t(xb, Xb_u + (uint32_t)((s * 16 + g01 + lr) * QPH + j0 * 8 + g23) * 2);
                mma16816(vacc[j0],     pa[s], xb + 0);
                mma16816(vacc[j0 + 1], pa[s], xb + 2);
            }
        }
        cur = nxt; nxt = (nxt + 1 == 3) ? 0 : nxt + 1;
    }

    // ---- rowsum reduce over quad (lanes share row), publish inv ----
    rsum0 += __shfl_xor_sync(0xffffffffu, rsum0, 1);
    rsum0 += __shfl_xor_sync(0xffffffffu, rsum0, 2);
    rsum1 += __shfl_xor_sync(0xffffffffu, rsum1, 1);
    rsum1 += __shfl_xor_sync(0xffffffffu, rsum1, 2);
    const float inv0 = 1.0f / rsum0;
    const float inv1 = 1.0f / rsum1;
    const int rlo = wid * 16 + (lane >> 2);
    if ((lane & 3) == 0) {
        g_invs[(size_t)bh * SEQ + q0 + rlo]     = inv0;
        g_invs[(size_t)bh * SEQ + q0 + rlo + 8] = inv1;
    }

    // ---- feat: scale vacc by inv, store fp16 directly ----
    const int b = bh >> 4, h = bh & 15;
    const size_t rowlo = ((size_t)(b * SEQ) + q0 + rlo) * DMODEL + h * DH + (lane & 3) * 2;
    const size_t rowhi = rowlo + 8 * DMODEL;
    #pragma unroll
    for (int j = 0; j < 8; j++) {
        *(uint32_t*)&g_feat16[rowlo + j * 8] = h2u(vacc[j][0] * inv0, vacc[j][1] * inv0);
        *(uint32_t*)&g_feat16[rowhi + j * 8] = h2u(vacc[j][2] * inv1, vacc[j][3] * inv1);
    }
}

// ---------------------------------------------------------------------------
// Attention pass B: recompute scores+exp (wmma), scale by g_invs, stream attn.
// (unchanged from R14 — at the 1.07 GB DRAM write floor)
// ---------------------------------------------------------------------------
__global__ __launch_bounds__(256, 2) void write_attn_kernel(float* __restrict__ attn)
{
    extern __shared__ char smc[];
    __half* Aq = (__half*)smc;                  // [128][72]
    __half* Bk = Aq + 128 * QPH;                // [3][32][72]
    float*  Cb = (float*)(Bk + 3 * 32 * QPH);   // [128][36]
    float* sinvs = (float*)(Cb + 128 * CPF);    // [128]
    const int tid = threadIdx.x, wid = tid >> 5;
    const int bh = blockIdx.y, q0 = blockIdx.x * 128;
    const __half* ehb = g_eh16 + (size_t)bh * SEQ * DH;
    const uint32_t Bk_u = smem_u32(Bk);

    auto stage = [&](int k0, int buf) {
        const uint32_t ko = Bk_u + (uint32_t)buf * 32 * QPH * 2;
        int r = tid >> 3, c8 = (tid & 7) * 8;
        cp16(ko + (uint32_t)(r * QPH + c8) * 2, ehb + (size_t)(k0 + r) * DH + c8);
    };

    stage(0, 0); CP_COMMIT();

    if (tid < 128) sinvs[tid] = g_invs[(size_t)bh * SEQ + q0 + tid];

    {
        const __half2 sc = __half2half2(__float2half(0.125f));
        #pragma unroll
        for (int i = tid; i < 128 * 8; i += 256) {
            int r = i >> 3, c8 = (i & 7) * 8;
            uint4 raw = *(const uint4*)&ehb[(size_t)(q0 + r) * DH + c8];
            __half2* hp = (__half2*)&raw;
            hp[0] = __hmul2(hp[0], sc); hp[1] = __hmul2(hp[1], sc);
            hp[2] = __hmul2(hp[2], sc); hp[3] = __hmul2(hp[3], sc);
            *(uint4*)&Aq[r * QPH + c8] = raw;
        }
    }
    __syncthreads();

    FragAh aq[4];
    #pragma unroll
    for (int ks = 0; ks < 4; ks++)
        wmma::load_matrix_sync(aq[ks], Aq + (wid * 16) * QPH + ks * 16, QPH);

    const int erow = tid >> 3;
    const int ecol = (tid & 7) * 4;
    float* abase = attn + ((size_t)bh * SEQ + q0) * SEQ;

    int cur = 0, nxt = 1;
    for (int kc = 0; kc < NCH; kc++) {
        if (kc + 1 < NCH) { stage((kc + 1) * CH, nxt); CP_COMMIT(); CP_WAIT(1); }
        else CP_WAIT(0);
        __syncthreads();
        const __half* Kb = Bk + cur * 32 * QPH;

        FragCh sacc[2];
        #pragma unroll
        for (int j = 0; j < 2; j++) wmma::fill_fragment(sacc[j], 0.0f);
        #pragma unroll
        for (int ks = 0; ks < 4; ks++) {
            FragBhC bk[2];
            #pragma unroll
            for (int j = 0; j < 2; j++)
                wmma::load_matrix_sync(bk[j], Kb + (j * 16) * QPH + ks * 16, QPH);
            #pragma unroll
            for (int j = 0; j < 2; j++)
                wmma::mma_sync(sacc[j], aq[ks], bk[j], sacc[j]);
        }
        #pragma unroll
        for (int j = 0; j < 2; j++) {
            #pragma unroll
            for (int t = 0; t < sacc[j].num_elements; t++)
                sacc[j].x[t] = __expf(sacc[j].x[t]);
            wmma::store_matrix_sync(Cb + (wid * 16) * CPF + j * 16,
                                    sacc[j], CPF, wmma::mem_row_major);
        }
        __syncthreads();

        #pragma unroll
        for (int it = 0; it < 4; it++) {
            int r = it * 32 + erow;
            float is = sinvs[r];
            float4 v = *(const float4*)(Cb + r * CPF + ecol);
            v.x *= is; v.y *= is; v.z *= is; v.w *= is;
            __stcs((float4*)(abase + (size_t)r * SEQ + kc * CH + ecol), v);
        }
        cur = nxt; nxt = (nxt + 1 == 3) ? 0 : nxt + 1;
    }
}

// ---------------------------------------------------------------------------
// LayerNorm: warp-per-row (8 rows per 256-thr block), shfl-only reduction.
// ---------------------------------------------------------------------------
__global__ __launch_bounds__(256) void ln_kernel(const float* __restrict__ gamma,
                                                 const float* __restrict__ beta,
                                                 float* __restrict__ out)
{
    const int lane = threadIdx.x & 31;
    const size_t row = (size_t)blockIdx.x * 8 + (threadIdx.x >> 5);
    const float4* p = (const float4*)(g_tmp + row * DMODEL);

    float4 v[8];
    float s = 0.f, ss = 0.f;
    #pragma unroll
    for (int i = 0; i < 8; i++) {
        v[i] = p[lane + 32 * i];
        s  += v[i].x + v[i].y + v[i].z + v[i].w;
        ss += v[i].x*v[i].x + v[i].y*v[i].y + v[i].z*v[i].z + v[i].w*v[i].w;
    }
    #pragma unroll
    for (int o = 16; o; o >>= 1) {
        s  += __shfl_xor_sync(0xffffffffu, s, o);
        ss += __shfl_xor_sync(0xffffffffu, ss, o);
    }
    const float mean = s * (1.0f / DMODEL);
    const float var  = ss * (1.0f / DMODEL) - mean * mean;
    const float inv  = rsqrtf(var + 1e-6f);

    float4* q = (float4*)(out + row * DMODEL);
    const float4* gp = (const float4*)gamma;
    const float4* bp = (const float4*)beta;
    #pragma unroll
    for (int i = 0; i < 8; i++) {
        float4 g = gp[lane + 32 * i];
        float4 b = bp[lane + 32 * i];
        float4 o;
        o.x = (v[i].x - mean) * inv * g.x + b.x;
        o.y = (v[i].y - mean) * inv * g.y + b.y;
        o.z = (v[i].z - mean) * inv * g.z + b.z;
        o.w = (v[i].w - mean) * inv * g.w + b.w;
        q[lane + 32 * i] = o;
    }
}

// ---------------------------------------------------------------------------
// Launch
// ---------------------------------------------------------------------------
namespace {
constexpr int SMEM_GEMM  = 3 * 2 * 128 * GQ * 2;                        // 110592
constexpr int SMEM_ATTN  = 128*QPH*2 + 3*32*QPH*2 + 3*32*QPH*2;         // 46080
constexpr int SMEM_WATTN = 128*QPH*2 + 3*32*QPH*2 + 128*CPF*4 + 128*4;  // 51200
}

extern "C" void kernel_launch(void* const* d_in, const int* in_sizes, int n_in,
                              void* d_out, int out_size)
{
    const float* e     = (const float*)d_in[0];
    const float* x     = (const float*)d_in[1];
    const float* We    = (const float*)d_in[2];
    const float* Wx    = (const float*)d_in[3];
    const float* Wfc   = (const float*)d_in[4];
    const float* gamma = (const float*)d_in[5];
    const float* beta  = (const float*)d_in[6];

    float* out      = (float*)d_out;
    float* out_feat = out;
    float* out_attn = out + FEAT_ELEMS;

    cudaFuncSetAttribute(gemm16_kernel,     cudaFuncAttributeMaxDynamicSharedMemorySize, SMEM_GEMM);
    cudaFuncSetAttribute(attn_kernel,       cudaFuncAttributeMaxDynamicSharedMemorySize, SMEM_ATTN);
    cudaFuncSetAttribute(write_attn_kernel, cudaFuncAttributeMaxDynamicSharedMemorySize, SMEM_WATTN);

    cvt_ex_kernel<<<dim3(FEAT_ELEMS / 8 / 256, 2), 256>>>(e, x);          // idx 0
    cvt_w_kernel<<<dim3(W_ELEMS / 8 / 256, 3), 256>>>(We, Wx, Wfc);       // idx 1

    gemm16_kernel<<<dim3(DMODEL / 128, MROWS / 128, 2), 256, SMEM_GEMM>>>(x, 0);  // idx 2

    dim3 ga(SEQ / 128, BHTOT);              // (16, 64)
    attn_kernel<<<ga, 256, SMEM_ATTN>>>();                                // idx 3 (ncu)

    write_attn_kernel<<<ga, 256, SMEM_WATTN>>>(out_attn);                 // idx 4

    gemm16_kernel<<<dim3(DMODEL / 128, MROWS / 128, 1), 256, SMEM_GEMM>>>(x, 2);  // idx 5

    ln_kernel<<<MROWS / 8, 256>>>(gamma, beta, out_feat);                 // idx 6
}

// round 16
// speedup vs baseline: 6.8072x; 1.0382x over previous
#include <cuda_runtime.h>
#include <cuda_fp16.h>
#include <mma.h>
#include <cstdint>

using namespace nvcuda;

// ---------------------------------------------------------------------------
// Problem constants
// ---------------------------------------------------------------------------
namespace {
constexpr int BATCH  = 4;
constexpr int HEADS  = 16;
constexpr int SEQ    = 2048;
constexpr int DH     = 64;
constexpr int DMODEL = 1024;
constexpr int MROWS  = BATCH * SEQ;           // 8192
constexpr int BHTOT  = BATCH * HEADS;         // 64
constexpr size_t HEAD_ELEMS = (size_t)BHTOT * SEQ * DH;
constexpr size_t FEAT_ELEMS = (size_t)MROWS * DMODEL;
constexpr size_t W_ELEMS    = (size_t)DMODEL * DMODEL;
}

// Scratch (device globals; allocation-free)
__device__ __align__(16) __half g_e16 [FEAT_ELEMS];
__device__ __align__(16) __half g_x16 [FEAT_ELEMS];
__device__ __align__(16) __half g_We16[W_ELEMS];
__device__ __align__(16) __half g_Wx16[W_ELEMS];
__device__ __align__(16) __half g_Wfc16[W_ELEMS];
__device__ __align__(16) __half g_eh16[HEAD_ELEMS];  // [bh][l][64]
__device__ __align__(16) __half g_xh16[HEAD_ELEMS];  // [bh][l][64]
__device__ __align__(16) __half g_feat16[FEAT_ELEMS];// [b][l][1024] fp16 (attn out)
__device__ __align__(16) float  g_tmp[FEAT_ELEMS];   // pre-LN (f32)
__device__ __align__(16) float  g_invs[(size_t)BHTOT * SEQ];

// fp16 wmma fragments (GEMM + pass B)
using FragAh  = wmma::fragment<wmma::matrix_a, 16, 16, 16, __half, wmma::row_major>;
using FragBhC = wmma::fragment<wmma::matrix_b, 16, 16, 16, __half, wmma::col_major>;
using FragCh  = wmma::fragment<wmma::accumulator, 16, 16, 16, float>;

// ---------------------------------------------------------------------------
// helpers
// ---------------------------------------------------------------------------
__device__ __forceinline__ uint32_t smem_u32(const void* p) {
    uint32_t a;
    asm("{ .reg .u64 t; cvta.to.shared.u64 t, %1; cvt.u32.u64 %0, t; }" : "=r"(a) : "l"(p));
    return a;
}
__device__ __forceinline__ void cp16(uint32_t s, const void* g) {
    asm volatile("cp.async.cg.shared.global [%0], [%1], 16;" :: "r"(s), "l"(g));
}
#define CP_COMMIT()  asm volatile("cp.async.commit_group;" ::: "memory")
#define CP_WAIT(n)   asm volatile("cp.async.wait_group %0;" :: "n"(n) : "memory")

__device__ __forceinline__ void ldsm4(uint32_t* r, uint32_t addr) {
    asm volatile("ldmatrix.sync.aligned.m8n8.x4.shared.b16 {%0,%1,%2,%3}, [%4];"
        : "=r"(r[0]), "=r"(r[1]), "=r"(r[2]), "=r"(r[3]) : "r"(addr));
}
__device__ __forceinline__ void ldsm4t(uint32_t* r, uint32_t addr) {
    asm volatile("ldmatrix.sync.aligned.m8n8.x4.trans.shared.b16 {%0,%1,%2,%3}, [%4];"
        : "=r"(r[0]), "=r"(r[1]), "=r"(r[2]), "=r"(r[3]) : "r"(addr));
}
__device__ __forceinline__ void mma16816(float* d, const uint32_t* a, const uint32_t* b) {
    asm volatile("mma.sync.aligned.m16n8k16.row.col.f32.f16.f16.f32 "
        "{%0,%1,%2,%3}, {%4,%5,%6,%7}, {%8,%9}, {%0,%1,%2,%3};"
        : "+f"(d[0]), "+f"(d[1]), "+f"(d[2]), "+f"(d[3])
        : "r"(a[0]), "r"(a[1]), "r"(a[2]), "r"(a[3]), "r"(b[0]), "r"(b[1]));
}
__device__ __forceinline__ uint32_t h2u(float lo, float hi) {
    __half2 h = __floats2half2_rn(lo, hi);
    return *(uint32_t*)&h;
}

// ---------------------------------------------------------------------------
// fp32 -> fp16 streaming converts (batched: blockIdx.y selects tensor)
// ---------------------------------------------------------------------------
__global__ __launch_bounds__(256) void cvt_ex_kernel(const float* __restrict__ e,
                                                     const float* __restrict__ x)
{
    const float* src = blockIdx.y ? x : e;
    __half* dst = blockIdx.y ? g_x16 : g_e16;
    size_t i = ((size_t)blockIdx.x * 256 + threadIdx.x) * 8;
    if (i < FEAT_ELEMS) {
        float4 v0 = *(const float4*)(src + i);
        float4 v1 = *(const float4*)(src + i + 4);
        __half2 h[4];
        h[0] = __floats2half2_rn(v0.x, v0.y);
        h[1] = __floats2half2_rn(v0.z, v0.w);
        h[2] = __floats2half2_rn(v1.x, v1.y);
        h[3] = __floats2half2_rn(v1.z, v1.w);
        *(uint4*)(dst + i) = *(uint4*)h;
    }
}
__global__ __launch_bounds__(256) void cvt_w_kernel(const float* __restrict__ We,
                                                    const float* __restrict__ Wx,
                                                    const float* __restrict__ Wfc)
{
    const float* src = (blockIdx.y == 0) ? We : (blockIdx.y == 1) ? Wx : Wfc;
    __half* dst = (blockIdx.y == 0) ? g_We16 : (blockIdx.y == 1) ? g_Wx16 : g_Wfc16;
    size_t i = ((size_t)blockIdx.x * 256 + threadIdx.x) * 8;
    if (i < W_ELEMS) {
        float4 v0 = *(const float4*)(src + i);
        float4 v1 = *(const float4*)(src + i + 4);
        __half2 h[4];
        h[0] = __floats2half2_rn(v0.x, v0.y);
        h[1] = __floats2half2_rn(v0.z, v0.w);
        h[2] = __floats2half2_rn(v1.x, v1.y);
        h[3] = __floats2half2_rn(v1.z, v1.w);
        *(uint4*)(dst + i) = *(uint4*)h;
    }
}

// ---------------------------------------------------------------------------
// fp16 GEMM: D[m,n] = sum_k A[m,k] * W[n,k]  (M=8192, N=1024, K=1024)
// Block 128x128, 8 warps (4m x 2n). 3-stage cp.async, BK=64.
// ---------------------------------------------------------------------------
namespace { constexpr int GQ = 72; }   // smem pad (halves)

__global__ __launch_bounds__(256, 2) void gemm16_kernel(const float* __restrict__ x,
                                                        int mode_base)
{
    extern __shared__ char smc[];
    __half* As = (__half*)smc;          // [3][128][GQ]
    __half* Bs = As + 3 * 128 * GQ;     // [3][128][GQ]
    const int tid = threadIdx.x, wid = tid >> 5;
    const int wm = wid & 3, wn = wid >> 2;
    const int n0 = blockIdx.x * 128, m0 = blockIdx.y * 128;
    const int mode = mode_base + blockIdx.z;

    const __half* A = (mode == 0) ? g_e16 : (mode == 1) ? g_x16 : g_feat16;
    const __half* W = (mode == 0) ? g_We16 : (mode == 1) ? g_Wx16 : g_Wfc16;
    const uint32_t As_u = smem_u32(As), Bs_u = smem_u32(Bs);

    FragCh acc[2][4];
    if (mode == 2) {
        #pragma unroll
        for (int i = 0; i < 2; i++)
            #pragma unroll
            for (int j = 0; j < 4; j++)
                wmma::load_matrix_sync(acc[i][j],
                    x + (size_t)(m0 + wm*32 + i*16) * DMODEL + n0 + wn*64 + j*16,
                    DMODEL, wmma::mem_row_major);
    } else {
        #pragma unroll
        for (int i = 0; i < 2; i++)
            #pragma unroll
            for (int j = 0; j < 4; j++)
                wmma::fill_fragment(acc[i][j], 0.0f);
    }

    auto stage = [&](int k0, int buf) {
        const uint32_t ao = As_u + (uint32_t)buf * 128 * GQ * 2;
        const uint32_t bo = Bs_u + (uint32_t)buf * 128 * GQ * 2;
        #pragma unroll
        for (int i = tid; i < 128 * 8; i += 256) {
            int r = i >> 3, c8 = (i & 7) * 8;
            cp16(ao + (uint32_t)(r * GQ + c8) * 2, A + (size_t)(m0 + r) * DMODEL + k0 + c8);
            cp16(bo + (uint32_t)(r * GQ + c8) * 2, W + (size_t)(n0 + r) * DMODEL + k0 + c8);
        }
    };

    stage(0, 0); CP_COMMIT();
    stage(64, 1); CP_COMMIT();
    for (int kc = 0; kc < 16; kc++) {
        if (kc + 2 < 16)      { stage((kc + 2) * 64, (kc + 2) % 3); CP_COMMIT(); CP_WAIT(2); }
        else if (kc + 1 < 16) { CP_WAIT(1); }
        else                  { CP_WAIT(0); }
        __syncthreads();
        const __half* Ab = As + (kc % 3) * 128 * GQ;
        const __half* Bb = Bs + (kc % 3) * 128 * GQ;
        #pragma unroll
        for (int ks = 0; ks < 4; ks++) {
            FragAh a[2]; FragBhC b[4];
            #pragma unroll
            for (int i = 0; i < 2; i++)
                wmma::load_matrix_sync(a[i], Ab + (wm*32 + i*16) * GQ + ks*16, GQ);
            #pragma unroll
            for (int j = 0; j < 4; j++)
                wmma::load_matrix_sync(b[j], Bb + (wn*64 + j*16) * GQ + ks*16, GQ);
            #pragma unroll
            for (int i = 0; i < 2; i++)
                #pragma unroll
                for (int j = 0; j < 4; j++)
                    wmma::mma_sync(acc[i][j], a[i], b[j], acc[i][j]);
        }
        __syncthreads();
    }

    const int b  = m0 >> 11;
    const int ml = m0 & 2047;

    if (mode == 2) {
        #pragma unroll
        for (int i = 0; i < 2; i++)
            #pragma unroll
            for (int j = 0; j < 4; j++)
                wmma::store_matrix_sync(
                    g_tmp + (size_t)(m0 + wm*32 + i*16) * DMODEL + n0 + wn*64 + j*16,
                    acc[i][j], DMODEL, wmma::mem_row_major);
    } else {
        float* Ts = (float*)smc;   // [128][132]
        __syncthreads();
        #pragma unroll
        for (int i = 0; i < 2; i++)
            #pragma unroll
            for (int j = 0; j < 4; j++)
                wmma::store_matrix_sync(Ts + (wm*32 + i*16) * 132 + wn*64 + j*16,
                                        acc[i][j], 132, wmma::mem_row_major);
        __syncthreads();
        __half* dst_base = (mode == 0) ? g_eh16 : g_xh16;
        #pragma unroll
        for (int i = tid; i < 128 * 16; i += 256) {
            int r = i >> 4, c8 = (i & 15) * 8;
            float4 v0 = *(float4*)&Ts[r * 132 + c8];
            float4 v1 = *(float4*)&Ts[r * 132 + c8 + 4];
            __half2 hv[4];
            hv[0] = __floats2half2_rn(v0.x, v0.y);
            hv[1] = __floats2half2_rn(v0.z, v0.w);
            hv[2] = __floats2half2_rn(v1.x, v1.y);
            hv[3] = __floats2half2_rn(v1.z, v1.w);
            int n = n0 + c8, hh = n >> 6, d0 = n & 63;
            *(uint4*)&dst_base[((size_t)(b*HEADS + hh) * SEQ + ml + r) * DH + d0] =
                *(uint4*)hv;
        }
    }
}

// ---------------------------------------------------------------------------
// Attention pass A — register-resident (raw mma.m16n8k16 + ldmatrix).
// (unchanged from R15: 184.6 us, tensor 61.6%)
// ---------------------------------------------------------------------------
namespace {
constexpr int QPH = 72;   // row pad (halves), 64 data cols, 144B rows
constexpr int CH  = 32;
constexpr int NCH = SEQ / CH;   // 64
constexpr int CPF = 36;   // Cb pad (floats) — pass B only
}

__global__ __launch_bounds__(256, 2) void attn_kernel()
{
    extern __shared__ char smc[];
    __half* Aq = (__half*)smc;                  // [128][72]
    __half* Bk = Aq + 128 * QPH;                // [3][32][72]
    __half* Bx = Bk + 3 * 32 * QPH;             // [3][32][72]
    const int tid = threadIdx.x, wid = tid >> 5, lane = tid & 31;
    const int bh = blockIdx.y, q0 = blockIdx.x * 128;
    const __half* ehb = g_eh16 + (size_t)bh * SEQ * DH;
    const __half* xhb = g_xh16 + (size_t)bh * SEQ * DH;
    const uint32_t Aq_u = smem_u32(Aq), Bk_u = smem_u32(Bk), Bx_u = smem_u32(Bx);

    auto stage = [&](int k0, int buf) {
        const uint32_t ko = Bk_u + (uint32_t)buf * 32 * QPH * 2;
        const uint32_t xo = Bx_u + (uint32_t)buf * 32 * QPH * 2;
        int r = tid >> 3, c8 = (tid & 7) * 8;
        cp16(ko + (uint32_t)(r * QPH + c8) * 2, ehb + (size_t)(k0 + r) * DH + c8);
        cp16(xo + (uint32_t)(r * QPH + c8) * 2, xhb + (size_t)(k0 + r) * DH + c8);
    };

    stage(0, 0); CP_COMMIT();

    {
        const __half2 sc = __half2half2(__float2half(0.125f));
        #pragma unroll
        for (int i = tid; i < 128 * 8; i += 256) {
            int r = i >> 3, c8 = (i & 7) * 8;
            uint4 raw = *(const uint4*)&ehb[(size_t)(q0 + r) * DH + c8];
            __half2* hp = (__half2*)&raw;
            hp[0] = __hmul2(hp[0], sc); hp[1] = __hmul2(hp[1], sc);
            hp[2] = __hmul2(hp[2], sc); hp[3] = __hmul2(hp[3], sc);
            *(uint4*)&Aq[r * QPH + c8] = raw;
        }
    }
    __syncthreads();

    uint32_t aq[4][4];
    {
        const int lr0 = lane & 7;
        const int rofs = ((lane >> 3) & 1) * 8;
        const int cofs = (lane >> 4) * 8;
        const int row  = wid * 16 + rofs + lr0;
        #pragma unroll
        for (int s = 0; s < 4; s++)
            ldsm4(aq[s], Aq_u + (uint32_t)(row * QPH + s * 16 + cofs) * 2);
    }

    float vacc[8][4];
    #pragma unroll
    for (int j = 0; j < 8; j++)
        #pragma unroll
        for (int e = 0; e < 4; e++) vacc[j][e] = 0.0f;
    float rsum0 = 0.0f, rsum1 = 0.0f;

    const int lr = lane & 7;
    const int g01 = ((lane >> 3) & 1) * 8;
    const int g23 = (lane >> 4) * 8;

    int cur = 0, nxt = 1;
    for (int kc = 0; kc < NCH; kc++) {
        if (kc + 1 < NCH) { stage((kc + 1) * CH, nxt); CP_COMMIT(); CP_WAIT(1); }
        else CP_WAIT(0);
        __syncthreads();
        const uint32_t Kb_u = Bk_u + (uint32_t)cur * 32 * QPH * 2;
        const uint32_t Xb_u = Bx_u + (uint32_t)cur * 32 * QPH * 2;

        float P[4][4];
        #pragma unroll
        for (int j = 0; j < 4; j++) {
            #pragma unroll
            for (int e = 0; e < 4; e++) P[j][e] = 0.0f;
            uint32_t kb0[4], kb1[4];
            ldsm4(kb0, Kb_u + (uint32_t)((j * 8 + lr) * QPH + 0  + (lane >> 3) * 8) * 2);
            ldsm4(kb1, Kb_u + (uint32_t)((j * 8 + lr) * QPH + 32 + (lane >> 3) * 8) * 2);
            mma16816(P[j], aq[0], kb0 + 0);
            mma16816(P[j], aq[1], kb0 + 2);
            mma16816(P[j], aq[2], kb1 + 0);
            mma16816(P[j], aq[3], kb1 + 2);
        }
        #pragma unroll
        for (int j = 0; j < 4; j++) {
            P[j][0] = __expf(P[j][0]); P[j][1] = __expf(P[j][1]);
            P[j][2] = __expf(P[j][2]); P[j][3] = __expf(P[j][3]);
            rsum0 += P[j][0] + P[j][1];
            rsum1 += P[j][2] + P[j][3];
        }
        uint32_t pa[2][4];
        #pragma unroll
        for (int s = 0; s < 2; s++) {
            pa[s][0] = h2u(P[2*s][0],   P[2*s][1]);
            pa[s][1] = h2u(P[2*s][2],   P[2*s][3]);
            pa[s][2] = h2u(P[2*s+1][0], P[2*s+1][1]);
            pa[s][3] = h2u(P[2*s+1][2], P[2*s+1][3]);
        }
        #pragma unroll
        for (int s = 0; s < 2; s++) {
            #pragma unroll
            for (int j0 = 0; j0 < 8; j0 += 2) {
                uint32_t xb[4];
                ldsm4t(xb, Xb_u + (uint32_t)((s * 16 + g01 + lr) * QPH + j0 * 8 + g23) * 2);
                mma16816(vacc[j0],     pa[s], xb + 0);
                mma16816(vacc[j0 + 1], pa[s], xb + 2);
            }
        }
        cur = nxt; nxt = (nxt + 1 == 3) ? 0 : nxt + 1;
    }

    rsum0 += __shfl_xor_sync(0xffffffffu, rsum0, 1);
    rsum0 += __shfl_xor_sync(0xffffffffu, rsum0, 2);
    rsum1 += __shfl_xor_sync(0xffffffffu, rsum1, 1);
    rsum1 += __shfl_xor_sync(0xffffffffu, rsum1, 2);
    const float inv0 = 1.0f / rsum0;
    const float inv1 = 1.0f / rsum1;
    const int rlo = wid * 16 + (lane >> 2);
    if ((lane & 3) == 0) {
        g_invs[(size_t)bh * SEQ + q0 + rlo]     = inv0;
        g_invs[(size_t)bh * SEQ + q0 + rlo + 8] = inv1;
    }

    const int b = bh >> 4, h = bh & 15;
    const size_t rowlo = ((size_t)(b * SEQ) + q0 + rlo) * DMODEL + h * DH + (lane & 3) * 2;
    const size_t rowhi = rowlo + 8 * DMODEL;
    #pragma unroll
    for (int j = 0; j < 8; j++) {
        *(uint32_t*)&g_feat16[rowlo + j * 8] = h2u(vacc[j][0] * inv0, vacc[j][1] * inv0);
        *(uint32_t*)&g_feat16[rowhi + j * 8] = h2u(vacc[j][2] * inv1, vacc[j][3] * inv1);
    }
}

// ---------------------------------------------------------------------------
// Attention pass B: recompute scores+exp (wmma), scale by g_invs, stream attn.
// ---------------------------------------------------------------------------
__global__ __launch_bounds__(256, 2) void write_attn_kernel(float* __restrict__ attn)
{
    extern __shared__ char smc[];
    __half* Aq = (__half*)smc;                  // [128][72]
    __half* Bk = Aq + 128 * QPH;                // [3][32][72]
    float*  Cb = (float*)(Bk + 3 * 32 * QPH);   // [128][36]
    float* sinvs = (float*)(Cb + 128 * CPF);    // [128]
    const int tid = threadIdx.x, wid = tid >> 5;
    const int bh = blockIdx.y, q0 = blockIdx.x * 128;
    const __half* ehb = g_eh16 + (size_t)bh * SEQ * DH;
    const uint32_t Bk_u = smem_u32(Bk);

    auto stage = [&](int k0, int buf) {
        const uint32_t ko = Bk_u + (uint32_t)buf * 32 * QPH * 2;
        int r = tid >> 3, c8 = (tid & 7) * 8;
        cp16(ko + (uint32_t)(r * QPH + c8) * 2, ehb + (size_t)(k0 + r) * DH + c8);
    };

    stage(0, 0); CP_COMMIT();

    if (tid < 128) sinvs[tid] = g_invs[(size_t)bh * SEQ + q0 + tid];

    {
        const __half2 sc = __half2half2(__float2half(0.125f));
        #pragma unroll
        for (int i = tid; i < 128 * 8; i += 256) {
            int r = i >> 3, c8 = (i & 7) * 8;
            uint4 raw = *(const uint4*)&ehb[(size_t)(q0 + r) * DH + c8];
            __half2* hp = (__half2*)&raw;
            hp[0] = __hmul2(hp[0], sc); hp[1] = __hmul2(hp[1], sc);
            hp[2] = __hmul2(hp[2], sc); hp[3] = __hmul2(hp[3], sc);
            *(uint4*)&Aq[r * QPH + c8] = raw;
        }
    }
    __syncthreads();

    FragAh aq[4];
    #pragma unroll
    for (int ks = 0; ks < 4; ks++)
        wmma::load_matrix_sync(aq[ks], Aq + (wid * 16) * QPH + ks * 16, QPH);

    const int erow = tid >> 3;
    const int ecol = (tid & 7) * 4;
    float* abase = attn + ((size_t)bh * SEQ + q0) * SEQ;

    int cur = 0, nxt = 1;
    for (int kc = 0; kc < NCH; kc++) {
        if (kc + 1 < NCH) { stage((kc + 1) * CH, nxt); CP_COMMIT(); CP_WAIT(1); }
        else CP_WAIT(0);
        __syncthreads();
        const __half* Kb = Bk + cur * 32 * QPH;

        FragCh sacc[2];
        #pragma unroll
        for (int j = 0; j < 2; j++) wmma::fill_fragment(sacc[j], 0.0f);
        #pragma unroll
        for (int ks = 0; ks < 4; ks++) {
            FragBhC bk[2];
            #pragma unroll
            for (int j = 0; j < 2; j++)
                wmma::load_matrix_sync(bk[j], Kb + (j * 16) * QPH + ks * 16, QPH);
            #pragma unroll
            for (int j = 0; j < 2; j++)
                wmma::mma_sync(sacc[j], aq[ks], bk[j], sacc[j]);
        }
        #pragma unroll
        for (int j = 0; j < 2; j++) {
            #pragma unroll
            for (int t = 0; t < sacc[j].num_elements; t++)
                sacc[j].x[t] = __expf(sacc[j].x[t]);
            wmma::store_matrix_sync(Cb + (wid * 16) * CPF + j * 16,
                                    sacc[j], CPF, wmma::mem_row_major);
        }
        __syncthreads();

        #pragma unroll
        for (int it = 0; it < 4; it++) {
            int r = it * 32 + erow;
            float is = sinvs[r];
            float4 v = *(const float4*)(Cb + r * CPF + ecol);
            v.x *= is; v.y *= is; v.z *= is; v.w *= is;
            __stcs((float4*)(abase + (size_t)r * SEQ + kc * CH + ecol), v);
        }
        cur = nxt; nxt = (nxt + 1 == 3) ? 0 : nxt + 1;
    }
}

// ---------------------------------------------------------------------------
// LayerNorm: warp-per-row (8 rows per 256-thr block), shfl-only reduction.
// ---------------------------------------------------------------------------
__global__ __launch_bounds__(256) void ln_kernel(const float* __restrict__ gamma,
                                                 const float* __restrict__ beta,
                                                 float* __restrict__ out)
{
    const int lane = threadIdx.x & 31;
    const size_t row = (size_t)blockIdx.x * 8 + (threadIdx.x >> 5);
    const float4* p = (const float4*)(g_tmp + row * DMODEL);

    float4 v[8];
    float s = 0.f, ss = 0.f;
    #pragma unroll
    for (int i = 0; i < 8; i++) {
        v[i] = p[lane + 32 * i];
        s  += v[i].x + v[i].y + v[i].z + v[i].w;
        ss += v[i].x*v[i].x + v[i].y*v[i].y + v[i].z*v[i].z + v[i].w*v[i].w;
    }
    #pragma unroll
    for (int o = 16; o; o >>= 1) {
        s  += __shfl_xor_sync(0xffffffffu, s, o);
        ss += __shfl_xor_sync(0xffffffffu, ss, o);
    }
    const float mean = s * (1.0f / DMODEL);
    const float var  = ss * (1.0f / DMODEL) - mean * mean;
    const float inv  = rsqrtf(var + 1e-6f);

    float4* q = (float4*)(out + row * DMODEL);
    const float4* gp = (const float4*)gamma;
    const float4* bp = (const float4*)beta;
    #pragma unroll
    for (int i = 0; i < 8; i++) {
        float4 g = gp[lane + 32 * i];
        float4 b = bp[lane + 32 * i];
        float4 o;
        o.x = (v[i].x - mean) * inv * g.x + b.x;
        o.y = (v[i].y - mean) * inv * g.y + b.y;
        o.z = (v[i].z - mean) * inv * g.z + b.z;
        o.w = (v[i].w - mean) * inv * g.w + b.w;
        q[lane + 32 * i] = o;
    }
}

// ---------------------------------------------------------------------------
// Launch — write_attn forked onto a second stream, overlapping fc+LN.
// ---------------------------------------------------------------------------
namespace {
constexpr int SMEM_GEMM  = 3 * 2 * 128 * GQ * 2;                        // 110592
constexpr int SMEM_ATTN  = 128*QPH*2 + 3*32*QPH*2 + 3*32*QPH*2;         // 46080
constexpr int SMEM_WATTN = 128*QPH*2 + 3*32*QPH*2 + 128*CPF*4 + 128*4;  // 51200
}

extern "C" void kernel_launch(void* const* d_in, const int* in_sizes, int n_in,
                              void* d_out, int out_size)
{
    const float* e     = (const float*)d_in[0];
    const float* x     = (const float*)d_in[1];
    const float* We    = (const float*)d_in[2];
    const float* Wx    = (const float*)d_in[3];
    const float* Wfc   = (const float*)d_in[4];
    const float* gamma = (const float*)d_in[5];
    const float* beta  = (const float*)d_in[6];

    float* out      = (float*)d_out;
    float* out_feat = out;
    float* out_attn = out + FEAT_ELEMS;

    // persistent stream/events (handles only; no device memory)
    static cudaStream_t s2 = [] {
        cudaStream_t s; cudaStreamCreateWithFlags(&s, cudaStreamNonBlocking); return s;
    }();
    static cudaEvent_t evFork = [] {
        cudaEvent_t ev; cudaEventCreateWithFlags(&ev, cudaEventDisableTiming); return ev;
    }();
    static cudaEvent_t evJoin = [] {
        cudaEvent_t ev; cudaEventCreateWithFlags(&ev, cudaEventDisableTiming); return ev;
    }();

    cudaFuncSetAttribute(gemm16_kernel,     cudaFuncAttributeMaxDynamicSharedMemorySize, SMEM_GEMM);
    cudaFuncSetAttribute(attn_kernel,       cudaFuncAttributeMaxDynamicSharedMemorySize, SMEM_ATTN);
    cudaFuncSetAttribute(write_attn_kernel, cudaFuncAttributeMaxDynamicSharedMemorySize, SMEM_WATTN);

    cvt_ex_kernel<<<dim3(FEAT_ELEMS / 8 / 256, 2), 256>>>(e, x);
    cvt_w_kernel<<<dim3(W_ELEMS / 8 / 256, 3), 256>>>(We, Wx, Wfc);

    gemm16_kernel<<<dim3(DMODEL / 128, MROWS / 128, 2), 256, SMEM_GEMM>>>(x, 0);

    dim3 ga(SEQ / 128, BHTOT);              // (16, 64)
    attn_kernel<<<ga, 256, SMEM_ATTN>>>();

    // fork: write_attn on s2 (needs g_invs only), concurrent with fc+LN
    cudaEventRecord(evFork, 0);
    cudaStreamWaitEvent(s2, evFork, 0);
    write_attn_kernel<<<ga, 256, SMEM_WATTN, s2>>>(out_attn);
    cudaEventRecord(evJoin, s2);

    gemm16_kernel<<<dim3(DMODEL / 128, MROWS / 128, 1), 256, SMEM_GEMM>>>(x, 2);
    ln_kernel<<<MROWS / 8, 256>>>(gamma, beta, out_feat);

    // join
    cudaStreamWaitEvent(0, evJoin, 0);
}